// round 1
// baseline (speedup 1.0000x reference)
#include <cuda_runtime.h>
#include <math.h>

#define N_CELLS 4096
#define IN_DIM 1024
#define HID 1024
#define OUT_DIM 1024
#define MID 128
#define NT 8
#define NF 8
#define GIN 1025
#define G3 3072

// ---------------- scratch (device globals; no allocations allowed) ----------------
__device__ float g_A1G1[N_CELLS * 256];       // relu'd [A1 | G1], [4096,256]
__device__ float g_out[N_CELLS * OUT_DIM];    // out = a - g
__device__ float g_gi[N_CELLS * G3];
__device__ float g_gh[N_CELLS * G3];
__device__ float g_nh[N_CELLS * HID];
__device__ float g_tension[N_CELLS];
__device__ float g_energy[N_CELLS];
__device__ int   g_votes[N_CELLS];
__device__ float g_Bcat1[256 * 1024];         // [Wa1h ; Wg1h]
__device__ float g_bias1[256];                // [xa1 | xg1]
__device__ float g_Wcat2[1024 * 256];         // [Wa2 | -Wg2] per row j
__device__ float g_bconst[1024];              // ba2 - bg2
__device__ float g_Mcat[G3 * 256];            // [W_ih_o@Wa2 | -W_ih_o@Wg2]
__device__ float g_vih[G3];                   // b_ih + W_ih_o @ bconst
__device__ float g_counts[NT];
__device__ float g_sums[NT * HID];
__device__ float g_fsums[NF * HID];
__device__ float g_glob[HID];
__device__ float g_w[N_CELLS];
__device__ float g_combined[OUT_DIM];

// ---------------- generic 128x128x16 SIMT fp32 GEMM ----------------
// C[i][j] = alpha * sum_k A[i][k] * B(k,j)  (+ bias[j]) (+ rowv[i]*colv[j*cs]) (relu)
// BT=true:  B stored [N,K] row-major (element B[j*ldb + k])
// BT=false: B stored [K,N] row-major (element B[k*ldb + j])
template <bool BT, bool VECA, bool RELU, bool HASROW>
__global__ void __launch_bounds__(256) gemm128(
    const float* __restrict__ A, int lda,
    const float* __restrict__ B, int ldb,
    float* __restrict__ C, int ldc,
    int K,
    const float* __restrict__ bias,
    const float* __restrict__ rowv,
    const float* __restrict__ colv, int colv_stride,
    float alpha)
{
    __shared__ __align__(16) float As[16][132];
    __shared__ __align__(16) float Bs[16][132];

    const int tid = threadIdx.x;
    const int m0 = blockIdx.y * 128;
    const int n0 = blockIdx.x * 128;
    const int tx = tid & 15;
    const int ty = tid >> 4;

    float acc[8][8];
#pragma unroll
    for (int i = 0; i < 8; i++)
#pragma unroll
        for (int j = 0; j < 8; j++) acc[i][j] = 0.f;

    for (int k0 = 0; k0 < K; k0 += 16) {
        // A tile: 128 rows x 16 cols, transposed into As[k][m]
#pragma unroll
        for (int it = 0; it < 2; it++) {
            int f = tid + it * 256;
            int r = f >> 2;
            int c = (f & 3) * 4;
            const float* src = A + (size_t)(m0 + r) * lda + k0 + c;
            float4 v;
            if (VECA) v = *(const float4*)src;
            else { v.x = src[0]; v.y = src[1]; v.z = src[2]; v.w = src[3]; }
            As[c + 0][r] = v.x; As[c + 1][r] = v.y;
            As[c + 2][r] = v.z; As[c + 3][r] = v.w;
        }
        // B tile into Bs[k][n]
        if (BT) {
#pragma unroll
            for (int it = 0; it < 2; it++) {
                int f = tid + it * 256;
                int r = f >> 2;
                int c = (f & 3) * 4;
                float4 v = *(const float4*)(B + (size_t)(n0 + r) * ldb + k0 + c);
                Bs[c + 0][r] = v.x; Bs[c + 1][r] = v.y;
                Bs[c + 2][r] = v.z; Bs[c + 3][r] = v.w;
            }
        } else {
#pragma unroll
            for (int it = 0; it < 2; it++) {
                int f = tid + it * 256;
                int r = f >> 5;
                int c = (f & 31) * 4;
                *(float4*)&Bs[r][c] = *(const float4*)(B + (size_t)(k0 + r) * ldb + n0 + c);
            }
        }
        __syncthreads();

#pragma unroll
        for (int kk = 0; kk < 16; kk++) {
            float4 a0 = *(const float4*)&As[kk][ty * 8];
            float4 a1 = *(const float4*)&As[kk][ty * 8 + 4];
            float4 b0 = *(const float4*)&Bs[kk][tx * 8];
            float4 b1 = *(const float4*)&Bs[kk][tx * 8 + 4];
            float a[8] = {a0.x, a0.y, a0.z, a0.w, a1.x, a1.y, a1.z, a1.w};
            float b[8] = {b0.x, b0.y, b0.z, b0.w, b1.x, b1.y, b1.z, b1.w};
#pragma unroll
            for (int i = 0; i < 8; i++)
#pragma unroll
                for (int j = 0; j < 8; j++)
                    acc[i][j] = fmaf(a[i], b[j], acc[i][j]);
        }
        __syncthreads();
    }

#pragma unroll
    for (int i = 0; i < 8; i++) {
        int row = m0 + ty * 8 + i;
        float rv = HASROW ? rowv[row] : 0.f;
#pragma unroll
        for (int j = 0; j < 8; j++) {
            int col = n0 + tx * 8 + j;
            float v = acc[i][j] * alpha;
            if (bias) v += bias[col];
            if (HASROW) v += rv * colv[(size_t)col * colv_stride];
            if (RELU) v = fmaxf(v, 0.f);
            C[(size_t)row * ldc + col] = v;
        }
    }
}

// ---------------- small kernels ----------------
__global__ void k_zero()
{
    int i = blockIdx.x * 256 + threadIdx.x;
    if (i < NT) g_counts[i] = 0.f;
    if (i < NT * HID) { g_sums[i] = 0.f; g_fsums[i] = 0.f; }
    if (i < OUT_DIM) { g_combined[i] = 0.f; g_glob[i] = 0.f; }
}

__global__ void k_prep(const float* __restrict__ Wa1, const float* __restrict__ Wg1,
                       const float* __restrict__ Wa2, const float* __restrict__ Wg2,
                       const float* __restrict__ ba2, const float* __restrict__ bg2)
{
    int i = blockIdx.x * 256 + threadIdx.x;   // grid covers 262144
    if (i < 256 * 1024) {
        int r = i >> 10, k = i & 1023;
        g_Bcat1[i] = (r < 128) ? Wa1[r * 2048 + 1024 + k]
                               : Wg1[(r - 128) * 2048 + 1024 + k];
    }
    if (i < 1024 * 128) {
        int j = i >> 7, m = i & 127;
        g_Wcat2[j * 256 + m] = Wa2[i];
        g_Wcat2[j * 256 + 128 + m] = -Wg2[i];
    }
    if (i < 1024) g_bconst[i] = ba2[i] - bg2[i];
}

__global__ void k_bias1(const float* __restrict__ Wa1, const float* __restrict__ ba1,
                        const float* __restrict__ Wg1, const float* __restrict__ bg1,
                        const float* __restrict__ x)
{
    int b = blockIdx.x;
    const float* row = (b < 128) ? (Wa1 + (size_t)b * 2048) : (Wg1 + (size_t)(b - 128) * 2048);
    float s = 0.f;
    for (int j = threadIdx.x; j < 1024; j += 256) s += row[j] * x[j];
    __shared__ float sh[256];
    sh[threadIdx.x] = s; __syncthreads();
    for (int o = 128; o > 0; o >>= 1) {
        if (threadIdx.x < o) sh[threadIdx.x] += sh[threadIdx.x + o];
        __syncthreads();
    }
    if (threadIdx.x == 0)
        g_bias1[b] = sh[0] + ((b < 128) ? ba1[b] : bg1[b - 128]);
}

__global__ void k_vih(const float* __restrict__ W_ih, const float* __restrict__ b_ih)
{
    int k = blockIdx.x;
    const float* row = W_ih + (size_t)k * GIN;
    float s = 0.f;
    for (int j = threadIdx.x; j < 1024; j += 256) s += row[j] * g_bconst[j];
    __shared__ float sh[256];
    sh[threadIdx.x] = s; __syncthreads();
    for (int o = 128; o > 0; o >>= 1) {
        if (threadIdx.x < o) sh[threadIdx.x] += sh[threadIdx.x + o];
        __syncthreads();
    }
    if (threadIdx.x == 0) g_vih[k] = sh[0] + b_ih[k];
}

__global__ void k_vote(const float* __restrict__ infl, const float* __restrict__ op,
                       const float* __restrict__ noise)
{
    int row = blockIdx.x;
    int tid = threadIdx.x;
    float acc[NT];
#pragma unroll
    for (int t = 0; t < NT; t++) acc[t] = 0.f;
    const float* ir = infl + (size_t)row * N_CELLS;
    for (int c = tid; c < N_CELLS; c += 256) {
        float w = ir[c];
        if (w != 0.f) {
#pragma unroll
            for (int t = 0; t < NT; t++) acc[t] += w * op[c * NT + t];
        }
    }
    __shared__ float sh[256];
    __shared__ float s8[NT];
    for (int t = 0; t < NT; t++) {
        sh[tid] = acc[t]; __syncthreads();
        for (int o = 128; o > 0; o >>= 1) {
            if (tid < o) sh[tid] += sh[tid + o];
            __syncthreads();
        }
        if (tid == 0) s8[t] = sh[0];
        __syncthreads();
    }
    if (tid == 0) {
        float v[NT]; float sum = 0.f;
#pragma unroll
        for (int t = 0; t < NT; t++) {
            float u = 0.7f * op[row * NT + t] + 0.3f * s8[t] + 0.01f * noise[row * NT + t];
            u = fmaxf(u, 0.01f);
            v[t] = u; sum += u;
        }
        float inv = 1.f / sum;
        int am = 0; float mx = v[0] * inv;
#pragma unroll
        for (int t = 1; t < NT; t++) {
            float u = v[t] * inv;
            if (u > mx) { mx = u; am = t; }
        }
        g_votes[row] = am;
        g_energy[row] = mx;
        atomicAdd(&g_counts[am], 1.f);
    }
}

__global__ void k_tension()
{
    int i = blockIdx.x, tid = threadIdx.x;
    const float* o = g_out + (size_t)i * 1024;
    float s = 0.f;
    for (int j = tid; j < 1024; j += 256) { float v = o[j]; s += v * v; }
    __shared__ float sh[256];
    sh[tid] = s; __syncthreads();
    for (int off = 128; off > 0; off >>= 1) {
        if (tid < off) sh[tid] += sh[tid + off];
        __syncthreads();
    }
    if (tid == 0) g_tension[i] = sh[0] * (1.f / 1024.f);
}

__global__ void k_gru(const float* __restrict__ hiddens)
{
    int i = blockIdx.x;
    float scale = 0.9f + 0.2f * g_energy[i];
    const float* gi = g_gi + (size_t)i * G3;
    const float* gh = g_gh + (size_t)i * G3;
    for (int j = threadIdx.x; j < HID; j += 256) {
        float r = 1.f / (1.f + expf(-(gi[j] + gh[j])));
        float z = 1.f / (1.f + expf(-(gi[j + 1024] + gh[j + 1024])));
        float n = tanhf(gi[j + 2048] + r * gh[j + 2048]);
        float h = hiddens[(size_t)i * 1024 + j];
        float nh = (1.f - z) * n + z * h;
        nh = fminf(fmaxf(nh * scale, -10.f), 10.f);
        g_nh[(size_t)i * HID + j] = nh;
    }
}

__global__ void k_segsum()
{
    int c = blockIdx.x * 256 + threadIdx.x;
    int r0 = blockIdx.y * 128;
    float acc[NT];
#pragma unroll
    for (int q = 0; q < NT; q++) acc[q] = 0.f;
    for (int r = r0; r < r0 + 128; r++) {
        float v = g_nh[(size_t)r * HID + c];
        int t = g_votes[r];
#pragma unroll
        for (int q = 0; q < NT; q++) acc[q] += (t == q) ? v : 0.f;
    }
#pragma unroll
    for (int q = 0; q < NT; q++) atomicAdd(&g_sums[q * HID + c], acc[q]);
}

__global__ void k_blend()
{
    int c = blockIdx.x * 256 + threadIdx.x;
    int r0 = blockIdx.y * 64;
    int f = r0 >> 9;
    float facc = 0.f;
    for (int r = r0; r < r0 + 64; r++) {
        int t = g_votes[r];
        float cnt = g_counts[t];
        float v = g_nh[(size_t)r * HID + c];
        if (cnt >= 2.f)
            v = 0.85f * v + 0.15f * (g_sums[t * HID + c] / fmaxf(cnt, 1.f));
        g_nh[(size_t)r * HID + c] = v;
        facc += v;
    }
    atomicAdd(&g_fsums[f * HID + c], facc);
}

__global__ void k_glob()
{
    int j = blockIdx.x * 256 + threadIdx.x;
    float s = 0.f;
#pragma unroll
    for (int f = 0; f < NF; f++) s += g_fsums[f * HID + j];
    g_glob[j] = s * (1.f / 4096.f);   // mean over 8 factions of (fsum/512)
}

__global__ void k_final(float* __restrict__ out_nh, const int* __restrict__ step)
{
    int i = blockIdx.x;
    int f = i >> 9;
    bool dcz = (*step > 5) && ((i & 511) < 128);
    for (int j = threadIdx.x; j < HID; j += 256) {
        float fm = g_fsums[f * HID + j] * (1.f / 512.f);
        float v = 0.85f * g_nh[(size_t)i * HID + j] + 0.15f * fm;
        if (dcz) v = 0.85f * v + 0.15f * g_glob[j];
        out_nh[(size_t)i * HID + j] = v;
    }
}

__global__ void k_softmax(float* __restrict__ out_avg)
{
    __shared__ float sh[1024];
    int tid = threadIdx.x;
    float t4[4];
    float mx = -1e30f, av = 0.f;
#pragma unroll
    for (int q = 0; q < 4; q++) {
        t4[q] = g_tension[tid + q * 1024];
        mx = fmaxf(mx, t4[q]);
        av += t4[q];
    }
    sh[tid] = mx; __syncthreads();
    for (int o = 512; o > 0; o >>= 1) {
        if (tid < o) sh[tid] = fmaxf(sh[tid], sh[tid + o]);
        __syncthreads();
    }
    float M = sh[0]; __syncthreads();
    float sm = 0.f;
#pragma unroll
    for (int q = 0; q < 4; q++) {
        float e = expf(t4[q] - M);
        g_w[tid + q * 1024] = e;
        sm += e;
    }
    sh[tid] = sm; __syncthreads();
    for (int o = 512; o > 0; o >>= 1) {
        if (tid < o) sh[tid] += sh[tid + o];
        __syncthreads();
    }
    float inv = 1.f / sh[0]; __syncthreads();
#pragma unroll
    for (int q = 0; q < 4; q++) g_w[tid + q * 1024] *= inv;
    sh[tid] = av; __syncthreads();
    for (int o = 512; o > 0; o >>= 1) {
        if (tid < o) sh[tid] += sh[tid + o];
        __syncthreads();
    }
    if (tid == 0) out_avg[0] = sh[0] * (1.f / 4096.f);
}

__global__ void k_combined()
{
    int c = blockIdx.x * 256 + threadIdx.x;
    int r0 = blockIdx.y * 128;
    float acc = 0.f;
    for (int r = r0; r < r0 + 128; r++)
        acc += g_w[r] * g_out[(size_t)r * 1024 + c];
    atomicAdd(&g_combined[c], acc);
}

__global__ void k_pred(const float* __restrict__ Wo, const float* __restrict__ bo,
                       float* __restrict__ out_pred)
{
    int i = blockIdx.x;
    const float* row = Wo + (size_t)i * 1024;
    float s = 0.f;
    for (int j = threadIdx.x; j < 1024; j += 256) s += g_combined[j] * row[j];
    __shared__ float sh[256];
    sh[threadIdx.x] = s; __syncthreads();
    for (int o = 128; o > 0; o >>= 1) {
        if (threadIdx.x < o) sh[threadIdx.x] += sh[threadIdx.x + o];
        __syncthreads();
    }
    if (threadIdx.x == 0) out_pred[i] = sh[0] + bo[i];
}

// ---------------- launch ----------------
static float* symf(const void* s)
{
    void* p = nullptr;
    cudaGetSymbolAddress(&p, s);
    return (float*)p;
}

extern "C" void kernel_launch(void* const* d_in, const int* in_sizes, int n_in,
                              void* d_out, int out_size)
{
    const float* x        = (const float*)d_in[0];
    const float* hiddens  = (const float*)d_in[1];
    const float* opinions = (const float*)d_in[2];
    const float* influence= (const float*)d_in[3];
    const float* noise    = (const float*)d_in[4];
    const float* Wa1 = (const float*)d_in[5];
    const float* ba1 = (const float*)d_in[6];
    const float* Wa2 = (const float*)d_in[7];
    const float* ba2 = (const float*)d_in[8];
    const float* Wg1 = (const float*)d_in[9];
    const float* bg1 = (const float*)d_in[10];
    const float* Wg2 = (const float*)d_in[11];
    const float* bg2 = (const float*)d_in[12];
    const float* W_ih = (const float*)d_in[13];
    const float* b_ih = (const float*)d_in[14];
    const float* W_hh = (const float*)d_in[15];
    const float* b_hh = (const float*)d_in[16];
    const float* Wo  = (const float*)d_in[17];
    const float* bo  = (const float*)d_in[18];
    const int*   step = (const int*)d_in[19];

    float* out = (float*)d_out;
    float* out_pred = out;           // [1024]
    float* out_avg  = out + 1024;    // [1]
    float* out_nh   = out + 1025;    // [4096*1024]

    float* pA1G1  = symf(g_A1G1);
    float* pOut   = symf(g_out);
    float* pGi    = symf(g_gi);
    float* pGh    = symf(g_gh);
    float* pBcat1 = symf(g_Bcat1);
    float* pBias1 = symf(g_bias1);
    float* pWcat2 = symf(g_Wcat2);
    float* pBconst= symf(g_bconst);
    float* pMcat  = symf(g_Mcat);
    float* pVih   = symf(g_vih);
    float* pTens  = symf(g_tension);

    // init + precomputes
    k_zero<<<32, 256>>>();
    k_prep<<<1024, 256>>>(Wa1, Wg1, Wa2, Wg2, ba2, bg2);
    k_bias1<<<256, 256>>>(Wa1, ba1, Wg1, bg1, x);
    k_vih<<<3072, 256>>>(W_ih, b_ih);

    // vote round (independent)
    k_vote<<<N_CELLS, 256>>>(influence, opinions, noise);

    // Mcat = [W_ih_o @ Wa2 | -W_ih_o @ Wg2]   (3072 x 256)
    gemm128<false, false, false, false><<<dim3(1, 24), 256>>>(
        W_ih, GIN, Wa2, 128, pMcat, 256, 1024,
        nullptr, nullptr, nullptr, 0, 1.f);
    gemm128<false, false, false, false><<<dim3(1, 24), 256>>>(
        W_ih, GIN, Wg2, 128, pMcat + 128, 256, 1024,
        nullptr, nullptr, nullptr, 0, -1.f);

    // A1G1 = relu(hiddens @ Bcat1^T + bias1)   (4096 x 256)
    gemm128<true, true, true, false><<<dim3(2, 32), 256>>>(
        hiddens, 1024, pBcat1, 1024, pA1G1, 256, 1024,
        pBias1, nullptr, nullptr, 0, 1.f);

    // out = A1G1 @ Wcat2^T + bconst            (4096 x 1024)
    gemm128<true, true, false, false><<<dim3(8, 32), 256>>>(
        pA1G1, 256, pWcat2, 256, pOut, 1024, 256,
        pBconst, nullptr, nullptr, 0, 1.f);

    k_tension<<<N_CELLS, 256>>>();

    // gh = hiddens @ W_hh^T + b_hh             (4096 x 3072)
    gemm128<true, true, false, false><<<dim3(24, 32), 256>>>(
        hiddens, 1024, W_hh, 1024, pGh, G3, 1024,
        b_hh, nullptr, nullptr, 0, 1.f);

    // gi = A1G1 @ Mcat^T + vih + tension * W_ih[:,1024]   (4096 x 3072)
    gemm128<true, true, false, true><<<dim3(24, 32), 256>>>(
        pA1G1, 256, pMcat, 256, pGi, G3, 256,
        pVih, pTens, W_ih + 1024, GIN, 1.f);

    k_gru<<<N_CELLS, 256>>>(hiddens);
    k_segsum<<<dim3(4, 32), 256>>>();
    k_blend<<<dim3(4, 64), 256>>>();
    k_glob<<<4, 256>>>();
    k_final<<<N_CELLS, 256>>>(out_nh, step);

    k_softmax<<<1, 1024>>>(out_avg);
    k_combined<<<dim3(4, 32), 256>>>();
    k_pred<<<1024, 256>>>(Wo, bo, out_pred);
}

// round 3
// speedup vs baseline: 1.6074x; 1.6074x over previous
#include <cuda_runtime.h>
#include <cuda_bf16.h>
#include <math.h>
#include <stdint.h>

#define N_CELLS 4096
#define IN_DIM 1024
#define HID 1024
#define OUT_DIM 1024
#define MID 128
#define NT 8
#define NF 8
#define GIN 1025
#define G3 3072

// ---------------- scratch (device globals; no allocations allowed) ----------------
__device__ float g_A1G1[N_CELLS * 256];       // relu'd [A1 | G1], [4096,256]
__device__ float g_out[N_CELLS * OUT_DIM];    // out = a - g
__device__ float g_gi[N_CELLS * G3];
__device__ float g_gh[N_CELLS * G3];
__device__ float g_nh[N_CELLS * HID];
__device__ float g_tension[N_CELLS];
__device__ float g_energy[N_CELLS];
__device__ int   g_votes[N_CELLS];
__device__ float g_Bcat1[256 * 1024];         // [Wa1h ; Wg1h]
__device__ float g_bias1[256];                // [xa1 | xg1]
__device__ float g_Wcat2[1024 * 256];         // [Wa2 | -Wg2] per row j
__device__ float g_bconst[1024];              // ba2 - bg2
__device__ float g_Mcat[G3 * 256];            // [W_ih_o@Wa2 | -W_ih_o@Wg2]
__device__ float g_vih[G3];                   // b_ih + W_ih_o @ bconst
__device__ float g_counts[NT];
__device__ float g_sums[NT * HID];
__device__ float g_fsums[NF * HID];
__device__ float g_glob[HID];
__device__ float g_w[N_CELLS];
__device__ float g_combined[OUT_DIM];

// ---------------- warp MMA helper (HMMA, plain PTX, works on compute_103) ----------------
__device__ __forceinline__ void mma16816(float c[4], const uint32_t a[4], const uint32_t b[2])
{
    asm("mma.sync.aligned.m16n8k16.row.col.f32.bf16.bf16.f32 "
        "{%0,%1,%2,%3}, {%4,%5,%6,%7}, {%8,%9}, {%0,%1,%2,%3};"
        : "+f"(c[0]), "+f"(c[1]), "+f"(c[2]), "+f"(c[3])
        : "r"(a[0]), "r"(a[1]), "r"(a[2]), "r"(a[3]), "r"(b[0]), "r"(b[1]));
}

__device__ __forceinline__ void split_bf16(float x, __nv_bfloat16& hi, __nv_bfloat16& lo)
{
    hi = __float2bfloat16_rn(x);
    lo = __float2bfloat16_rn(x - __bfloat162float(hi));
}

// =============== HMMA GEMM: C[MxN] = alpha*A@B(^T) (+bias)(+rowv*colv)(relu) ===============
// A: [M,K] fp32 row-major. BT=true: B [N,K] row-major. BT=false: B [K,N] row-major.
// fp32 emulated via bf16 hi/lo split (3 products), fp32 accumulate in registers.
// CTA: 128x128 tile, 8 warps in 4(m) x 2(n), warp tile 32x64. K chunk = 32.
template <bool BT, bool VECA, bool RELU, bool HASROW>
__global__ void __launch_bounds__(256) gemm_mma(
    const float* __restrict__ A, int lda,
    const float* __restrict__ B, int ldb,
    float* __restrict__ C, int ldc,
    int K,
    const float* __restrict__ bias,
    const float* __restrict__ rowv,
    const float* __restrict__ colv, int cs,
    float alpha)
{
    const int KP = 40;  // bf16 row stride (32 data + 8 pad): conflict-free frag loads
    __shared__ __nv_bfloat16 sAhi[128 * 40], sAlo[128 * 40];
    __shared__ __nv_bfloat16 sBhi[128 * 40], sBlo[128 * 40];

    const int tid = threadIdx.x;
    const int wid = tid >> 5, lane = tid & 31;
    const int wm = wid & 3, wn = wid >> 2;
    const int g = lane >> 2, tg = lane & 3;
    const int m0 = blockIdx.y * 128, n0 = blockIdx.x * 128;

    float acc[2][8][4];
#pragma unroll
    for (int mi = 0; mi < 2; mi++)
#pragma unroll
        for (int ni = 0; ni < 8; ni++)
#pragma unroll
            for (int q = 0; q < 4; q++) acc[mi][ni][q] = 0.f;

    for (int k0 = 0; k0 < K; k0 += 32) {
        float2 av[8], bv[8];
#pragma unroll
        for (int i = 0; i < 8; i++) {
            int idx = tid + i * 256;
            int r = idx >> 4, c2 = idx & 15;   // 16 float2 per 32-col row
            const float* src = A + (size_t)(m0 + r) * lda + k0 + c2 * 2;
            if (VECA) av[i] = *(const float2*)src;
            else { av[i].x = src[0]; av[i].y = src[1]; }
        }
        if (BT) {
#pragma unroll
            for (int i = 0; i < 8; i++) {
                int idx = tid + i * 256;
                int r = idx >> 4, c2 = idx & 15;
                bv[i] = *(const float2*)(B + (size_t)(n0 + r) * ldb + k0 + c2 * 2);
            }
        } else {
#pragma unroll
            for (int i = 0; i < 8; i++) {
                int idx = tid + i * 256;
                int kk = idx >> 6, n2 = idx & 63;  // 64 float2 per 128-col row
                bv[i] = *(const float2*)(B + (size_t)(k0 + kk) * ldb + n0 + n2 * 2);
            }
        }

        __syncthreads();  // previous chunk's compute done before overwriting smem

#pragma unroll
        for (int i = 0; i < 8; i++) {
            int idx = tid + i * 256;
            int r = idx >> 4, col = (idx & 15) * 2;
            __nv_bfloat16 hx, lx, hy, ly;
            split_bf16(av[i].x, hx, lx);
            split_bf16(av[i].y, hy, ly);
            __nv_bfloat162 h2; h2.x = hx; h2.y = hy;
            __nv_bfloat162 l2; l2.x = lx; l2.y = ly;
            *(uint32_t*)&sAhi[r * KP + col] = *(uint32_t*)&h2;
            *(uint32_t*)&sAlo[r * KP + col] = *(uint32_t*)&l2;
        }
        if (BT) {
#pragma unroll
            for (int i = 0; i < 8; i++) {
                int idx = tid + i * 256;
                int r = idx >> 4, col = (idx & 15) * 2;
                __nv_bfloat16 hx, lx, hy, ly;
                split_bf16(bv[i].x, hx, lx);
                split_bf16(bv[i].y, hy, ly);
                __nv_bfloat162 h2; h2.x = hx; h2.y = hy;
                __nv_bfloat162 l2; l2.x = lx; l2.y = ly;
                *(uint32_t*)&sBhi[r * KP + col] = *(uint32_t*)&h2;
                *(uint32_t*)&sBlo[r * KP + col] = *(uint32_t*)&l2;
            }
        } else {
            // transpose: B[k][n] -> sB[n][k]
#pragma unroll
            for (int i = 0; i < 8; i++) {
                int idx = tid + i * 256;
                int kk = idx >> 6, n2 = (idx & 63) * 2;
                __nv_bfloat16 hx, lx, hy, ly;
                split_bf16(bv[i].x, hx, lx);
                split_bf16(bv[i].y, hy, ly);
                sBhi[n2 * KP + kk] = hx;       sBlo[n2 * KP + kk] = lx;
                sBhi[(n2 + 1) * KP + kk] = hy; sBlo[(n2 + 1) * KP + kk] = ly;
            }
        }
        __syncthreads();

#pragma unroll
        for (int ks = 0; ks < 32; ks += 16) {
            uint32_t ah[2][4], al[2][4], bh[8][2], bl[8][2];
#pragma unroll
            for (int mi = 0; mi < 2; mi++) {
                int r = wm * 32 + mi * 16 + g;
                ah[mi][0] = *(const uint32_t*)&sAhi[r * KP + ks + tg * 2];
                ah[mi][1] = *(const uint32_t*)&sAhi[(r + 8) * KP + ks + tg * 2];
                ah[mi][2] = *(const uint32_t*)&sAhi[r * KP + ks + 8 + tg * 2];
                ah[mi][3] = *(const uint32_t*)&sAhi[(r + 8) * KP + ks + 8 + tg * 2];
                al[mi][0] = *(const uint32_t*)&sAlo[r * KP + ks + tg * 2];
                al[mi][1] = *(const uint32_t*)&sAlo[(r + 8) * KP + ks + tg * 2];
                al[mi][2] = *(const uint32_t*)&sAlo[r * KP + ks + 8 + tg * 2];
                al[mi][3] = *(const uint32_t*)&sAlo[(r + 8) * KP + ks + 8 + tg * 2];
            }
#pragma unroll
            for (int ni = 0; ni < 8; ni++) {
                int c = wn * 64 + ni * 8 + g;
                bh[ni][0] = *(const uint32_t*)&sBhi[c * KP + ks + tg * 2];
                bh[ni][1] = *(const uint32_t*)&sBhi[c * KP + ks + 8 + tg * 2];
                bl[ni][0] = *(const uint32_t*)&sBlo[c * KP + ks + tg * 2];
                bl[ni][1] = *(const uint32_t*)&sBlo[c * KP + ks + 8 + tg * 2];
            }
#pragma unroll
            for (int mi = 0; mi < 2; mi++)
#pragma unroll
                for (int ni = 0; ni < 8; ni++) {
                    mma16816(acc[mi][ni], ah[mi], bh[ni]);
                    mma16816(acc[mi][ni], ah[mi], bl[ni]);
                    mma16816(acc[mi][ni], al[mi], bh[ni]);
                }
        }
    }

    // ---- epilogue ----
#pragma unroll
    for (int mi = 0; mi < 2; mi++) {
        int row0 = m0 + wm * 32 + mi * 16 + g;
        float rv0 = HASROW ? rowv[row0] : 0.f;
        float rv1 = HASROW ? rowv[row0 + 8] : 0.f;
#pragma unroll
        for (int ni = 0; ni < 8; ni++) {
            int col = n0 + wn * 64 + ni * 8 + tg * 2;
            float b0 = bias ? bias[col] : 0.f;
            float b1 = bias ? bias[col + 1] : 0.f;
            float cv0 = HASROW ? colv[(size_t)col * cs] : 0.f;
            float cv1 = HASROW ? colv[(size_t)(col + 1) * cs] : 0.f;
            float v0 = acc[mi][ni][0] * alpha + b0;
            float v1 = acc[mi][ni][1] * alpha + b1;
            float v2 = acc[mi][ni][2] * alpha + b0;
            float v3 = acc[mi][ni][3] * alpha + b1;
            if (HASROW) { v0 += rv0 * cv0; v1 += rv0 * cv1; v2 += rv1 * cv0; v3 += rv1 * cv1; }
            if (RELU) {
                v0 = fmaxf(v0, 0.f); v1 = fmaxf(v1, 0.f);
                v2 = fmaxf(v2, 0.f); v3 = fmaxf(v3, 0.f);
            }
            float2 p0; p0.x = v0; p0.y = v1;
            float2 p1; p1.x = v2; p1.y = v3;
            *(float2*)(C + (size_t)row0 * ldc + col) = p0;
            *(float2*)(C + (size_t)(row0 + 8) * ldc + col) = p1;
        }
    }
}

// ---------------- small kernels ----------------
__global__ void k_zero()
{
    int i = blockIdx.x * 256 + threadIdx.x;
    if (i < NT) g_counts[i] = 0.f;
    if (i < NT * HID) { g_sums[i] = 0.f; g_fsums[i] = 0.f; }
    if (i < OUT_DIM) { g_combined[i] = 0.f; g_glob[i] = 0.f; }
}

__global__ void k_prep(const float* __restrict__ Wa1, const float* __restrict__ Wg1,
                       const float* __restrict__ Wa2, const float* __restrict__ Wg2,
                       const float* __restrict__ ba2, const float* __restrict__ bg2)
{
    int i = blockIdx.x * 256 + threadIdx.x;   // grid covers 262144
    if (i < 256 * 1024) {
        int r = i >> 10, k = i & 1023;
        g_Bcat1[i] = (r < 128) ? Wa1[r * 2048 + 1024 + k]
                               : Wg1[(r - 128) * 2048 + 1024 + k];
    }
    if (i < 1024 * 128) {
        int j = i >> 7, m = i & 127;
        g_Wcat2[j * 256 + m] = Wa2[i];
        g_Wcat2[j * 256 + 128 + m] = -Wg2[i];
    }
    if (i < 1024) g_bconst[i] = ba2[i] - bg2[i];
}

__global__ void k_bias1(const float* __restrict__ Wa1, const float* __restrict__ ba1,
                        const float* __restrict__ Wg1, const float* __restrict__ bg1,
                        const float* __restrict__ x)
{
    int b = blockIdx.x;
    const float* row = (b < 128) ? (Wa1 + (size_t)b * 2048) : (Wg1 + (size_t)(b - 128) * 2048);
    float s = 0.f;
    for (int j = threadIdx.x; j < 1024; j += 256) s += row[j] * x[j];
    __shared__ float sh[256];
    sh[threadIdx.x] = s; __syncthreads();
    for (int o = 128; o > 0; o >>= 1) {
        if (threadIdx.x < o) sh[threadIdx.x] += sh[threadIdx.x + o];
        __syncthreads();
    }
    if (threadIdx.x == 0)
        g_bias1[b] = sh[0] + ((b < 128) ? ba1[b] : bg1[b - 128]);
}

__global__ void k_vih(const float* __restrict__ W_ih, const float* __restrict__ b_ih)
{
    int k = blockIdx.x;
    const float* row = W_ih + (size_t)k * GIN;
    float s = 0.f;
    for (int j = threadIdx.x; j < 1024; j += 256) s += row[j] * g_bconst[j];
    __shared__ float sh[256];
    sh[threadIdx.x] = s; __syncthreads();
    for (int o = 128; o > 0; o >>= 1) {
        if (threadIdx.x < o) sh[threadIdx.x] += sh[threadIdx.x + o];
        __syncthreads();
    }
    if (threadIdx.x == 0) g_vih[k] = sh[0] + b_ih[k];
}

__global__ void k_vote(const float* __restrict__ infl, const float* __restrict__ op,
                       const float* __restrict__ noise)
{
    int row = blockIdx.x;
    int tid = threadIdx.x;
    float acc[NT];
#pragma unroll
    for (int t = 0; t < NT; t++) acc[t] = 0.f;
    const float* ir = infl + (size_t)row * N_CELLS;
    for (int c = tid; c < N_CELLS; c += 256) {
        float w = ir[c];
        if (w != 0.f) {
#pragma unroll
            for (int t = 0; t < NT; t++) acc[t] += w * op[c * NT + t];
        }
    }
    __shared__ float sh[256];
    __shared__ float s8[NT];
    for (int t = 0; t < NT; t++) {
        sh[tid] = acc[t]; __syncthreads();
        for (int o = 128; o > 0; o >>= 1) {
            if (tid < o) sh[tid] += sh[tid + o];
            __syncthreads();
        }
        if (tid == 0) s8[t] = sh[0];
        __syncthreads();
    }
    if (tid == 0) {
        float v[NT]; float sum = 0.f;
#pragma unroll
        for (int t = 0; t < NT; t++) {
            float u = 0.7f * op[row * NT + t] + 0.3f * s8[t] + 0.01f * noise[row * NT + t];
            u = fmaxf(u, 0.01f);
            v[t] = u; sum += u;
        }
        float inv = 1.f / sum;
        int am = 0; float mx = v[0] * inv;
#pragma unroll
        for (int t = 1; t < NT; t++) {
            float u = v[t] * inv;
            if (u > mx) { mx = u; am = t; }
        }
        g_votes[row] = am;
        g_energy[row] = mx;
        atomicAdd(&g_counts[am], 1.f);
    }
}

__global__ void k_tension()
{
    int i = blockIdx.x, tid = threadIdx.x;
    const float* o = g_out + (size_t)i * 1024;
    float s = 0.f;
    for (int j = tid; j < 1024; j += 256) { float v = o[j]; s += v * v; }
    __shared__ float sh[256];
    sh[tid] = s; __syncthreads();
    for (int off = 128; off > 0; off >>= 1) {
        if (tid < off) sh[tid] += sh[tid + off];
        __syncthreads();
    }
    if (tid == 0) g_tension[i] = sh[0] * (1.f / 1024.f);
}

__global__ void k_gru(const float* __restrict__ hiddens)
{
    int i = blockIdx.x;
    float scale = 0.9f + 0.2f * g_energy[i];
    const float* gi = g_gi + (size_t)i * G3;
    const float* gh = g_gh + (size_t)i * G3;
    for (int j = threadIdx.x; j < HID; j += 256) {
        float r = 1.f / (1.f + expf(-(gi[j] + gh[j])));
        float z = 1.f / (1.f + expf(-(gi[j + 1024] + gh[j + 1024])));
        float n = tanhf(gi[j + 2048] + r * gh[j + 2048]);
        float h = hiddens[(size_t)i * 1024 + j];
        float nh = (1.f - z) * n + z * h;
        nh = fminf(fmaxf(nh * scale, -10.f), 10.f);
        g_nh[(size_t)i * HID + j] = nh;
    }
}

__global__ void k_segsum()
{
    int c = blockIdx.x * 256 + threadIdx.x;
    int r0 = blockIdx.y * 128;
    float acc[NT];
#pragma unroll
    for (int q = 0; q < NT; q++) acc[q] = 0.f;
    for (int r = r0; r < r0 + 128; r++) {
        float v = g_nh[(size_t)r * HID + c];
        int t = g_votes[r];
#pragma unroll
        for (int q = 0; q < NT; q++) acc[q] += (t == q) ? v : 0.f;
    }
#pragma unroll
    for (int q = 0; q < NT; q++) atomicAdd(&g_sums[q * HID + c], acc[q]);
}

__global__ void k_blend()
{
    int c = blockIdx.x * 256 + threadIdx.x;
    int r0 = blockIdx.y * 64;
    int f = r0 >> 9;
    float facc = 0.f;
    for (int r = r0; r < r0 + 64; r++) {
        int t = g_votes[r];
        float cnt = g_counts[t];
        float v = g_nh[(size_t)r * HID + c];
        if (cnt >= 2.f)
            v = 0.85f * v + 0.15f * (g_sums[t * HID + c] / fmaxf(cnt, 1.f));
        g_nh[(size_t)r * HID + c] = v;
        facc += v;
    }
    atomicAdd(&g_fsums[f * HID + c], facc);
}

__global__ void k_glob()
{
    int j = blockIdx.x * 256 + threadIdx.x;
    float s = 0.f;
#pragma unroll
    for (int f = 0; f < NF; f++) s += g_fsums[f * HID + j];
    g_glob[j] = s * (1.f / 4096.f);
}

__global__ void k_final(float* __restrict__ out_nh, const int* __restrict__ step)
{
    int i = blockIdx.x;
    int f = i >> 9;
    bool dcz = (*step > 5) && ((i & 511) < 128);
    for (int j = threadIdx.x; j < HID; j += 256) {
        float fm = g_fsums[f * HID + j] * (1.f / 512.f);
        float v = 0.85f * g_nh[(size_t)i * HID + j] + 0.15f * fm;
        if (dcz) v = 0.85f * v + 0.15f * g_glob[j];
        out_nh[(size_t)i * HID + j] = v;
    }
}

__global__ void k_softmax(float* __restrict__ out_avg)
{
    __shared__ float sh[1024];
    int tid = threadIdx.x;
    float t4[4];
    float mx = -1e30f, av = 0.f;
#pragma unroll
    for (int q = 0; q < 4; q++) {
        t4[q] = g_tension[tid + q * 1024];
        mx = fmaxf(mx, t4[q]);
        av += t4[q];
    }
    sh[tid] = mx; __syncthreads();
    for (int o = 512; o > 0; o >>= 1) {
        if (tid < o) sh[tid] = fmaxf(sh[tid], sh[tid + o]);
        __syncthreads();
    }
    float M = sh[0]; __syncthreads();
    float sm = 0.f;
#pragma unroll
    for (int q = 0; q < 4; q++) {
        float e = expf(t4[q] - M);
        g_w[tid + q * 1024] = e;
        sm += e;
    }
    sh[tid] = sm; __syncthreads();
    for (int o = 512; o > 0; o >>= 1) {
        if (tid < o) sh[tid] += sh[tid + o];
        __syncthreads();
    }
    float inv = 1.f / sh[0]; __syncthreads();
#pragma unroll
    for (int q = 0; q < 4; q++) g_w[tid + q * 1024] *= inv;
    sh[tid] = av; __syncthreads();
    for (int o = 512; o > 0; o >>= 1) {
        if (tid < o) sh[tid] += sh[tid + o];
        __syncthreads();
    }
    if (tid == 0) out_avg[0] = sh[0] * (1.f / 4096.f);
}

__global__ void k_combined()
{
    int c = blockIdx.x * 256 + threadIdx.x;
    int r0 = blockIdx.y * 128;
    float acc = 0.f;
    for (int r = r0; r < r0 + 128; r++)
        acc += g_w[r] * g_out[(size_t)r * 1024 + c];
    atomicAdd(&g_combined[c], acc);
}

__global__ void k_pred(const float* __restrict__ Wo, const float* __restrict__ bo,
                       float* __restrict__ out_pred)
{
    int i = blockIdx.x;
    const float* row = Wo + (size_t)i * 1024;
    float s = 0.f;
    for (int j = threadIdx.x; j < 1024; j += 256) s += g_combined[j] * row[j];
    __shared__ float sh[256];
    sh[threadIdx.x] = s; __syncthreads();
    for (int o = 128; o > 0; o >>= 1) {
        if (threadIdx.x < o) sh[threadIdx.x] += sh[threadIdx.x + o];
        __syncthreads();
    }
    if (threadIdx.x == 0) out_pred[i] = sh[0] + bo[i];
}

// ---------------- launch ----------------
static float* symf(const void* s)
{
    void* p = nullptr;
    cudaGetSymbolAddress(&p, s);
    return (float*)p;
}

extern "C" void kernel_launch(void* const* d_in, const int* in_sizes, int n_in,
                              void* d_out, int out_size)
{
    const float* x        = (const float*)d_in[0];
    const float* hiddens  = (const float*)d_in[1];
    const float* opinions = (const float*)d_in[2];
    const float* influence= (const float*)d_in[3];
    const float* noise    = (const float*)d_in[4];
    const float* Wa1 = (const float*)d_in[5];
    const float* ba1 = (const float*)d_in[6];
    const float* Wa2 = (const float*)d_in[7];
    const float* ba2 = (const float*)d_in[8];
    const float* Wg1 = (const float*)d_in[9];
    const float* bg1 = (const float*)d_in[10];
    const float* Wg2 = (const float*)d_in[11];
    const float* bg2 = (const float*)d_in[12];
    const float* W_ih = (const float*)d_in[13];
    const float* b_ih = (const float*)d_in[14];
    const float* W_hh = (const float*)d_in[15];
    const float* b_hh = (const float*)d_in[16];
    const float* Wo  = (const float*)d_in[17];
    const float* bo  = (const float*)d_in[18];
    const int*   step = (const int*)d_in[19];

    float* out = (float*)d_out;
    float* out_pred = out;           // [1024]
    float* out_avg  = out + 1024;    // [1]
    float* out_nh   = out + 1025;    // [4096*1024]

    float* pA1G1  = symf(g_A1G1);
    float* pOut   = symf(g_out);
    float* pGi    = symf(g_gi);
    float* pGh    = symf(g_gh);
    float* pBcat1 = symf(g_Bcat1);
    float* pBias1 = symf(g_bias1);
    float* pWcat2 = symf(g_Wcat2);
    float* pMcat  = symf(g_Mcat);
    float* pVih   = symf(g_vih);
    float* pTens  = symf(g_tension);

    // init + precomputes
    k_zero<<<32, 256>>>();
    k_prep<<<1024, 256>>>(Wa1, Wg1, Wa2, Wg2, ba2, bg2);
    k_bias1<<<256, 256>>>(Wa1, ba1, Wg1, bg1, x);
    k_vih<<<3072, 256>>>(W_ih, b_ih);

    // vote round (independent)
    k_vote<<<N_CELLS, 256>>>(influence, opinions, noise);

    // Mcat = [W_ih_o @ Wa2 | -W_ih_o @ Wg2]   (3072 x 256); A lda=1025 (odd) -> scalar loads
    gemm_mma<false, false, false, false><<<dim3(1, 24), 256>>>(
        W_ih, GIN, Wa2, 128, pMcat, 256, 1024,
        nullptr, nullptr, nullptr, 0, 1.f);
    gemm_mma<false, false, false, false><<<dim3(1, 24), 256>>>(
        W_ih, GIN, Wg2, 128, pMcat + 128, 256, 1024,
        nullptr, nullptr, nullptr, 0, -1.f);

    // A1G1 = relu(hiddens @ Bcat1^T + bias1)   (4096 x 256)
    gemm_mma<true, true, true, false><<<dim3(2, 32), 256>>>(
        hiddens, 1024, pBcat1, 1024, pA1G1, 256, 1024,
        pBias1, nullptr, nullptr, 0, 1.f);

    // out = A1G1 @ Wcat2^T + bconst            (4096 x 1024)
    gemm_mma<true, true, false, false><<<dim3(8, 32), 256>>>(
        pA1G1, 256, pWcat2, 256, pOut, 1024, 256,
        symf(g_bconst), nullptr, nullptr, 0, 1.f);

    k_tension<<<N_CELLS, 256>>>();

    // gh = hiddens @ W_hh^T + b_hh             (4096 x 3072)
    gemm_mma<true, true, false, false><<<dim3(24, 32), 256>>>(
        hiddens, 1024, W_hh, 1024, pGh, G3, 1024,
        b_hh, nullptr, nullptr, 0, 1.f);

    // gi = A1G1 @ Mcat^T + vih + tension * W_ih[:,1024]   (4096 x 3072)
    gemm_mma<true, true, false, true><<<dim3(24, 32), 256>>>(
        pA1G1, 256, pMcat, 256, pGi, G3, 256,
        pVih, pTens, W_ih + 1024, GIN, 1.f);

    k_gru<<<N_CELLS, 256>>>(hiddens);
    k_segsum<<<dim3(4, 32), 256>>>();
    k_blend<<<dim3(4, 64), 256>>>();
    k_glob<<<4, 256>>>();
    k_final<<<N_CELLS, 256>>>(out_nh, step);

    k_softmax<<<1, 1024>>>(out_avg);
    k_combined<<<dim3(4, 32), 256>>>();
    k_pred<<<1024, 256>>>(Wo, bo, out_pred);
}

// round 4
// speedup vs baseline: 2.4630x; 1.5323x over previous
#include <cuda_runtime.h>
#include <cuda_bf16.h>
#include <math.h>
#include <stdint.h>

#define N_CELLS 4096
#define IN_DIM 1024
#define HID 1024
#define OUT_DIM 1024
#define MID 128
#define NT 8
#define NF 8
#define GIN 1025
#define G3 3072

typedef __nv_bfloat16 bf16;
typedef __nv_bfloat162 bf162;

// ---------------- scratch (device globals; no allocations allowed) ----------------
// bf16 hi/lo split operands
__device__ bf16 g_hid_h[N_CELLS * HID],   g_hid_l[N_CELLS * HID];
__device__ bf16 g_wih_h[G3 * 1024],       g_wih_l[G3 * 1024];
__device__ bf16 g_whh_h[G3 * 1024],       g_whh_l[G3 * 1024];
__device__ bf16 g_b1_h[256 * 1024],       g_b1_l[256 * 1024];     // [Wa1h;Wg1h]
__device__ bf16 g_wc2_h[1024 * 256],      g_wc2_l[1024 * 256];    // [Wa2|-Wg2] rows j
__device__ bf16 g_w2t_h[256 * 1024],      g_w2t_l[256 * 1024];    // rows m: Wa2[:,m]; -Wg2[:,m]
__device__ bf16 g_mcat_h[G3 * 256],       g_mcat_l[G3 * 256];
__device__ bf16 g_a1g1_h[N_CELLS * 256],  g_a1g1_l[N_CELLS * 256];
// fp32 intermediates
__device__ float g_out[N_CELLS * OUT_DIM];
__device__ float g_gi[N_CELLS * G3];
__device__ float g_gh[N_CELLS * G3];
__device__ float g_nh[N_CELLS * HID];
__device__ float g_tension[N_CELLS];
__device__ float g_energy[N_CELLS];
__device__ int   g_votes[N_CELLS];
__device__ float g_bias1[256];
__device__ float g_bconst[1024];
__device__ float g_vih[G3];
__device__ float g_counts[NT];
__device__ float g_sums[NT * HID];
__device__ float g_fsums[NF * HID];
__device__ float g_glob[HID];
__device__ float g_w[N_CELLS];
__device__ float g_combined[OUT_DIM];

// ---------------- asm helpers ----------------
__device__ __forceinline__ uint32_t smem_u32(const void* p) {
    uint32_t a;
    asm("{ .reg .u64 t; cvta.to.shared.u64 t, %1; cvt.u32.u64 %0, t; }" : "=r"(a) : "l"(p));
    return a;
}
__device__ __forceinline__ void cpa16(uint32_t s, const void* g) {
    asm volatile("cp.async.cg.shared.global [%0], [%1], 16;" :: "r"(s), "l"(g));
}
__device__ __forceinline__ void cp_commit() {
    asm volatile("cp.async.commit_group;" ::: "memory");
}
template <int N>
__device__ __forceinline__ void cp_wait() {
    asm volatile("cp.async.wait_group %0;" :: "n"(N) : "memory");
}
__device__ __forceinline__ void ldsm4(uint32_t& r0, uint32_t& r1, uint32_t& r2, uint32_t& r3,
                                      uint32_t a) {
    asm volatile("ldmatrix.sync.aligned.m8n8.x4.shared.b16 {%0,%1,%2,%3}, [%4];"
                 : "=r"(r0), "=r"(r1), "=r"(r2), "=r"(r3) : "r"(a));
}
__device__ __forceinline__ void mma16816(float c[4], const uint32_t a[4], const uint32_t b[2])
{
    asm("mma.sync.aligned.m16n8k16.row.col.f32.bf16.bf16.f32 "
        "{%0,%1,%2,%3}, {%4,%5,%6,%7}, {%8,%9}, {%0,%1,%2,%3};"
        : "+f"(c[0]), "+f"(c[1]), "+f"(c[2]), "+f"(c[3])
        : "r"(a[0]), "r"(a[1]), "r"(a[2]), "r"(a[3]), "r"(b[0]), "r"(b[1]));
}
__device__ __forceinline__ void split_bf16(float x, bf16& hi, bf16& lo)
{
    hi = __float2bfloat16_rn(x);
    lo = __float2bfloat16_rn(x - __bfloat162float(hi));
}

// =============== bf16 split-pipelined GEMM ===============
// C[MxN] = (Ahi+Alo)[M,K] @ (Bhi+Blo)[N,K]^T (3-product), +bias, +rowv*colv, relu,
// output fp32 C or bf16 hi/lo pair (Chi/Clo).
// CTA 128x128, K-chunk 64, 2-stage cp.async pipeline, SW128 swizzle, ldmatrix frags.
#define MATB 16384
#define STAGEB 65536
#define GEMM_SMEM (2 * STAGEB)

template <bool RELU, bool HASROW, bool WRITEBF>
__global__ void __launch_bounds__(256) gemm_bf(
    const bf16* __restrict__ Ahi, const bf16* __restrict__ Alo, int lda,
    const bf16* __restrict__ Bhi, const bf16* __restrict__ Blo, int ldb,
    float* __restrict__ C, bf16* __restrict__ Chi, bf16* __restrict__ Clo, int ldc,
    int K,
    const float* __restrict__ bias,
    const float* __restrict__ rowv,
    const float* __restrict__ colv, int cs)
{
    extern __shared__ __align__(1024) char smem[];
    const uint32_t sb = smem_u32(smem);
    const int tid = threadIdx.x;
    const int wid = tid >> 5, lane = tid & 31;
    const int wm = wid & 3, wn = wid >> 2;
    const int g = lane >> 2, tg = lane & 3;
    const int m0 = blockIdx.y * 128, n0 = blockIdx.x * 128;
    const int nc = K >> 6;

    float acc[2][8][4];
#pragma unroll
    for (int mi = 0; mi < 2; mi++)
#pragma unroll
        for (int ni = 0; ni < 8; ni++)
#pragma unroll
            for (int q = 0; q < 4; q++) acc[mi][ni][q] = 0.f;

    // ---- stage loader ----
    auto load_stage = [&](int c, int b) {
        const uint32_t s0 = sb + b * STAGEB;
        const int k0 = c << 6;
#pragma unroll
        for (int it = 0; it < 4; it++) {
            int idx = tid + it * 256;
            int row = idx >> 3, ch = idx & 7;
            uint32_t so = (uint32_t)(row << 7) + (uint32_t)((ch ^ (row & 7)) << 4);
            size_t goA = (size_t)(m0 + row) * lda + k0 + ch * 8;
            size_t goB = (size_t)(n0 + row) * ldb + k0 + ch * 8;
            cpa16(s0 + so,             Ahi + goA);
            cpa16(s0 + MATB + so,      Alo + goA);
            cpa16(s0 + 2 * MATB + so,  Bhi + goB);
            cpa16(s0 + 3 * MATB + so,  Blo + goB);
        }
        cp_commit();
    };

    const int j = lane >> 3;
    const int arow_b = wm * 32 + (j & 1) * 8 + (lane & 7);
    const int brow_b = wn * 64 + (j >> 1) * 8 + (lane & 7);

    load_stage(0, 0);

    for (int c = 0; c < nc; c++) {
        if (c + 1 < nc) { load_stage(c + 1, (c + 1) & 1); cp_wait<1>(); }
        else            { cp_wait<0>(); }
        __syncthreads();

        const uint32_t sA = sb + (c & 1) * STAGEB;
        const uint32_t sB = sA + 2 * MATB;

#pragma unroll
        for (int ks = 0; ks < 4; ks++) {
            uint32_t ah[2][4], al[2][4], bh[8][2], bl[8][2];
            const int achunk = ks * 2 + (j >> 1);
            const int bchunk = ks * 2 + (j & 1);
#pragma unroll
            for (int mi = 0; mi < 2; mi++) {
                int r = arow_b + mi * 16;
                uint32_t off = (uint32_t)(r << 7) + (uint32_t)((achunk ^ (r & 7)) << 4);
                ldsm4(ah[mi][0], ah[mi][1], ah[mi][2], ah[mi][3], sA + off);
                ldsm4(al[mi][0], al[mi][1], al[mi][2], al[mi][3], sA + MATB + off);
            }
#pragma unroll
            for (int nb = 0; nb < 4; nb++) {
                int r = brow_b + nb * 16;
                uint32_t off = (uint32_t)(r << 7) + (uint32_t)((bchunk ^ (r & 7)) << 4);
                uint32_t t0, t1, t2, t3;
                ldsm4(t0, t1, t2, t3, sB + off);
                bh[2 * nb][0] = t0; bh[2 * nb][1] = t1;
                bh[2 * nb + 1][0] = t2; bh[2 * nb + 1][1] = t3;
                ldsm4(t0, t1, t2, t3, sB + MATB + off);
                bl[2 * nb][0] = t0; bl[2 * nb][1] = t1;
                bl[2 * nb + 1][0] = t2; bl[2 * nb + 1][1] = t3;
            }
#pragma unroll
            for (int mi = 0; mi < 2; mi++)
#pragma unroll
                for (int ni = 0; ni < 8; ni++) {
                    mma16816(acc[mi][ni], ah[mi], bh[ni]);
                    mma16816(acc[mi][ni], ah[mi], bl[ni]);
                    mma16816(acc[mi][ni], al[mi], bh[ni]);
                }
        }
        __syncthreads();
    }

    // ---- epilogue ----
#pragma unroll
    for (int mi = 0; mi < 2; mi++) {
        int row0 = m0 + wm * 32 + mi * 16 + g;
        float rv0 = HASROW ? rowv[row0] : 0.f;
        float rv1 = HASROW ? rowv[row0 + 8] : 0.f;
#pragma unroll
        for (int ni = 0; ni < 8; ni++) {
            int col = n0 + wn * 64 + ni * 8 + tg * 2;
            float b0 = bias ? bias[col] : 0.f;
            float b1 = bias ? bias[col + 1] : 0.f;
            float v0 = acc[mi][ni][0] + b0;
            float v1 = acc[mi][ni][1] + b1;
            float v2 = acc[mi][ni][2] + b0;
            float v3 = acc[mi][ni][3] + b1;
            if (HASROW) {
                float cv0 = colv[(size_t)col * cs];
                float cv1 = colv[(size_t)(col + 1) * cs];
                v0 += rv0 * cv0; v1 += rv0 * cv1; v2 += rv1 * cv0; v3 += rv1 * cv1;
            }
            if (RELU) {
                v0 = fmaxf(v0, 0.f); v1 = fmaxf(v1, 0.f);
                v2 = fmaxf(v2, 0.f); v3 = fmaxf(v3, 0.f);
            }
            if (WRITEBF) {
                bf16 h0, l0, h1, l1;
                bf162 hp, lp;
                split_bf16(v0, h0, l0); split_bf16(v1, h1, l1);
                hp.x = h0; hp.y = h1; lp.x = l0; lp.y = l1;
                *(bf162*)(Chi + (size_t)row0 * ldc + col) = hp;
                *(bf162*)(Clo + (size_t)row0 * ldc + col) = lp;
                split_bf16(v2, h0, l0); split_bf16(v3, h1, l1);
                hp.x = h0; hp.y = h1; lp.x = l0; lp.y = l1;
                *(bf162*)(Chi + (size_t)(row0 + 8) * ldc + col) = hp;
                *(bf162*)(Clo + (size_t)(row0 + 8) * ldc + col) = lp;
            } else {
                float2 p0; p0.x = v0; p0.y = v1;
                float2 p1; p1.x = v2; p1.y = v3;
                *(float2*)(C + (size_t)row0 * ldc + col) = p0;
                *(float2*)(C + (size_t)(row0 + 8) * ldc + col) = p1;
            }
        }
    }
}

// ---------------- conversion / prep kernels ----------------
// generic: src fp32 [M,1024] (row stride ld) -> hi/lo bf16 packed [M,1024]
__global__ void k_cvt1024(const float* __restrict__ src, int ld,
                          bf16* __restrict__ hi, bf16* __restrict__ lo, int total)
{
    int i = blockIdx.x * 256 + threadIdx.x;
    if (i >= total) return;
    int r = i >> 10, c = i & 1023;
    float v = src[(size_t)r * ld + c];
    bf16 h, l; split_bf16(v, h, l);
    hi[i] = h; lo[i] = l;
}

// Bcat1 rows: r<128 -> Wa1[r][1024+k]; else Wg1[r-128][1024+k]
__global__ void k_cvt_b1(const float* __restrict__ Wa1, const float* __restrict__ Wg1)
{
    int i = blockIdx.x * 256 + threadIdx.x;   // 256*1024
    int r = i >> 10, k = i & 1023;
    float v = (r < 128) ? Wa1[r * 2048 + 1024 + k] : Wg1[(r - 128) * 2048 + 1024 + k];
    bf16 h, l; split_bf16(v, h, l);
    g_b1_h[i] = h; g_b1_l[i] = l;
}

// Wcat2 [1024,256] and its transpose W2T [256,1024]
__global__ void k_cvt_w2(const float* __restrict__ Wa2, const float* __restrict__ Wg2)
{
    int i = blockIdx.x * 256 + threadIdx.x;   // 1024*128
    if (i >= 1024 * 128) return;
    int jr = i >> 7, m = i & 127;
    float va = Wa2[i], vg = -Wg2[i];
    bf16 h, l;
    split_bf16(va, h, l);
    g_wc2_h[jr * 256 + m] = h;          g_wc2_l[jr * 256 + m] = l;
    g_w2t_h[m * 1024 + jr] = h;         g_w2t_l[m * 1024 + jr] = l;
    split_bf16(vg, h, l);
    g_wc2_h[jr * 256 + 128 + m] = h;    g_wc2_l[jr * 256 + 128 + m] = l;
    g_w2t_h[(128 + m) * 1024 + jr] = h; g_w2t_l[(128 + m) * 1024 + jr] = l;
}

__global__ void k_bconst(const float* __restrict__ ba2, const float* __restrict__ bg2)
{
    int i = blockIdx.x * 256 + threadIdx.x;
    if (i < 1024) g_bconst[i] = ba2[i] - bg2[i];
}

__global__ void k_zero()
{
    int i = blockIdx.x * 256 + threadIdx.x;
    if (i < NT) g_counts[i] = 0.f;
    if (i < NT * HID) { g_sums[i] = 0.f; g_fsums[i] = 0.f; }
    if (i < OUT_DIM) { g_combined[i] = 0.f; g_glob[i] = 0.f; }
}

__global__ void k_bias1(const float* __restrict__ Wa1, const float* __restrict__ ba1,
                        const float* __restrict__ Wg1, const float* __restrict__ bg1,
                        const float* __restrict__ x)
{
    int b = blockIdx.x;
    const float* row = (b < 128) ? (Wa1 + (size_t)b * 2048) : (Wg1 + (size_t)(b - 128) * 2048);
    float s = 0.f;
    for (int jj = threadIdx.x; jj < 1024; jj += 256) s += row[jj] * x[jj];
    __shared__ float sh[256];
    sh[threadIdx.x] = s; __syncthreads();
    for (int o = 128; o > 0; o >>= 1) {
        if (threadIdx.x < o) sh[threadIdx.x] += sh[threadIdx.x + o];
        __syncthreads();
    }
    if (threadIdx.x == 0)
        g_bias1[b] = sh[0] + ((b < 128) ? ba1[b] : bg1[b - 128]);
}

__global__ void k_vih(const float* __restrict__ W_ih, const float* __restrict__ b_ih)
{
    int k = blockIdx.x;
    const float* row = W_ih + (size_t)k * GIN;
    float s = 0.f;
    for (int jj = threadIdx.x; jj < 1024; jj += 256) s += row[jj] * g_bconst[jj];
    __shared__ float sh[256];
    sh[threadIdx.x] = s; __syncthreads();
    for (int o = 128; o > 0; o >>= 1) {
        if (threadIdx.x < o) sh[threadIdx.x] += sh[threadIdx.x + o];
        __syncthreads();
    }
    if (threadIdx.x == 0) g_vih[k] = sh[0] + b_ih[k];
}

__global__ void k_vote(const float* __restrict__ infl, const float* __restrict__ op,
                       const float* __restrict__ noise)
{
    int row = blockIdx.x;
    int tid = threadIdx.x;
    float acc[NT];
#pragma unroll
    for (int t = 0; t < NT; t++) acc[t] = 0.f;
    const float* ir = infl + (size_t)row * N_CELLS;
    for (int c = tid; c < N_CELLS; c += 256) {
        float w = ir[c];
        if (w != 0.f) {
#pragma unroll
            for (int t = 0; t < NT; t++) acc[t] += w * op[c * NT + t];
        }
    }
    __shared__ float sh[256];
    __shared__ float s8[NT];
    for (int t = 0; t < NT; t++) {
        sh[tid] = acc[t]; __syncthreads();
        for (int o = 128; o > 0; o >>= 1) {
            if (tid < o) sh[tid] += sh[tid + o];
            __syncthreads();
        }
        if (tid == 0) s8[t] = sh[0];
        __syncthreads();
    }
    if (tid == 0) {
        float v[NT]; float sum = 0.f;
#pragma unroll
        for (int t = 0; t < NT; t++) {
            float u = 0.7f * op[row * NT + t] + 0.3f * s8[t] + 0.01f * noise[row * NT + t];
            u = fmaxf(u, 0.01f);
            v[t] = u; sum += u;
        }
        float inv = 1.f / sum;
        int am = 0; float mx = v[0] * inv;
#pragma unroll
        for (int t = 1; t < NT; t++) {
            float u = v[t] * inv;
            if (u > mx) { mx = u; am = t; }
        }
        g_votes[row] = am;
        g_energy[row] = mx;
        atomicAdd(&g_counts[am], 1.f);
    }
}

__global__ void k_tension()
{
    int i = blockIdx.x, tid = threadIdx.x;
    const float* o = g_out + (size_t)i * 1024;
    float s = 0.f;
    for (int jj = tid; jj < 1024; jj += 256) { float v = o[jj]; s += v * v; }
    __shared__ float sh[256];
    sh[tid] = s; __syncthreads();
    for (int off = 128; off > 0; off >>= 1) {
        if (tid < off) sh[tid] += sh[tid + off];
        __syncthreads();
    }
    if (tid == 0) g_tension[i] = sh[0] * (1.f / 1024.f);
}

__global__ void k_gru(const float* __restrict__ hiddens)
{
    int i = blockIdx.x;
    float scale = 0.9f + 0.2f * g_energy[i];
    const float* gi = g_gi + (size_t)i * G3;
    const float* gh = g_gh + (size_t)i * G3;
    for (int jj = threadIdx.x; jj < HID; jj += 256) {
        float r = 1.f / (1.f + expf(-(gi[jj] + gh[jj])));
        float z = 1.f / (1.f + expf(-(gi[jj + 1024] + gh[jj + 1024])));
        float n = tanhf(gi[jj + 2048] + r * gh[jj + 2048]);
        float h = hiddens[(size_t)i * 1024 + jj];
        float nh = (1.f - z) * n + z * h;
        nh = fminf(fmaxf(nh * scale, -10.f), 10.f);
        g_nh[(size_t)i * HID + jj] = nh;
    }
}

__global__ void k_segsum()
{
    int c = blockIdx.x * 256 + threadIdx.x;
    int r0 = blockIdx.y * 128;
    float acc[NT];
#pragma unroll
    for (int q = 0; q < NT; q++) acc[q] = 0.f;
    for (int r = r0; r < r0 + 128; r++) {
        float v = g_nh[(size_t)r * HID + c];
        int t = g_votes[r];
#pragma unroll
        for (int q = 0; q < NT; q++) acc[q] += (t == q) ? v : 0.f;
    }
#pragma unroll
    for (int q = 0; q < NT; q++) atomicAdd(&g_sums[q * HID + c], acc[q]);
}

__global__ void k_blend()
{
    int c = blockIdx.x * 256 + threadIdx.x;
    int r0 = blockIdx.y * 64;
    int f = r0 >> 9;
    float facc = 0.f;
    for (int r = r0; r < r0 + 64; r++) {
        int t = g_votes[r];
        float cnt = g_counts[t];
        float v = g_nh[(size_t)r * HID + c];
        if (cnt >= 2.f)
            v = 0.85f * v + 0.15f * (g_sums[t * HID + c] / fmaxf(cnt, 1.f));
        g_nh[(size_t)r * HID + c] = v;
        facc += v;
    }
    atomicAdd(&g_fsums[f * HID + c], facc);
}

__global__ void k_glob()
{
    int jj = blockIdx.x * 256 + threadIdx.x;
    float s = 0.f;
#pragma unroll
    for (int f = 0; f < NF; f++) s += g_fsums[f * HID + jj];
    g_glob[jj] = s * (1.f / 4096.f);
}

__global__ void k_final(float* __restrict__ out_nh, const int* __restrict__ step)
{
    int i = blockIdx.x;
    int f = i >> 9;
    bool dcz = (*step > 5) && ((i & 511) < 128);
    for (int jj = threadIdx.x; jj < HID; jj += 256) {
        float fm = g_fsums[f * HID + jj] * (1.f / 512.f);
        float v = 0.85f * g_nh[(size_t)i * HID + jj] + 0.15f * fm;
        if (dcz) v = 0.85f * v + 0.15f * g_glob[jj];
        out_nh[(size_t)i * HID + jj] = v;
    }
}

__global__ void k_softmax(float* __restrict__ out_avg)
{
    __shared__ float sh[1024];
    int tid = threadIdx.x;
    float t4[4];
    float mx = -1e30f, av = 0.f;
#pragma unroll
    for (int q = 0; q < 4; q++) {
        t4[q] = g_tension[tid + q * 1024];
        mx = fmaxf(mx, t4[q]);
        av += t4[q];
    }
    sh[tid] = mx; __syncthreads();
    for (int o = 512; o > 0; o >>= 1) {
        if (tid < o) sh[tid] = fmaxf(sh[tid], sh[tid + o]);
        __syncthreads();
    }
    float M = sh[0]; __syncthreads();
    float sm = 0.f;
#pragma unroll
    for (int q = 0; q < 4; q++) {
        float e = expf(t4[q] - M);
        g_w[tid + q * 1024] = e;
        sm += e;
    }
    sh[tid] = sm; __syncthreads();
    for (int o = 512; o > 0; o >>= 1) {
        if (tid < o) sh[tid] += sh[tid + o];
        __syncthreads();
    }
    float inv = 1.f / sh[0]; __syncthreads();
#pragma unroll
    for (int q = 0; q < 4; q++) g_w[tid + q * 1024] *= inv;
    sh[tid] = av; __syncthreads();
    for (int o = 512; o > 0; o >>= 1) {
        if (tid < o) sh[tid] += sh[tid + o];
        __syncthreads();
    }
    if (tid == 0) out_avg[0] = sh[0] * (1.f / 4096.f);
}

__global__ void k_combined()
{
    int c = blockIdx.x * 256 + threadIdx.x;
    int r0 = blockIdx.y * 128;
    float acc = 0.f;
    for (int r = r0; r < r0 + 128; r++)
        acc += g_w[r] * g_out[(size_t)r * 1024 + c];
    atomicAdd(&g_combined[c], acc);
}

__global__ void k_pred(const float* __restrict__ Wo, const float* __restrict__ bo,
                       float* __restrict__ out_pred)
{
    int i = blockIdx.x;
    const float* row = Wo + (size_t)i * 1024;
    float s = 0.f;
    for (int jj = threadIdx.x; jj < 1024; jj += 256) s += g_combined[jj] * row[jj];
    __shared__ float sh[256];
    sh[threadIdx.x] = s; __syncthreads();
    for (int o = 128; o > 0; o >>= 1) {
        if (threadIdx.x < o) sh[threadIdx.x] += sh[threadIdx.x + o];
        __syncthreads();
    }
    if (threadIdx.x == 0) out_pred[i] = sh[0] + bo[i];
}

// ---------------- launch ----------------
template <typename T>
static T* symp(const void* s)
{
    void* p = nullptr;
    cudaGetSymbolAddress(&p, s);
    return (T*)p;
}

extern "C" void kernel_launch(void* const* d_in, const int* in_sizes, int n_in,
                              void* d_out, int out_size)
{
    const float* x        = (const float*)d_in[0];
    const float* hiddens  = (const float*)d_in[1];
    const float* opinions = (const float*)d_in[2];
    const float* influence= (const float*)d_in[3];
    const float* noise    = (const float*)d_in[4];
    const float* Wa1 = (const float*)d_in[5];
    const float* ba1 = (const float*)d_in[6];
    const float* Wa2 = (const float*)d_in[7];
    const float* ba2 = (const float*)d_in[8];
    const float* Wg1 = (const float*)d_in[9];
    const float* bg1 = (const float*)d_in[10];
    const float* Wg2 = (const float*)d_in[11];
    const float* bg2 = (const float*)d_in[12];
    const float* W_ih = (const float*)d_in[13];
    const float* b_ih = (const float*)d_in[14];
    const float* W_hh = (const float*)d_in[15];
    const float* b_hh = (const float*)d_in[16];
    const float* Wo  = (const float*)d_in[17];
    const float* bo  = (const float*)d_in[18];
    const int*   step = (const int*)d_in[19];

    float* out = (float*)d_out;
    float* out_pred = out;
    float* out_avg  = out + 1024;
    float* out_nh   = out + 1025;

    bf16* pHidH = symp<bf16>(g_hid_h);  bf16* pHidL = symp<bf16>(g_hid_l);
    bf16* pWihH = symp<bf16>(g_wih_h);  bf16* pWihL = symp<bf16>(g_wih_l);
    bf16* pWhhH = symp<bf16>(g_whh_h);  bf16* pWhhL = symp<bf16>(g_whh_l);
    bf16* pB1H  = symp<bf16>(g_b1_h);   bf16* pB1L  = symp<bf16>(g_b1_l);
    bf16* pWc2H = symp<bf16>(g_wc2_h);  bf16* pWc2L = symp<bf16>(g_wc2_l);
    bf16* pW2TH = symp<bf16>(g_w2t_h);  bf16* pW2TL = symp<bf16>(g_w2t_l);
    bf16* pMcH  = symp<bf16>(g_mcat_h); bf16* pMcL  = symp<bf16>(g_mcat_l);
    bf16* pAgH  = symp<bf16>(g_a1g1_h); bf16* pAgL  = symp<bf16>(g_a1g1_l);
    float* pOut = symp<float>(g_out);
    float* pGi  = symp<float>(g_gi);
    float* pGh  = symp<float>(g_gh);
    float* pBias1 = symp<float>(g_bias1);
    float* pBconst= symp<float>(g_bconst);
    float* pVih = symp<float>(g_vih);
    float* pTens= symp<float>(g_tension);

    static bool attr_done = false;
    if (!attr_done) {
        cudaFuncSetAttribute(gemm_bf<false, false, true>,
                             cudaFuncAttributeMaxDynamicSharedMemorySize, GEMM_SMEM);
        cudaFuncSetAttribute(gemm_bf<true, false, true>,
                             cudaFuncAttributeMaxDynamicSharedMemorySize, GEMM_SMEM);
        cudaFuncSetAttribute(gemm_bf<false, false, false>,
                             cudaFuncAttributeMaxDynamicSharedMemorySize, GEMM_SMEM);
        cudaFuncSetAttribute(gemm_bf<false, true, false>,
                             cudaFuncAttributeMaxDynamicSharedMemorySize, GEMM_SMEM);
        attr_done = true;
    }

    // init + conversions
    k_zero<<<32, 256>>>();
    k_bconst<<<4, 256>>>(ba2, bg2);
    k_cvt1024<<<(N_CELLS * 1024) / 256, 256>>>(hiddens, 1024, pHidH, pHidL, N_CELLS * 1024);
    k_cvt1024<<<(G3 * 1024) / 256, 256>>>(W_ih, GIN, pWihH, pWihL, G3 * 1024);
    k_cvt1024<<<(G3 * 1024) / 256, 256>>>(W_hh, 1024, pWhhH, pWhhL, G3 * 1024);
    k_cvt_b1<<<1024, 256>>>(Wa1, Wg1);
    k_cvt_w2<<<512, 256>>>(Wa2, Wg2);
    k_bias1<<<256, 256>>>(Wa1, ba1, Wg1, bg1, x);
    k_vih<<<3072, 256>>>(W_ih, b_ih);

    // vote round (independent)
    k_vote<<<N_CELLS, 256>>>(influence, opinions, noise);

    // Mcat[3072,256] = Wih @ W2T^T -> bf16 hi/lo
    gemm_bf<false, false, true><<<dim3(2, 24), 256, GEMM_SMEM>>>(
        pWihH, pWihL, 1024, pW2TH, pW2TL, 1024,
        nullptr, pMcH, pMcL, 256, 1024, nullptr, nullptr, nullptr, 0);

    // A1G1[4096,256] = relu(hid @ Bcat1^T + bias1) -> bf16 hi/lo
    gemm_bf<true, false, true><<<dim3(2, 32), 256, GEMM_SMEM>>>(
        pHidH, pHidL, 1024, pB1H, pB1L, 1024,
        nullptr, pAgH, pAgL, 256, 1024, pBias1, nullptr, nullptr, 0);

    // out[4096,1024] = A1G1 @ Wcat2^T + bconst -> fp32
    gemm_bf<false, false, false><<<dim3(8, 32), 256, GEMM_SMEM>>>(
        pAgH, pAgL, 256, pWc2H, pWc2L, 256,
        pOut, nullptr, nullptr, 1024, 256, pBconst, nullptr, nullptr, 0);

    k_tension<<<N_CELLS, 256>>>();

    // gh[4096,3072] = hid @ W_hh^T + b_hh -> fp32
    gemm_bf<false, false, false><<<dim3(24, 32), 256, GEMM_SMEM>>>(
        pHidH, pHidL, 1024, pWhhH, pWhhL, 1024,
        pGh, nullptr, nullptr, G3, 1024, b_hh, nullptr, nullptr, 0);

    // gi[4096,3072] = A1G1 @ Mcat^T + vih + tension * W_ih[:,1024] -> fp32
    gemm_bf<false, true, false><<<dim3(24, 32), 256, GEMM_SMEM>>>(
        pAgH, pAgL, 256, pMcH, pMcL, 256,
        pGi, nullptr, nullptr, G3, 256, pVih, pTens, W_ih + 1024, GIN);

    k_gru<<<N_CELLS, 256>>>(hiddens);
    k_segsum<<<dim3(4, 32), 256>>>();
    k_blend<<<dim3(4, 64), 256>>>();
    k_glob<<<4, 256>>>();
    k_final<<<N_CELLS, 256>>>(out_nh, step);

    k_softmax<<<1, 1024>>>(out_avg);
    k_combined<<<dim3(4, 32), 256>>>();
    k_pred<<<1024, 256>>>(Wo, bo, out_pred);
}

// round 5
// speedup vs baseline: 2.8894x; 1.1731x over previous
#include <cuda_runtime.h>
#include <cuda_bf16.h>
#include <math.h>
#include <stdint.h>

#define N_CELLS 4096
#define IN_DIM 1024
#define HID 1024
#define OUT_DIM 1024
#define NT 8
#define NF 8
#define GIN 1025
#define G3 3072

typedef __nv_bfloat16 bf16;
typedef __nv_bfloat162 bf162;

// ---------------- scratch (device globals) ----------------
__device__ bf16 g_hid_h[N_CELLS * HID],   g_hid_l[N_CELLS * HID];
__device__ bf16 g_wih_h[G3 * 1024],       g_wih_l[G3 * 1024];
__device__ bf16 g_whh_h[G3 * 1024],       g_whh_l[G3 * 1024];
__device__ bf16 g_b1_h[256 * 1024],       g_b1_l[256 * 1024];
__device__ bf16 g_wc2_h[1024 * 256],      g_wc2_l[1024 * 256];
__device__ bf16 g_w2t_h[256 * 1024],      g_w2t_l[256 * 1024];
__device__ bf16 g_mcat_h[G3 * 256],       g_mcat_l[G3 * 256];
__device__ bf16 g_a1g1_h[N_CELLS * 256],  g_a1g1_l[N_CELLS * 256];
__device__ float g_out[N_CELLS * OUT_DIM];
__device__ float g_gi[N_CELLS * G3];
__device__ float g_gh[N_CELLS * G3];
__device__ float g_nh[N_CELLS * HID];
__device__ float g_tension[N_CELLS];
__device__ float g_energy[N_CELLS];
__device__ int   g_votes[N_CELLS];
__device__ float g_bias1[256];
__device__ float g_bconst[1024];
__device__ float g_vih[G3];
__device__ float g_wt[G3];
__device__ float g_counts[NT];
__device__ float g_sums[NT * HID];
__device__ float g_fsums[NF * HID];
__device__ float g_glob[HID];
__device__ float g_w[N_CELLS];
__device__ float g_combined[OUT_DIM];

// ---------------- asm helpers ----------------
__device__ __forceinline__ uint32_t smem_u32(const void* p) {
    uint32_t a;
    asm("{ .reg .u64 t; cvta.to.shared.u64 t, %1; cvt.u32.u64 %0, t; }" : "=r"(a) : "l"(p));
    return a;
}
__device__ __forceinline__ void cpa16(uint32_t s, const void* g) {
    asm volatile("cp.async.cg.shared.global [%0], [%1], 16;" :: "r"(s), "l"(g));
}
__device__ __forceinline__ void cp_commit() {
    asm volatile("cp.async.commit_group;" ::: "memory");
}
template <int N>
__device__ __forceinline__ void cp_wait() {
    asm volatile("cp.async.wait_group %0;" :: "n"(N) : "memory");
}
__device__ __forceinline__ void ldsm4(uint32_t& r0, uint32_t& r1, uint32_t& r2, uint32_t& r3,
                                      uint32_t a) {
    asm volatile("ldmatrix.sync.aligned.m8n8.x4.shared.b16 {%0,%1,%2,%3}, [%4];"
                 : "=r"(r0), "=r"(r1), "=r"(r2), "=r"(r3) : "r"(a));
}
__device__ __forceinline__ void mma16816(float c[4], const uint32_t a[4], const uint32_t b[2])
{
    asm("mma.sync.aligned.m16n8k16.row.col.f32.bf16.bf16.f32 "
        "{%0,%1,%2,%3}, {%4,%5,%6,%7}, {%8,%9}, {%0,%1,%2,%3};"
        : "+f"(c[0]), "+f"(c[1]), "+f"(c[2]), "+f"(c[3])
        : "r"(a[0]), "r"(a[1]), "r"(a[2]), "r"(a[3]), "r"(b[0]), "r"(b[1]));
}
__device__ __forceinline__ void split_bf16(float x, bf16& hi, bf16& lo)
{
    hi = __float2bfloat16_rn(x);
    lo = __float2bfloat16_rn(x - __bfloat162float(hi));
}

// =============== bf16 split-pipelined GEMM ===============
// C[MxN] = (Ahi+Alo)[M,K] @ (Bhi+Blo)[N,K]^T (3-product), +bias, optional relu,
// output fp32 C or bf16 hi/lo pair, optional fused sum-of-squares into g_tension.
// CTA tile (64*MI) x 128, K-chunk 64, 2-stage cp.async pipeline, swizzled, ldmatrix.
template <int MI, bool RELU, bool WRITEBF, bool SUMSQ>
__global__ void __launch_bounds__(256) gemm_bf(
    const bf16* __restrict__ Ahi, const bf16* __restrict__ Alo, int lda,
    const bf16* __restrict__ Bhi, const bf16* __restrict__ Blo, int ldb,
    float* __restrict__ C, bf16* __restrict__ Chi, bf16* __restrict__ Clo, int ldc,
    int K, const float* __restrict__ bias)
{
    constexpr int TM = 64 * MI;
    constexpr int ABYTES = TM * 128;
    constexpr int BBYTES = 128 * 128;
    constexpr int STAGE = 2 * ABYTES + 2 * BBYTES;

    extern __shared__ __align__(1024) char smem[];
    const uint32_t sb = smem_u32(smem);
    const int tid = threadIdx.x;
    const int wid = tid >> 5, lane = tid & 31;
    const int wm = wid & 3, wn = wid >> 2;
    const int g = lane >> 2, tg = lane & 3;
    const int m0 = blockIdx.y * TM, n0 = blockIdx.x * 128;
    const int nc = K >> 6;

    float acc[MI][8][4];
#pragma unroll
    for (int mi = 0; mi < MI; mi++)
#pragma unroll
        for (int ni = 0; ni < 8; ni++)
#pragma unroll
            for (int q = 0; q < 4; q++) acc[mi][ni][q] = 0.f;

    auto load_stage = [&](int c, int b) {
        const uint32_t s0 = sb + b * STAGE;
        const int k0 = c << 6;
#pragma unroll
        for (int it = 0; it < TM * 8 / 256; it++) {
            int idx = tid + it * 256;
            int row = idx >> 3, ch = idx & 7;
            uint32_t so = (uint32_t)(row << 7) + (uint32_t)((ch ^ (row & 7)) << 4);
            size_t go = (size_t)(m0 + row) * lda + k0 + ch * 8;
            cpa16(s0 + so, Ahi + go);
            cpa16(s0 + ABYTES + so, Alo + go);
        }
#pragma unroll
        for (int it = 0; it < 4; it++) {
            int idx = tid + it * 256;
            int row = idx >> 3, ch = idx & 7;
            uint32_t so = (uint32_t)(row << 7) + (uint32_t)((ch ^ (row & 7)) << 4);
            size_t go = (size_t)(n0 + row) * ldb + k0 + ch * 8;
            cpa16(s0 + 2 * ABYTES + so, Bhi + go);
            cpa16(s0 + 2 * ABYTES + BBYTES + so, Blo + go);
        }
        cp_commit();
    };

    const int j = lane >> 3;
    const int arow_b = wm * (16 * MI) + (j & 1) * 8 + (lane & 7);
    const int brow_b = wn * 64 + (j >> 1) * 8 + (lane & 7);

    load_stage(0, 0);

    for (int c = 0; c < nc; c++) {
        if (c + 1 < nc) { load_stage(c + 1, (c + 1) & 1); cp_wait<1>(); }
        else            { cp_wait<0>(); }
        __syncthreads();

        const uint32_t sA = sb + (c & 1) * STAGE;
        const uint32_t sB = sA + 2 * ABYTES;

#pragma unroll
        for (int ks = 0; ks < 4; ks++) {
            uint32_t bh[8][2], bl[8][2];
            const int achunk = ks * 2 + (j >> 1);
            const int bchunk = ks * 2 + (j & 1);
#pragma unroll
            for (int nb = 0; nb < 4; nb++) {
                int r = brow_b + nb * 16;
                uint32_t off = (uint32_t)(r << 7) + (uint32_t)((bchunk ^ (r & 7)) << 4);
                uint32_t t0, t1, t2, t3;
                ldsm4(t0, t1, t2, t3, sB + off);
                bh[2 * nb][0] = t0; bh[2 * nb][1] = t1;
                bh[2 * nb + 1][0] = t2; bh[2 * nb + 1][1] = t3;
                ldsm4(t0, t1, t2, t3, sB + BBYTES + off);
                bl[2 * nb][0] = t0; bl[2 * nb][1] = t1;
                bl[2 * nb + 1][0] = t2; bl[2 * nb + 1][1] = t3;
            }
#pragma unroll
            for (int mi = 0; mi < MI; mi++) {
                uint32_t ah[4], al[4];
                int r = arow_b + mi * 16;
                uint32_t off = (uint32_t)(r << 7) + (uint32_t)((achunk ^ (r & 7)) << 4);
                ldsm4(ah[0], ah[1], ah[2], ah[3], sA + off);
                ldsm4(al[0], al[1], al[2], al[3], sA + ABYTES + off);
#pragma unroll
                for (int ni = 0; ni < 8; ni++) {
                    mma16816(acc[mi][ni], ah, bh[ni]);
                    mma16816(acc[mi][ni], ah, bl[ni]);
                    mma16816(acc[mi][ni], al, bh[ni]);
                }
            }
        }
        __syncthreads();
    }

    // ---- epilogue ----
#pragma unroll
    for (int mi = 0; mi < MI; mi++) {
        int row0 = m0 + wm * (16 * MI) + mi * 16 + g;
        float p0 = 0.f, p1 = 0.f;
#pragma unroll
        for (int ni = 0; ni < 8; ni++) {
            int col = n0 + wn * 64 + ni * 8 + tg * 2;
            float b0 = bias ? bias[col] : 0.f;
            float b1 = bias ? bias[col + 1] : 0.f;
            float v0 = acc[mi][ni][0] + b0;
            float v1 = acc[mi][ni][1] + b1;
            float v2 = acc[mi][ni][2] + b0;
            float v3 = acc[mi][ni][3] + b1;
            if (RELU) {
                v0 = fmaxf(v0, 0.f); v1 = fmaxf(v1, 0.f);
                v2 = fmaxf(v2, 0.f); v3 = fmaxf(v3, 0.f);
            }
            if (SUMSQ) { p0 += v0 * v0 + v1 * v1; p1 += v2 * v2 + v3 * v3; }
            if (WRITEBF) {
                bf16 h0, l0, h1, l1;
                bf162 hp, lp;
                split_bf16(v0, h0, l0); split_bf16(v1, h1, l1);
                hp.x = h0; hp.y = h1; lp.x = l0; lp.y = l1;
                *(bf162*)(Chi + (size_t)row0 * ldc + col) = hp;
                *(bf162*)(Clo + (size_t)row0 * ldc + col) = lp;
                split_bf16(v2, h0, l0); split_bf16(v3, h1, l1);
                hp.x = h0; hp.y = h1; lp.x = l0; lp.y = l1;
                *(bf162*)(Chi + (size_t)(row0 + 8) * ldc + col) = hp;
                *(bf162*)(Clo + (size_t)(row0 + 8) * ldc + col) = lp;
            } else {
                float2 q0; q0.x = v0; q0.y = v1;
                float2 q1; q1.x = v2; q1.y = v3;
                *(float2*)(C + (size_t)row0 * ldc + col) = q0;
                *(float2*)(C + (size_t)(row0 + 8) * ldc + col) = q1;
            }
        }
        if (SUMSQ) {
            p0 += __shfl_xor_sync(0xffffffffu, p0, 1);
            p0 += __shfl_xor_sync(0xffffffffu, p0, 2);
            p1 += __shfl_xor_sync(0xffffffffu, p1, 1);
            p1 += __shfl_xor_sync(0xffffffffu, p1, 2);
            if (tg == 0) {
                atomicAdd(&g_tension[row0], p0);
                atomicAdd(&g_tension[row0 + 8], p1);
            }
        }
    }
}

// ---------------- prep: all fp32->bf16 hi/lo conversions in one kernel ----------------
__global__ void k_prep_all(const float* __restrict__ hiddens, const float* __restrict__ W_ih,
                           const float* __restrict__ W_hh,
                           const float* __restrict__ Wa1, const float* __restrict__ Wg1,
                           const float* __restrict__ Wa2, const float* __restrict__ Wg2,
                           const float* __restrict__ ba2, const float* __restrict__ bg2)
{
    long i = (long)blockIdx.x * 256 + threadIdx.x;
    const long N0 = 4194304L;            // hiddens
    const long N1 = N0 + 3145728L;       // W_ih
    const long N2 = N1 + 3145728L;       // W_hh
    const long N3 = N2 + 262144L;        // Bcat1
    const long N4 = N3 + 131072L;        // Wcat2 / W2T
    const long N5 = N4 + 1024L;          // bconst
    bf16 h, l;
    if (i < N0) {
        float v = hiddens[i];
        split_bf16(v, h, l); g_hid_h[i] = h; g_hid_l[i] = l;
    } else if (i < N1) {
        long k = i - N0; int r = (int)(k >> 10), c = (int)(k & 1023);
        float v = W_ih[(size_t)r * GIN + c];
        split_bf16(v, h, l); g_wih_h[k] = h; g_wih_l[k] = l;
    } else if (i < N2) {
        long k = i - N1;
        float v = W_hh[k];
        split_bf16(v, h, l); g_whh_h[k] = h; g_whh_l[k] = l;
    } else if (i < N3) {
        long k = i - N2; int r = (int)(k >> 10), c = (int)(k & 1023);
        float v = (r < 128) ? Wa1[r * 2048 + 1024 + c] : Wg1[(r - 128) * 2048 + 1024 + c];
        split_bf16(v, h, l); g_b1_h[k] = h; g_b1_l[k] = l;
    } else if (i < N4) {
        long k = i - N3; int jr = (int)(k >> 7), m = (int)(k & 127);
        float va = Wa2[k], vg = -Wg2[k];
        split_bf16(va, h, l);
        g_wc2_h[jr * 256 + m] = h;          g_wc2_l[jr * 256 + m] = l;
        g_w2t_h[m * 1024 + jr] = h;         g_w2t_l[m * 1024 + jr] = l;
        split_bf16(vg, h, l);
        g_wc2_h[jr * 256 + 128 + m] = h;    g_wc2_l[jr * 256 + 128 + m] = l;
        g_w2t_h[(128 + m) * 1024 + jr] = h; g_w2t_l[(128 + m) * 1024 + jr] = l;
    } else if (i < N5) {
        long k = i - N4;
        g_bconst[k] = ba2[k] - bg2[k];
    }
}

__global__ void k_zero()
{
    int i = blockIdx.x * 256 + threadIdx.x;   // grid covers 8192
    if (i < NT) g_counts[i] = 0.f;
    if (i < NT * HID) { g_sums[i] = 0.f; g_fsums[i] = 0.f; }
    if (i < OUT_DIM) { g_combined[i] = 0.f; g_glob[i] = 0.f; }
    if (i < N_CELLS) g_tension[i] = 0.f;
}

__global__ void k_bias1(const float* __restrict__ Wa1, const float* __restrict__ ba1,
                        const float* __restrict__ Wg1, const float* __restrict__ bg1,
                        const float* __restrict__ x)
{
    int b = blockIdx.x;
    const float* row = (b < 128) ? (Wa1 + (size_t)b * 2048) : (Wg1 + (size_t)(b - 128) * 2048);
    float s = 0.f;
    for (int jj = threadIdx.x; jj < 1024; jj += 256) s += row[jj] * x[jj];
    __shared__ float sh[256];
    sh[threadIdx.x] = s; __syncthreads();
    for (int o = 128; o > 0; o >>= 1) {
        if (threadIdx.x < o) sh[threadIdx.x] += sh[threadIdx.x + o];
        __syncthreads();
    }
    if (threadIdx.x == 0)
        g_bias1[b] = sh[0] + ((b < 128) ? ba1[b] : bg1[b - 128]);
}

// vih = W_ih[:, :1024] @ bconst + b_ih ; wt = W_ih[:, 1024]
__global__ void k_vih(const float* __restrict__ W_ih, const float* __restrict__ b_ih)
{
    int k = blockIdx.x;
    const float* row = W_ih + (size_t)k * GIN;
    float s = 0.f;
    for (int jj = threadIdx.x; jj < 1024; jj += 256) s += row[jj] * g_bconst[jj];
    __shared__ float sh[256];
    sh[threadIdx.x] = s; __syncthreads();
    for (int o = 128; o > 0; o >>= 1) {
        if (threadIdx.x < o) sh[threadIdx.x] += sh[threadIdx.x + o];
        __syncthreads();
    }
    if (threadIdx.x == 0) {
        g_vih[k] = sh[0] + b_ih[k];
        g_wt[k] = row[1024];
    }
}

__global__ void k_vote(const float* __restrict__ infl, const float* __restrict__ op,
                       const float* __restrict__ noise)
{
    int row = blockIdx.x;
    int tid = threadIdx.x;
    int lane = tid & 31, wid = tid >> 5;
    float acc[NT];
#pragma unroll
    for (int t = 0; t < NT; t++) acc[t] = 0.f;
    const float* ir = infl + (size_t)row * N_CELLS;
    for (int c = tid; c < N_CELLS; c += 256) {
        float w = ir[c];
        if (w != 0.f) {
            const float4* o4 = (const float4*)(op + (size_t)c * NT);
            float4 a = o4[0], b = o4[1];
            acc[0] += w * a.x; acc[1] += w * a.y; acc[2] += w * a.z; acc[3] += w * a.w;
            acc[4] += w * b.x; acc[5] += w * b.y; acc[6] += w * b.z; acc[7] += w * b.w;
        }
    }
    __shared__ float sh[8][NT];
#pragma unroll
    for (int t = 0; t < NT; t++) {
        float v = acc[t];
        v += __shfl_xor_sync(0xffffffffu, v, 16);
        v += __shfl_xor_sync(0xffffffffu, v, 8);
        v += __shfl_xor_sync(0xffffffffu, v, 4);
        v += __shfl_xor_sync(0xffffffffu, v, 2);
        v += __shfl_xor_sync(0xffffffffu, v, 1);
        if (lane == 0) sh[wid][t] = v;
    }
    __syncthreads();
    if (tid == 0) {
        float v[NT]; float sum = 0.f;
#pragma unroll
        for (int t = 0; t < NT; t++) {
            float s = 0.f;
#pragma unroll
            for (int w = 0; w < 8; w++) s += sh[w][t];
            float u = 0.7f * op[row * NT + t] + 0.3f * s + 0.01f * noise[row * NT + t];
            u = fmaxf(u, 0.01f);
            v[t] = u; sum += u;
        }
        float inv = 1.f / sum;
        int am = 0; float mx = v[0] * inv;
#pragma unroll
        for (int t = 1; t < NT; t++) {
            float u = v[t] * inv;
            if (u > mx) { mx = u; am = t; }
        }
        g_votes[row] = am;
        g_energy[row] = mx;
        atomicAdd(&g_counts[am], 1.f);
    }
}

__global__ void k_gru(const float* __restrict__ hiddens)
{
    int i = blockIdx.x;
    float scale = 0.9f + 0.2f * g_energy[i];
    float t = g_tension[i] * (1.f / 1024.f);
    const float* gi = g_gi + (size_t)i * G3;
    const float* gh = g_gh + (size_t)i * G3;
    for (int jj = threadIdx.x; jj < HID; jj += 256) {
        float r = 1.f / (1.f + expf(-(gi[jj] + t * g_wt[jj] + gh[jj])));
        float z = 1.f / (1.f + expf(-(gi[jj + 1024] + t * g_wt[jj + 1024] + gh[jj + 1024])));
        float n = tanhf(gi[jj + 2048] + t * g_wt[jj + 2048] + r * gh[jj + 2048]);
        float h = hiddens[(size_t)i * 1024 + jj];
        float nh = (1.f - z) * n + z * h;
        nh = fminf(fmaxf(nh * scale, -10.f), 10.f);
        g_nh[(size_t)i * HID + jj] = nh;
    }
}

__global__ void k_segsum()
{
    int c = blockIdx.x * 256 + threadIdx.x;
    int r0 = blockIdx.y * 128;
    float acc[NT];
#pragma unroll
    for (int q = 0; q < NT; q++) acc[q] = 0.f;
    for (int r = r0; r < r0 + 128; r++) {
        float v = g_nh[(size_t)r * HID + c];
        int t = g_votes[r];
#pragma unroll
        for (int q = 0; q < NT; q++) acc[q] += (t == q) ? v : 0.f;
    }
#pragma unroll
    for (int q = 0; q < NT; q++) atomicAdd(&g_sums[q * HID + c], acc[q]);
}

__global__ void k_blend()
{
    int c = blockIdx.x * 256 + threadIdx.x;
    int r0 = blockIdx.y * 64;
    int f = r0 >> 9;
    float facc = 0.f;
    for (int r = r0; r < r0 + 64; r++) {
        int t = g_votes[r];
        float cnt = g_counts[t];
        float v = g_nh[(size_t)r * HID + c];
        if (cnt >= 2.f)
            v = 0.85f * v + 0.15f * (g_sums[t * HID + c] / fmaxf(cnt, 1.f));
        g_nh[(size_t)r * HID + c] = v;
        facc += v;
    }
    atomicAdd(&g_fsums[f * HID + c], facc);
}

__global__ void k_glob()
{
    int jj = blockIdx.x * 256 + threadIdx.x;
    float s = 0.f;
#pragma unroll
    for (int f = 0; f < NF; f++) s += g_fsums[f * HID + jj];
    g_glob[jj] = s * (1.f / 4096.f);
}

__global__ void k_final(float* __restrict__ out_nh, const int* __restrict__ step)
{
    int i = blockIdx.x;
    int f = i >> 9;
    bool dcz = (*step > 5) && ((i & 511) < 128);
    for (int jj = threadIdx.x; jj < HID; jj += 256) {
        float fm = g_fsums[f * HID + jj] * (1.f / 512.f);
        float v = 0.85f * g_nh[(size_t)i * HID + jj] + 0.15f * fm;
        if (dcz) v = 0.85f * v + 0.15f * g_glob[jj];
        out_nh[(size_t)i * HID + jj] = v;
    }
}

__global__ void k_softmax(float* __restrict__ out_avg)
{
    __shared__ float sh[1024];
    int tid = threadIdx.x;
    float t4[4];
    float mx = -1e30f, av = 0.f;
#pragma unroll
    for (int q = 0; q < 4; q++) {
        t4[q] = g_tension[tid + q * 1024] * (1.f / 1024.f);
        mx = fmaxf(mx, t4[q]);
        av += t4[q];
    }
    sh[tid] = mx; __syncthreads();
    for (int o = 512; o > 0; o >>= 1) {
        if (tid < o) sh[tid] = fmaxf(sh[tid], sh[tid + o]);
        __syncthreads();
    }
    float M = sh[0]; __syncthreads();
    float sm = 0.f;
#pragma unroll
    for (int q = 0; q < 4; q++) {
        float e = expf(t4[q] - M);
        g_w[tid + q * 1024] = e;
        sm += e;
    }
    sh[tid] = sm; __syncthreads();
    for (int o = 512; o > 0; o >>= 1) {
        if (tid < o) sh[tid] += sh[tid + o];
        __syncthreads();
    }
    float inv = 1.f / sh[0]; __syncthreads();
#pragma unroll
    for (int q = 0; q < 4; q++) g_w[tid + q * 1024] *= inv;
    sh[tid] = av; __syncthreads();
    for (int o = 512; o > 0; o >>= 1) {
        if (tid < o) sh[tid] += sh[tid + o];
        __syncthreads();
    }
    if (tid == 0) out_avg[0] = sh[0] * (1.f / 4096.f);
}

__global__ void k_combined()
{
    int c = blockIdx.x * 256 + threadIdx.x;
    int r0 = blockIdx.y * 128;
    float acc = 0.f;
    for (int r = r0; r < r0 + 128; r++)
        acc += g_w[r] * g_out[(size_t)r * 1024 + c];
    atomicAdd(&g_combined[c], acc);
}

__global__ void k_pred(const float* __restrict__ Wo, const float* __restrict__ bo,
                       float* __restrict__ out_pred)
{
    int i = blockIdx.x;
    const float* row = Wo + (size_t)i * 1024;
    float s = 0.f;
    for (int jj = threadIdx.x; jj < 1024; jj += 256) s += g_combined[jj] * row[jj];
    __shared__ float sh[256];
    sh[threadIdx.x] = s; __syncthreads();
    for (int o = 128; o > 0; o >>= 1) {
        if (threadIdx.x < o) sh[threadIdx.x] += sh[threadIdx.x + o];
        __syncthreads();
    }
    if (threadIdx.x == 0) out_pred[i] = sh[0] + bo[i];
}

// ---------------- launch ----------------
template <typename T>
static T* symp(const void* s)
{
    void* p = nullptr;
    cudaGetSymbolAddress(&p, s);
    return (T*)p;
}

#define SMEM_MI1 (2 * (2 * 64 * 128 + 2 * 128 * 128))    // 96 KB
#define SMEM_MI4 (2 * (2 * 256 * 128 + 2 * 128 * 128))   // 192 KB

extern "C" void kernel_launch(void* const* d_in, const int* in_sizes, int n_in,
                              void* d_out, int out_size)
{
    const float* x        = (const float*)d_in[0];
    const float* hiddens  = (const float*)d_in[1];
    const float* opinions = (const float*)d_in[2];
    const float* influence= (const float*)d_in[3];
    const float* noise    = (const float*)d_in[4];
    const float* Wa1 = (const float*)d_in[5];
    const float* ba1 = (const float*)d_in[6];
    const float* Wa2 = (const float*)d_in[7];
    const float* ba2 = (const float*)d_in[8];
    const float* Wg1 = (const float*)d_in[9];
    const float* bg1 = (const float*)d_in[10];
    const float* Wg2 = (const float*)d_in[11];
    const float* bg2 = (const float*)d_in[12];
    const float* W_ih = (const float*)d_in[13];
    const float* b_ih = (const float*)d_in[14];
    const float* W_hh = (const float*)d_in[15];
    const float* b_hh = (const float*)d_in[16];
    const float* Wo  = (const float*)d_in[17];
    const float* bo  = (const float*)d_in[18];
    const int*   step = (const int*)d_in[19];

    float* out = (float*)d_out;
    float* out_pred = out;
    float* out_avg  = out + 1024;
    float* out_nh   = out + 1025;

    bf16* pHidH = symp<bf16>(g_hid_h);  bf16* pHidL = symp<bf16>(g_hid_l);
    bf16* pWihH = symp<bf16>(g_wih_h);  bf16* pWihL = symp<bf16>(g_wih_l);
    bf16* pWhhH = symp<bf16>(g_whh_h);  bf16* pWhhL = symp<bf16>(g_whh_l);
    bf16* pB1H  = symp<bf16>(g_b1_h);   bf16* pB1L  = symp<bf16>(g_b1_l);
    bf16* pWc2H = symp<bf16>(g_wc2_h);  bf16* pWc2L = symp<bf16>(g_wc2_l);
    bf16* pW2TH = symp<bf16>(g_w2t_h);  bf16* pW2TL = symp<bf16>(g_w2t_l);
    bf16* pMcH  = symp<bf16>(g_mcat_h); bf16* pMcL  = symp<bf16>(g_mcat_l);
    bf16* pAgH  = symp<bf16>(g_a1g1_h); bf16* pAgL  = symp<bf16>(g_a1g1_l);
    float* pOut = symp<float>(g_out);
    float* pGi  = symp<float>(g_gi);
    float* pGh  = symp<float>(g_gh);
    float* pBias1 = symp<float>(g_bias1);
    float* pBconst= symp<float>(g_bconst);
    float* pVih = symp<float>(g_vih);

    static bool init_done = false;
    static bool use_streams = false;
    static cudaStream_t s1 = nullptr;
    static cudaEvent_t evA = nullptr, evV = nullptr;
    if (!init_done) {
        init_done = true;
        cudaFuncSetAttribute(gemm_bf<1, false, true, false>,
                             cudaFuncAttributeMaxDynamicSharedMemorySize, SMEM_MI1);
        cudaFuncSetAttribute(gemm_bf<1, true, true, false>,
                             cudaFuncAttributeMaxDynamicSharedMemorySize, SMEM_MI1);
        cudaFuncSetAttribute(gemm_bf<4, false, false, false>,
                             cudaFuncAttributeMaxDynamicSharedMemorySize, SMEM_MI4);
        cudaFuncSetAttribute(gemm_bf<4, false, false, true>,
                             cudaFuncAttributeMaxDynamicSharedMemorySize, SMEM_MI4);
        use_streams =
            (cudaStreamCreateWithFlags(&s1, cudaStreamNonBlocking) == cudaSuccess) &&
            (cudaEventCreateWithFlags(&evA, cudaEventDisableTiming) == cudaSuccess) &&
            (cudaEventCreateWithFlags(&evV, cudaEventDisableTiming) == cudaSuccess);
    }

    k_zero<<<32, 256>>>();

    // fork: vote round on side stream (independent of GEMM chain until k_gru)
    if (use_streams) {
        cudaEventRecord(evA, 0);
        cudaStreamWaitEvent(s1, evA, 0);
        k_vote<<<N_CELLS, 256, 0, s1>>>(influence, opinions, noise);
        cudaEventRecord(evV, s1);
    } else {
        k_vote<<<N_CELLS, 256>>>(influence, opinions, noise);
    }

    // prep chain
    k_prep_all<<<42501, 256>>>(hiddens, W_ih, W_hh, Wa1, Wg1, Wa2, Wg2, ba2, bg2);
    k_bias1<<<256, 256>>>(Wa1, ba1, Wg1, bg1, x);
    k_vih<<<G3, 256>>>(W_ih, b_ih);

    // Mcat[3072,256] = Wih @ W2T^T -> bf16 hi/lo      (MI=1: grid 2 x 48)
    gemm_bf<1, false, true, false><<<dim3(2, 48), 256, SMEM_MI1>>>(
        pWihH, pWihL, 1024, pW2TH, pW2TL, 1024,
        nullptr, pMcH, pMcL, 256, 1024, nullptr);

    // A1G1[4096,256] = relu(hid @ Bcat1^T + bias1) -> bf16 hi/lo   (MI=1: 2 x 64)
    gemm_bf<1, true, true, false><<<dim3(2, 64), 256, SMEM_MI1>>>(
        pHidH, pHidL, 1024, pB1H, pB1L, 1024,
        nullptr, pAgH, pAgL, 256, 1024, pBias1);

    // out[4096,1024] = A1G1 @ Wcat2^T + bconst -> fp32, fused tension sumsq (MI=4: 8 x 16)
    gemm_bf<4, false, false, true><<<dim3(8, 16), 256, SMEM_MI4>>>(
        pAgH, pAgL, 256, pWc2H, pWc2L, 256,
        pOut, nullptr, nullptr, 1024, 256, pBconst);

    // gi[4096,3072] = A1G1 @ Mcat^T + vih (tension term moved to k_gru)  (MI=4: 24 x 16)
    gemm_bf<4, false, false, false><<<dim3(24, 16), 256, SMEM_MI4>>>(
        pAgH, pAgL, 256, pMcH, pMcL, 256,
        pGi, nullptr, nullptr, G3, 256, pVih);

    // gh[4096,3072] = hid @ W_hh^T + b_hh   (MI=4: 24 x 16)
    gemm_bf<4, false, false, false><<<dim3(24, 16), 256, SMEM_MI4>>>(
        pHidH, pHidL, 1024, pWhhH, pWhhL, 1024,
        pGh, nullptr, nullptr, G3, 1024, b_hh);

    // join vote stream before consumers of votes/energy/counts
    if (use_streams) cudaStreamWaitEvent(0, evV, 0);

    k_gru<<<N_CELLS, 256>>>(hiddens);
    k_segsum<<<dim3(4, 32), 256>>>();
    k_blend<<<dim3(4, 64), 256>>>();
    k_glob<<<4, 256>>>();
    k_final<<<N_CELLS, 256>>>(out_nh, step);

    k_softmax<<<1, 1024>>>(out_avg);
    k_combined<<<dim3(4, 32), 256>>>();
    k_pred<<<1024, 256>>>(Wo, bo, out_pred);
}

// round 6
// speedup vs baseline: 3.3427x; 1.1569x over previous
#include <cuda_runtime.h>
#include <cuda_bf16.h>
#include <math.h>
#include <stdint.h>

#define N_CELLS 4096
#define IN_DIM 1024
#define HID 1024
#define OUT_DIM 1024
#define NT 8
#define NF 8
#define GIN 1025
#define G3 3072

typedef __nv_bfloat16 bf16;
typedef __nv_bfloat162 bf162;

// ---------------- scratch (device globals) ----------------
__device__ bf16 g_hid_h[N_CELLS * HID],   g_hid_l[N_CELLS * HID];
__device__ bf16 g_wih_h[G3 * 1024],       g_wih_l[G3 * 1024];
__device__ bf16 g_whh_h[G3 * 1024],       g_whh_l[G3 * 1024];
__device__ bf16 g_b1_h[256 * 1024],       g_b1_l[256 * 1024];
__device__ bf16 g_wc2_h[1024 * 256],      g_wc2_l[1024 * 256];
__device__ bf16 g_w2t_h[256 * 1024],      g_w2t_l[256 * 1024];
__device__ bf16 g_mcat_h[G3 * 256],       g_mcat_l[G3 * 256];
__device__ bf16 g_a1g1_h[N_CELLS * 256],  g_a1g1_l[N_CELLS * 256];
__device__ float g_gi[N_CELLS * G3];
__device__ float g_gh[N_CELLS * G3];
__device__ float g_nh[N_CELLS * HID];
__device__ float g_tension[N_CELLS];
__device__ float g_energy[N_CELLS];
__device__ int   g_votes[N_CELLS];
__device__ float g_bias1[256];
__device__ float g_bconst[1024];
__device__ float g_vih[G3];
__device__ float g_wt[G3];
__device__ float g_counts[NT];
__device__ float g_sums[NT * HID];
__device__ float g_fsums[NF * HID];
__device__ float g_w[N_CELLS];
__device__ float g_wa[256];
__device__ float g_combined[OUT_DIM];

// ---------------- asm helpers ----------------
__device__ __forceinline__ uint32_t smem_u32(const void* p) {
    uint32_t a;
    asm("{ .reg .u64 t; cvta.to.shared.u64 t, %1; cvt.u32.u64 %0, t; }" : "=r"(a) : "l"(p));
    return a;
}
__device__ __forceinline__ void cpa16(uint32_t s, const void* g) {
    asm volatile("cp.async.cg.shared.global [%0], [%1], 16;" :: "r"(s), "l"(g));
}
__device__ __forceinline__ void cp_commit() {
    asm volatile("cp.async.commit_group;" ::: "memory");
}
template <int N>
__device__ __forceinline__ void cp_wait() {
    asm volatile("cp.async.wait_group %0;" :: "n"(N) : "memory");
}
__device__ __forceinline__ void ldsm4(uint32_t& r0, uint32_t& r1, uint32_t& r2, uint32_t& r3,
                                      uint32_t a) {
    asm volatile("ldmatrix.sync.aligned.m8n8.x4.shared.b16 {%0,%1,%2,%3}, [%4];"
                 : "=r"(r0), "=r"(r1), "=r"(r2), "=r"(r3) : "r"(a));
}
__device__ __forceinline__ void mma16816(float c[4], const uint32_t a[4], const uint32_t b[2])
{
    asm("mma.sync.aligned.m16n8k16.row.col.f32.bf16.bf16.f32 "
        "{%0,%1,%2,%3}, {%4,%5,%6,%7}, {%8,%9}, {%0,%1,%2,%3};"
        : "+f"(c[0]), "+f"(c[1]), "+f"(c[2]), "+f"(c[3])
        : "r"(a[0]), "r"(a[1]), "r"(a[2]), "r"(a[3]), "r"(b[0]), "r"(b[1]));
}
__device__ __forceinline__ void split_bf16(float x, bf16& hi, bf16& lo)
{
    hi = __float2bfloat16_rn(x);
    lo = __float2bfloat16_rn(x - __bfloat162float(hi));
}
__device__ __forceinline__ float wred(float v)
{
    v += __shfl_xor_sync(0xffffffffu, v, 16);
    v += __shfl_xor_sync(0xffffffffu, v, 8);
    v += __shfl_xor_sync(0xffffffffu, v, 4);
    v += __shfl_xor_sync(0xffffffffu, v, 2);
    v += __shfl_xor_sync(0xffffffffu, v, 1);
    return v;
}

// =============== bf16 split-pipelined GEMM ===============
template <int MI, bool RELU, bool WRITEBF, bool SUMSQ, bool NOC>
__global__ void __launch_bounds__(256) gemm_bf(
    const bf16* __restrict__ Ahi, const bf16* __restrict__ Alo, int lda,
    const bf16* __restrict__ Bhi, const bf16* __restrict__ Blo, int ldb,
    float* __restrict__ C, bf16* __restrict__ Chi, bf16* __restrict__ Clo, int ldc,
    int K, const float* __restrict__ bias)
{
    constexpr int TM = 64 * MI;
    constexpr int ABYTES = TM * 128;
    constexpr int BBYTES = 128 * 128;
    constexpr int STAGE = 2 * ABYTES + 2 * BBYTES;

    extern __shared__ __align__(1024) char smem[];
    const uint32_t sb = smem_u32(smem);
    const int tid = threadIdx.x;
    const int wid = tid >> 5, lane = tid & 31;
    const int wm = wid & 3, wn = wid >> 2;
    const int g = lane >> 2, tg = lane & 3;
    const int m0 = blockIdx.y * TM, n0 = blockIdx.x * 128;
    const int nc = K >> 6;

    float acc[MI][8][4];
#pragma unroll
    for (int mi = 0; mi < MI; mi++)
#pragma unroll
        for (int ni = 0; ni < 8; ni++)
#pragma unroll
            for (int q = 0; q < 4; q++) acc[mi][ni][q] = 0.f;

    auto load_stage = [&](int c, int b) {
        const uint32_t s0 = sb + b * STAGE;
        const int k0 = c << 6;
#pragma unroll
        for (int it = 0; it < TM * 8 / 256; it++) {
            int idx = tid + it * 256;
            int row = idx >> 3, ch = idx & 7;
            uint32_t so = (uint32_t)(row << 7) + (uint32_t)((ch ^ (row & 7)) << 4);
            size_t go = (size_t)(m0 + row) * lda + k0 + ch * 8;
            cpa16(s0 + so, Ahi + go);
            cpa16(s0 + ABYTES + so, Alo + go);
        }
#pragma unroll
        for (int it = 0; it < 4; it++) {
            int idx = tid + it * 256;
            int row = idx >> 3, ch = idx & 7;
            uint32_t so = (uint32_t)(row << 7) + (uint32_t)((ch ^ (row & 7)) << 4);
            size_t go = (size_t)(n0 + row) * ldb + k0 + ch * 8;
            cpa16(s0 + 2 * ABYTES + so, Bhi + go);
            cpa16(s0 + 2 * ABYTES + BBYTES + so, Blo + go);
        }
        cp_commit();
    };

    const int j = lane >> 3;
    const int arow_b = wm * (16 * MI) + (j & 1) * 8 + (lane & 7);
    const int brow_b = wn * 64 + (j >> 1) * 8 + (lane & 7);

    load_stage(0, 0);

    for (int c = 0; c < nc; c++) {
        if (c + 1 < nc) { load_stage(c + 1, (c + 1) & 1); cp_wait<1>(); }
        else            { cp_wait<0>(); }
        __syncthreads();

        const uint32_t sA = sb + (c & 1) * STAGE;
        const uint32_t sB = sA + 2 * ABYTES;

#pragma unroll
        for (int ks = 0; ks < 4; ks++) {
            uint32_t bh[8][2], bl[8][2];
            const int achunk = ks * 2 + (j >> 1);
            const int bchunk = ks * 2 + (j & 1);
#pragma unroll
            for (int nb = 0; nb < 4; nb++) {
                int r = brow_b + nb * 16;
                uint32_t off = (uint32_t)(r << 7) + (uint32_t)((bchunk ^ (r & 7)) << 4);
                uint32_t t0, t1, t2, t3;
                ldsm4(t0, t1, t2, t3, sB + off);
                bh[2 * nb][0] = t0; bh[2 * nb][1] = t1;
                bh[2 * nb + 1][0] = t2; bh[2 * nb + 1][1] = t3;
                ldsm4(t0, t1, t2, t3, sB + BBYTES + off);
                bl[2 * nb][0] = t0; bl[2 * nb][1] = t1;
                bl[2 * nb + 1][0] = t2; bl[2 * nb + 1][1] = t3;
            }
#pragma unroll
            for (int mi = 0; mi < MI; mi++) {
                uint32_t ah[4], al[4];
                int r = arow_b + mi * 16;
                uint32_t off = (uint32_t)(r << 7) + (uint32_t)((achunk ^ (r & 7)) << 4);
                ldsm4(ah[0], ah[1], ah[2], ah[3], sA + off);
                ldsm4(al[0], al[1], al[2], al[3], sA + ABYTES + off);
#pragma unroll
                for (int ni = 0; ni < 8; ni++) {
                    mma16816(acc[mi][ni], ah, bh[ni]);
                    mma16816(acc[mi][ni], ah, bl[ni]);
                    mma16816(acc[mi][ni], al, bh[ni]);
                }
            }
        }
        __syncthreads();
    }

    // ---- epilogue ----
#pragma unroll
    for (int mi = 0; mi < MI; mi++) {
        int row0 = m0 + wm * (16 * MI) + mi * 16 + g;
        float p0 = 0.f, p1 = 0.f;
#pragma unroll
        for (int ni = 0; ni < 8; ni++) {
            int col = n0 + wn * 64 + ni * 8 + tg * 2;
            float b0 = bias ? bias[col] : 0.f;
            float b1 = bias ? bias[col + 1] : 0.f;
            float v0 = acc[mi][ni][0] + b0;
            float v1 = acc[mi][ni][1] + b1;
            float v2 = acc[mi][ni][2] + b0;
            float v3 = acc[mi][ni][3] + b1;
            if (RELU) {
                v0 = fmaxf(v0, 0.f); v1 = fmaxf(v1, 0.f);
                v2 = fmaxf(v2, 0.f); v3 = fmaxf(v3, 0.f);
            }
            if (SUMSQ) { p0 += v0 * v0 + v1 * v1; p1 += v2 * v2 + v3 * v3; }
            if (WRITEBF) {
                bf16 h0, l0, h1, l1;
                bf162 hp, lp;
                split_bf16(v0, h0, l0); split_bf16(v1, h1, l1);
                hp.x = h0; hp.y = h1; lp.x = l0; lp.y = l1;
                *(bf162*)(Chi + (size_t)row0 * ldc + col) = hp;
                *(bf162*)(Clo + (size_t)row0 * ldc + col) = lp;
                split_bf16(v2, h0, l0); split_bf16(v3, h1, l1);
                hp.x = h0; hp.y = h1; lp.x = l0; lp.y = l1;
                *(bf162*)(Chi + (size_t)(row0 + 8) * ldc + col) = hp;
                *(bf162*)(Clo + (size_t)(row0 + 8) * ldc + col) = lp;
            } else if (!NOC) {
                float2 q0; q0.x = v0; q0.y = v1;
                float2 q1; q1.x = v2; q1.y = v3;
                *(float2*)(C + (size_t)row0 * ldc + col) = q0;
                *(float2*)(C + (size_t)(row0 + 8) * ldc + col) = q1;
            }
        }
        if (SUMSQ) {
            p0 += __shfl_xor_sync(0xffffffffu, p0, 1);
            p0 += __shfl_xor_sync(0xffffffffu, p0, 2);
            p1 += __shfl_xor_sync(0xffffffffu, p1, 1);
            p1 += __shfl_xor_sync(0xffffffffu, p1, 2);
            if (tg == 0) {
                atomicAdd(&g_tension[row0], p0);
                atomicAdd(&g_tension[row0 + 8], p1);
            }
        }
    }
}

// ---------------- prep ----------------
__global__ void k_prep_all(const float* __restrict__ hiddens, const float* __restrict__ W_ih,
                           const float* __restrict__ W_hh,
                           const float* __restrict__ Wa1, const float* __restrict__ Wg1,
                           const float* __restrict__ Wa2, const float* __restrict__ Wg2,
                           const float* __restrict__ ba2, const float* __restrict__ bg2)
{
    long i = (long)blockIdx.x * 256 + threadIdx.x;
    const long N0 = 4194304L;
    const long N1 = N0 + 3145728L;
    const long N2 = N1 + 3145728L;
    const long N3 = N2 + 262144L;
    const long N4 = N3 + 131072L;
    const long N5 = N4 + 1024L;
    bf16 h, l;
    if (i < N0) {
        float v = hiddens[i];
        split_bf16(v, h, l); g_hid_h[i] = h; g_hid_l[i] = l;
    } else if (i < N1) {
        long k = i - N0; int r = (int)(k >> 10), c = (int)(k & 1023);
        float v = W_ih[(size_t)r * GIN + c];
        split_bf16(v, h, l); g_wih_h[k] = h; g_wih_l[k] = l;
    } else if (i < N2) {
        long k = i - N1;
        float v = W_hh[k];
        split_bf16(v, h, l); g_whh_h[k] = h; g_whh_l[k] = l;
    } else if (i < N3) {
        long k = i - N2; int r = (int)(k >> 10), c = (int)(k & 1023);
        float v = (r < 128) ? Wa1[r * 2048 + 1024 + c] : Wg1[(r - 128) * 2048 + 1024 + c];
        split_bf16(v, h, l); g_b1_h[k] = h; g_b1_l[k] = l;
    } else if (i < N4) {
        long k = i - N3; int jr = (int)(k >> 7), m = (int)(k & 127);
        float va = Wa2[k], vg = -Wg2[k];
        split_bf16(va, h, l);
        g_wc2_h[jr * 256 + m] = h;          g_wc2_l[jr * 256 + m] = l;
        g_w2t_h[m * 1024 + jr] = h;         g_w2t_l[m * 1024 + jr] = l;
        split_bf16(vg, h, l);
        g_wc2_h[jr * 256 + 128 + m] = h;    g_wc2_l[jr * 256 + 128 + m] = l;
        g_w2t_h[(128 + m) * 1024 + jr] = h; g_w2t_l[(128 + m) * 1024 + jr] = l;
    } else if (i < N5) {
        long k = i - N4;
        g_bconst[k] = ba2[k] - bg2[k];
    }
}

__global__ void k_zero()
{
    int i = blockIdx.x * 256 + threadIdx.x;
    if (i < NT) g_counts[i] = 0.f;
    if (i < NT * HID) { g_sums[i] = 0.f; g_fsums[i] = 0.f; }
    if (i < 256) g_wa[i] = 0.f;
    if (i < N_CELLS) g_tension[i] = 0.f;
}

// warp-per-row: bias1 (256 rows)
__global__ void k_bias1(const float* __restrict__ Wa1, const float* __restrict__ ba1,
                        const float* __restrict__ Wg1, const float* __restrict__ bg1,
                        const float* __restrict__ x)
{
    int b = blockIdx.x * 8 + (threadIdx.x >> 5);
    int lane = threadIdx.x & 31;
    const float* row = (b < 128) ? (Wa1 + (size_t)b * 2048) : (Wg1 + (size_t)(b - 128) * 2048);
    float s = 0.f;
    for (int jj = lane; jj < 1024; jj += 32) s += row[jj] * x[jj];
    s = wred(s);
    if (lane == 0)
        g_bias1[b] = s + ((b < 128) ? ba1[b] : bg1[b - 128]);
}

// warp-per-row: vih (3072 rows)
__global__ void k_vih(const float* __restrict__ W_ih, const float* __restrict__ b_ih)
{
    int k = blockIdx.x * 8 + (threadIdx.x >> 5);
    int lane = threadIdx.x & 31;
    const float* row = W_ih + (size_t)k * GIN;
    float s = 0.f;
    for (int jj = lane; jj < 1024; jj += 32) s += row[jj] * g_bconst[jj];
    s = wred(s);
    if (lane == 0) { g_vih[k] = s + b_ih[k]; g_wt[k] = row[1024]; }
}

__global__ void k_vote(const float* __restrict__ infl, const float* __restrict__ op,
                       const float* __restrict__ noise)
{
    int row = blockIdx.x;
    int tid = threadIdx.x;
    int lane = tid & 31, wid = tid >> 5;
    float acc[NT];
#pragma unroll
    for (int t = 0; t < NT; t++) acc[t] = 0.f;
    const float* ir = infl + (size_t)row * N_CELLS;
    for (int c = tid; c < N_CELLS; c += 256) {
        float w = ir[c];
        if (w != 0.f) {
            const float4* o4 = (const float4*)(op + (size_t)c * NT);
            float4 a = o4[0], b = o4[1];
            acc[0] += w * a.x; acc[1] += w * a.y; acc[2] += w * a.z; acc[3] += w * a.w;
            acc[4] += w * b.x; acc[5] += w * b.y; acc[6] += w * b.z; acc[7] += w * b.w;
        }
    }
    __shared__ float sh[8][NT];
#pragma unroll
    for (int t = 0; t < NT; t++) {
        float v = wred(acc[t]);
        if (lane == 0) sh[wid][t] = v;
    }
    __syncthreads();
    if (tid == 0) {
        float v[NT]; float sum = 0.f;
#pragma unroll
        for (int t = 0; t < NT; t++) {
            float s = 0.f;
#pragma unroll
            for (int w = 0; w < 8; w++) s += sh[w][t];
            float u = 0.7f * op[row * NT + t] + 0.3f * s + 0.01f * noise[row * NT + t];
            u = fmaxf(u, 0.01f);
            v[t] = u; sum += u;
        }
        float inv = 1.f / sum;
        int am = 0; float mx = v[0] * inv;
#pragma unroll
        for (int t = 1; t < NT; t++) {
            float u = v[t] * inv;
            if (u > mx) { mx = u; am = t; }
        }
        g_votes[row] = am;
        g_energy[row] = mx;
        atomicAdd(&g_counts[am], 1.f);
    }
}

__global__ void k_gru(const float* __restrict__ hiddens)
{
    int i = blockIdx.x;
    float scale = 0.9f + 0.2f * g_energy[i];
    float t = g_tension[i] * (1.f / 1024.f);
    const float* gi = g_gi + (size_t)i * G3;
    const float* gh = g_gh + (size_t)i * G3;
    for (int jj = threadIdx.x; jj < HID; jj += 256) {
        float r = 1.f / (1.f + expf(-(gi[jj] + t * g_wt[jj] + gh[jj])));
        float z = 1.f / (1.f + expf(-(gi[jj + 1024] + t * g_wt[jj + 1024] + gh[jj + 1024])));
        float n = tanhf(gi[jj + 2048] + t * g_wt[jj + 2048] + r * gh[jj + 2048]);
        float h = hiddens[(size_t)i * 1024 + jj];
        float nh = (1.f - z) * n + z * h;
        nh = fminf(fmaxf(nh * scale, -10.f), 10.f);
        g_nh[(size_t)i * HID + jj] = nh;
    }
}

__global__ void k_segsum()
{
    int c = blockIdx.x * 256 + threadIdx.x;
    int r0 = blockIdx.y * 128;
    float acc[NT];
#pragma unroll
    for (int q = 0; q < NT; q++) acc[q] = 0.f;
    for (int r = r0; r < r0 + 128; r++) {
        float v = g_nh[(size_t)r * HID + c];
        int t = g_votes[r];
#pragma unroll
        for (int q = 0; q < NT; q++) acc[q] += (t == q) ? v : 0.f;
    }
#pragma unroll
    for (int q = 0; q < NT; q++) atomicAdd(&g_sums[q * HID + c], acc[q]);
}

__global__ void k_blend()
{
    int c = blockIdx.x * 256 + threadIdx.x;
    int r0 = blockIdx.y * 64;
    int f = r0 >> 9;
    float facc = 0.f;
    for (int r = r0; r < r0 + 64; r++) {
        int t = g_votes[r];
        float cnt = g_counts[t];
        float v = g_nh[(size_t)r * HID + c];
        if (cnt >= 2.f)
            v = 0.85f * v + 0.15f * (g_sums[t * HID + c] / fmaxf(cnt, 1.f));
        g_nh[(size_t)r * HID + c] = v;
        facc += v;
    }
    atomicAdd(&g_fsums[f * HID + c], facc);
}

// final: per-cell blend with faction mean and (step>5) global mean (glob inline)
__global__ void k_final(float* __restrict__ out_nh, const int* __restrict__ step)
{
    int i = blockIdx.x;
    int f = i >> 9;
    bool dcz = (*step > 5) && ((i & 511) < 128);
    for (int jj = threadIdx.x; jj < HID; jj += 256) {
        float fm = g_fsums[f * HID + jj] * (1.f / 512.f);
        float v = 0.85f * g_nh[(size_t)i * HID + jj] + 0.15f * fm;
        if (dcz) {
            float gsum = 0.f;
#pragma unroll
            for (int q = 0; q < NF; q++) gsum += g_fsums[q * HID + jj];
            v = 0.85f * v + 0.15f * (gsum * (1.f / 4096.f));
        }
        out_nh[(size_t)i * HID + jj] = v;
    }
}

__global__ void k_softmax(float* __restrict__ out_avg)
{
    __shared__ float sh[1024];
    int tid = threadIdx.x;
    float t4[4];
    float mx = -1e30f, av = 0.f;
#pragma unroll
    for (int q = 0; q < 4; q++) {
        t4[q] = g_tension[tid + q * 1024] * (1.f / 1024.f);
        mx = fmaxf(mx, t4[q]);
        av += t4[q];
    }
    sh[tid] = mx; __syncthreads();
    for (int o = 512; o > 0; o >>= 1) {
        if (tid < o) sh[tid] = fmaxf(sh[tid], sh[tid + o]);
        __syncthreads();
    }
    float M = sh[0]; __syncthreads();
    float sm = 0.f;
#pragma unroll
    for (int q = 0; q < 4; q++) {
        float e = expf(t4[q] - M);
        g_w[tid + q * 1024] = e;
        sm += e;
    }
    sh[tid] = sm; __syncthreads();
    for (int o = 512; o > 0; o >>= 1) {
        if (tid < o) sh[tid] += sh[tid + o];
        __syncthreads();
    }
    float inv = 1.f / sh[0]; __syncthreads();
#pragma unroll
    for (int q = 0; q < 4; q++) g_w[tid + q * 1024] *= inv;
    sh[tid] = av; __syncthreads();
    for (int o = 512; o > 0; o >>= 1) {
        if (tid < o) sh[tid] += sh[tid + o];
        __syncthreads();
    }
    if (tid == 0) out_avg[0] = sh[0] * (1.f / 4096.f);
}

// wa[c] = sum_r w[r] * A1G1[r][c]   (A1G1 = hi + lo)
__global__ void k_wA()
{
    int c = threadIdx.x;
    int r0 = blockIdx.x * 128;
    float acc = 0.f;
    for (int r = r0; r < r0 + 128; r++) {
        float w = g_w[r];
        float v = __bfloat162float(g_a1g1_h[(size_t)r * 256 + c])
                + __bfloat162float(g_a1g1_l[(size_t)r * 256 + c]);
        acc += w * v;
    }
    atomicAdd(&g_wa[c], acc);
}

// combined[j] = sum_m wa[m] * Wcat2[j][m] + bconst[j]   (warp per j)
__global__ void k_comb2()
{
    int jr = blockIdx.x * 8 + (threadIdx.x >> 5);
    int lane = threadIdx.x & 31;
    float s = 0.f;
    for (int m = lane; m < 256; m += 32) {
        float wv = __bfloat162float(g_wc2_h[(size_t)jr * 256 + m])
                 + __bfloat162float(g_wc2_l[(size_t)jr * 256 + m]);
        s += g_wa[m] * wv;
    }
    s = wred(s);
    if (lane == 0) g_combined[jr] = s + g_bconst[jr];
}

// pred[i] = Wo[i] . combined + bo[i]   (warp per i)
__global__ void k_pred(const float* __restrict__ Wo, const float* __restrict__ bo,
                       float* __restrict__ out_pred)
{
    int i = blockIdx.x * 8 + (threadIdx.x >> 5);
    int lane = threadIdx.x & 31;
    const float* row = Wo + (size_t)i * 1024;
    float s = 0.f;
    for (int jj = lane; jj < 1024; jj += 32) s += g_combined[jj] * row[jj];
    s = wred(s);
    if (lane == 0) out_pred[i] = s + bo[i];
}

// ---------------- launch ----------------
template <typename T>
static T* symp(const void* s)
{
    void* p = nullptr;
    cudaGetSymbolAddress(&p, s);
    return (T*)p;
}

#define SMEM_MI1 (2 * (2 * 64 * 128 + 2 * 128 * 128))    // 96 KB
#define SMEM_MI4 (2 * (2 * 256 * 128 + 2 * 128 * 128))   // 192 KB

extern "C" void kernel_launch(void* const* d_in, const int* in_sizes, int n_in,
                              void* d_out, int out_size)
{
    const float* x        = (const float*)d_in[0];
    const float* hiddens  = (const float*)d_in[1];
    const float* opinions = (const float*)d_in[2];
    const float* influence= (const float*)d_in[3];
    const float* noise    = (const float*)d_in[4];
    const float* Wa1 = (const float*)d_in[5];
    const float* ba1 = (const float*)d_in[6];
    const float* Wa2 = (const float*)d_in[7];
    const float* ba2 = (const float*)d_in[8];
    const float* Wg1 = (const float*)d_in[9];
    const float* bg1 = (const float*)d_in[10];
    const float* Wg2 = (const float*)d_in[11];
    const float* bg2 = (const float*)d_in[12];
    const float* W_ih = (const float*)d_in[13];
    const float* b_ih = (const float*)d_in[14];
    const float* W_hh = (const float*)d_in[15];
    const float* b_hh = (const float*)d_in[16];
    const float* Wo  = (const float*)d_in[17];
    const float* bo  = (const float*)d_in[18];
    const int*   step = (const int*)d_in[19];

    float* out = (float*)d_out;
    float* out_pred = out;
    float* out_avg  = out + 1024;
    float* out_nh   = out + 1025;

    bf16* pHidH = symp<bf16>(g_hid_h);  bf16* pHidL = symp<bf16>(g_hid_l);
    bf16* pWihH = symp<bf16>(g_wih_h);  bf16* pWihL = symp<bf16>(g_wih_l);
    bf16* pWhhH = symp<bf16>(g_whh_h);  bf16* pWhhL = symp<bf16>(g_whh_l);
    bf16* pB1H  = symp<bf16>(g_b1_h);   bf16* pB1L  = symp<bf16>(g_b1_l);
    bf16* pWc2H = symp<bf16>(g_wc2_h);  bf16* pWc2L = symp<bf16>(g_wc2_l);
    bf16* pW2TH = symp<bf16>(g_w2t_h);  bf16* pW2TL = symp<bf16>(g_w2t_l);
    bf16* pMcH  = symp<bf16>(g_mcat_h); bf16* pMcL  = symp<bf16>(g_mcat_l);
    bf16* pAgH  = symp<bf16>(g_a1g1_h); bf16* pAgL  = symp<bf16>(g_a1g1_l);
    float* pGi  = symp<float>(g_gi);
    float* pGh  = symp<float>(g_gh);
    float* pBias1 = symp<float>(g_bias1);
    float* pVih = symp<float>(g_vih);

    static bool init_done = false;
    static bool use_streams = false;
    static cudaStream_t sM = nullptr, sG = nullptr, sV = nullptr;
    static cudaEvent_t ev0 = nullptr, evPrep = nullptr, evM = nullptr,
                       evG = nullptr, evV = nullptr, evT = nullptr, evP = nullptr;
    if (!init_done) {
        init_done = true;
        cudaFuncSetAttribute(gemm_bf<1, false, true, false, false>,
                             cudaFuncAttributeMaxDynamicSharedMemorySize, SMEM_MI1);
        cudaFuncSetAttribute(gemm_bf<1, true, true, false, false>,
                             cudaFuncAttributeMaxDynamicSharedMemorySize, SMEM_MI1);
        cudaFuncSetAttribute(gemm_bf<4, false, false, false, false>,
                             cudaFuncAttributeMaxDynamicSharedMemorySize, SMEM_MI4);
        cudaFuncSetAttribute(gemm_bf<4, false, false, true, true>,
                             cudaFuncAttributeMaxDynamicSharedMemorySize, SMEM_MI4);
        use_streams =
            (cudaStreamCreateWithFlags(&sM, cudaStreamNonBlocking) == cudaSuccess) &&
            (cudaStreamCreateWithFlags(&sG, cudaStreamNonBlocking) == cudaSuccess) &&
            (cudaStreamCreateWithFlags(&sV, cudaStreamNonBlocking) == cudaSuccess) &&
            (cudaEventCreateWithFlags(&ev0, cudaEventDisableTiming) == cudaSuccess) &&
            (cudaEventCreateWithFlags(&evPrep, cudaEventDisableTiming) == cudaSuccess) &&
            (cudaEventCreateWithFlags(&evM, cudaEventDisableTiming) == cudaSuccess) &&
            (cudaEventCreateWithFlags(&evG, cudaEventDisableTiming) == cudaSuccess) &&
            (cudaEventCreateWithFlags(&evV, cudaEventDisableTiming) == cudaSuccess) &&
            (cudaEventCreateWithFlags(&evT, cudaEventDisableTiming) == cudaSuccess) &&
            (cudaEventCreateWithFlags(&evP, cudaEventDisableTiming) == cudaSuccess);
    }

    cudaStream_t m = use_streams ? sM : (cudaStream_t)0;
    cudaStream_t gg = use_streams ? sG : (cudaStream_t)0;
    cudaStream_t vv = use_streams ? sV : (cudaStream_t)0;

    k_zero<<<32, 256>>>();

    if (use_streams) { cudaEventRecord(ev0, 0); cudaStreamWaitEvent(vv, ev0, 0); }
    k_vote<<<N_CELLS, 256, 0, vv>>>(influence, opinions, noise);
    if (use_streams) cudaEventRecord(evV, vv);

    k_prep_all<<<42501, 256>>>(hiddens, W_ih, W_hh, Wa1, Wg1, Wa2, Wg2, ba2, bg2);
    if (use_streams) {
        cudaEventRecord(evPrep, 0);
        cudaStreamWaitEvent(m, evPrep, 0);
        cudaStreamWaitEvent(gg, evPrep, 0);
    }

    // gh on its own stream (heaviest, independent)
    gemm_bf<4, false, false, false, false><<<dim3(24, 16), 256, SMEM_MI4, gg>>>(
        pHidH, pHidL, 1024, pWhhH, pWhhL, 1024,
        pGh, nullptr, nullptr, G3, 1024, b_hh);
    if (use_streams) cudaEventRecord(evG, gg);

    // Mcat on stream m
    gemm_bf<1, false, true, false, false><<<dim3(2, 48), 256, SMEM_MI1, m>>>(
        pWihH, pWihL, 1024, pW2TH, pW2TL, 1024,
        nullptr, pMcH, pMcL, 256, 1024, nullptr);
    if (use_streams) cudaEventRecord(evM, m);

    // main chain
    k_bias1<<<32, 256>>>(Wa1, ba1, Wg1, bg1, x);
    k_vih<<<G3 / 8, 256>>>(W_ih, b_ih);

    gemm_bf<1, true, true, false, false><<<dim3(2, 64), 256, SMEM_MI1>>>(
        pHidH, pHidL, 1024, pB1H, pB1L, 1024,
        nullptr, pAgH, pAgL, 256, 1024, pBias1);

    // out-GEMM: tension only, no C write
    gemm_bf<4, false, false, true, true><<<dim3(8, 16), 256, SMEM_MI4>>>(
        pAgH, pAgL, 256, pWc2H, pWc2L, 256,
        nullptr, nullptr, nullptr, 1024, 256, symp<float>(g_bconst));
    if (use_streams) { cudaEventRecord(evT, 0); cudaStreamWaitEvent(m, evT, 0); }

    // softmax -> pred chain on stream m (hidden behind gi/gh)
    k_softmax<<<1, 1024, 0, m>>>(out_avg);
    k_wA<<<32, 256, 0, m>>>();
    k_comb2<<<128, 256, 0, m>>>();
    k_pred<<<128, 256, 0, m>>>(Wo, bo, out_pred);
    if (use_streams) cudaEventRecord(evP, m);

    // gi after Mcat
    if (use_streams) cudaStreamWaitEvent(0, evM, 0);
    gemm_bf<4, false, false, false, false><<<dim3(24, 16), 256, SMEM_MI4>>>(
        pAgH, pAgL, 256, pMcH, pMcL, 256,
        pGi, nullptr, nullptr, G3, 256, pVih);

    // join gh + vote, then GRU chain
    if (use_streams) { cudaStreamWaitEvent(0, evG, 0); cudaStreamWaitEvent(0, evV, 0); }
    k_gru<<<N_CELLS, 256>>>(hiddens);
    k_segsum<<<dim3(4, 32), 256>>>();
    k_blend<<<dim3(4, 64), 256>>>();
    k_final<<<N_CELLS, 256>>>(out_nh, step);

    // join pred chain
    if (use_streams) cudaStreamWaitEvent(0, evP, 0);
}

// round 7
// speedup vs baseline: 3.3864x; 1.0131x over previous
#include <cuda_runtime.h>
#include <cuda_bf16.h>
#include <math.h>
#include <stdint.h>

#define N_CELLS 4096
#define IN_DIM 1024
#define HID 1024
#define OUT_DIM 1024
#define NT 8
#define NF 8
#define GIN 1025
#define G3 3072

typedef __nv_bfloat16 bf16;
typedef __nv_bfloat162 bf162;

// ---------------- scratch (device globals) ----------------
__device__ bf16 g_hid_h[N_CELLS * HID],   g_hid_l[N_CELLS * HID];
__device__ bf16 g_wih_h[G3 * 1024],       g_wih_l[G3 * 1024];
__device__ bf16 g_whh_h[G3 * 1024],       g_whh_l[G3 * 1024];
__device__ bf16 g_b1_h[256 * 1024],       g_b1_l[256 * 1024];
__device__ bf16 g_wc2_h[1024 * 256],      g_wc2_l[1024 * 256];
__device__ bf16 g_w2t_h[256 * 1024],      g_w2t_l[256 * 1024];
__device__ bf16 g_mcat_h[G3 * 256],       g_mcat_l[G3 * 256];
__device__ bf16 g_a1g1_h[N_CELLS * 256],  g_a1g1_l[N_CELLS * 256];
__device__ float g_gi[N_CELLS * G3];
__device__ float g_gh[N_CELLS * G3];
__device__ float g_nh[N_CELLS * HID];
__device__ float g_tension[N_CELLS];
__device__ float g_energy[N_CELLS];
__device__ int   g_votes[N_CELLS];
__device__ float g_bias1[256];
__device__ float g_bconst[1024];
__device__ float g_vih[G3];
__device__ float g_wt[G3];
__device__ float g_counts[NT];
__device__ float g_sums[NT * HID];
__device__ float g_fsums[NF * HID];
__device__ float g_w[N_CELLS];
__device__ float g_wa[256];
__device__ float g_combined[OUT_DIM];

// ---------------- asm helpers ----------------
__device__ __forceinline__ uint32_t smem_u32(const void* p) {
    uint32_t a;
    asm("{ .reg .u64 t; cvta.to.shared.u64 t, %1; cvt.u32.u64 %0, t; }" : "=r"(a) : "l"(p));
    return a;
}
__device__ __forceinline__ void cpa16(uint32_t s, const void* g) {
    asm volatile("cp.async.cg.shared.global [%0], [%1], 16;" :: "r"(s), "l"(g));
}
__device__ __forceinline__ void cp_commit() {
    asm volatile("cp.async.commit_group;" ::: "memory");
}
template <int N>
__device__ __forceinline__ void cp_wait() {
    asm volatile("cp.async.wait_group %0;" :: "n"(N) : "memory");
}
__device__ __forceinline__ void ldsm4(uint32_t& r0, uint32_t& r1, uint32_t& r2, uint32_t& r3,
                                      uint32_t a) {
    asm volatile("ldmatrix.sync.aligned.m8n8.x4.shared.b16 {%0,%1,%2,%3}, [%4];"
                 : "=r"(r0), "=r"(r1), "=r"(r2), "=r"(r3) : "r"(a));
}
__device__ __forceinline__ void mma16816(float c[4], const uint32_t a[4], const uint32_t b[2])
{
    asm("mma.sync.aligned.m16n8k16.row.col.f32.bf16.bf16.f32 "
        "{%0,%1,%2,%3}, {%4,%5,%6,%7}, {%8,%9}, {%0,%1,%2,%3};"
        : "+f"(c[0]), "+f"(c[1]), "+f"(c[2]), "+f"(c[3])
        : "r"(a[0]), "r"(a[1]), "r"(a[2]), "r"(a[3]), "r"(b[0]), "r"(b[1]));
}
__device__ __forceinline__ void split_bf16(float x, bf16& hi, bf16& lo)
{
    hi = __float2bfloat16_rn(x);
    lo = __float2bfloat16_rn(x - __bfloat162float(hi));
}
__device__ __forceinline__ float wred(float v)
{
    v += __shfl_xor_sync(0xffffffffu, v, 16);
    v += __shfl_xor_sync(0xffffffffu, v, 8);
    v += __shfl_xor_sync(0xffffffffu, v, 4);
    v += __shfl_xor_sync(0xffffffffu, v, 2);
    v += __shfl_xor_sync(0xffffffffu, v, 1);
    return v;
}

// =============== bf16 split-pipelined GEMM (product-major MMA ordering) ===============
template <int MI, bool RELU, bool WRITEBF, bool SUMSQ, bool NOC>
__global__ void __launch_bounds__(256) gemm_bf(
    const bf16* __restrict__ Ahi, const bf16* __restrict__ Alo, int lda,
    const bf16* __restrict__ Bhi, const bf16* __restrict__ Blo, int ldb,
    float* __restrict__ C, bf16* __restrict__ Chi, bf16* __restrict__ Clo, int ldc,
    int K, const float* __restrict__ bias)
{
    constexpr int TM = 64 * MI;
    constexpr int ABYTES = TM * 128;
    constexpr int BBYTES = 128 * 128;
    constexpr int STAGE = 2 * ABYTES + 2 * BBYTES;

    extern __shared__ __align__(1024) char smem[];
    const uint32_t sb = smem_u32(smem);
    const int tid = threadIdx.x;
    const int wid = tid >> 5, lane = tid & 31;
    const int wm = wid & 3, wn = wid >> 2;
    const int g = lane >> 2, tg = lane & 3;
    const int m0 = blockIdx.y * TM, n0 = blockIdx.x * 128;
    const int nc = K >> 6;

    float acc[MI][8][4];
#pragma unroll
    for (int mi = 0; mi < MI; mi++)
#pragma unroll
        for (int ni = 0; ni < 8; ni++)
#pragma unroll
            for (int q = 0; q < 4; q++) acc[mi][ni][q] = 0.f;

    auto load_stage = [&](int c, int b) {
        const uint32_t s0 = sb + b * STAGE;
        const int k0 = c << 6;
#pragma unroll
        for (int it = 0; it < TM * 8 / 256; it++) {
            int idx = tid + it * 256;
            int row = idx >> 3, ch = idx & 7;
            uint32_t so = (uint32_t)(row << 7) + (uint32_t)((ch ^ (row & 7)) << 4);
            size_t go = (size_t)(m0 + row) * lda + k0 + ch * 8;
            cpa16(s0 + so, Ahi + go);
            cpa16(s0 + ABYTES + so, Alo + go);
        }
#pragma unroll
        for (int it = 0; it < 4; it++) {
            int idx = tid + it * 256;
            int row = idx >> 3, ch = idx & 7;
            uint32_t so = (uint32_t)(row << 7) + (uint32_t)((ch ^ (row & 7)) << 4);
            size_t go = (size_t)(n0 + row) * ldb + k0 + ch * 8;
            cpa16(s0 + 2 * ABYTES + so, Bhi + go);
            cpa16(s0 + 2 * ABYTES + BBYTES + so, Blo + go);
        }
        cp_commit();
    };

    const int j = lane >> 3;
    const int arow_b = wm * (16 * MI) + (j & 1) * 8 + (lane & 7);
    const int brow_b = wn * 64 + (j >> 1) * 8 + (lane & 7);

    load_stage(0, 0);

    for (int c = 0; c < nc; c++) {
        if (c + 1 < nc) { load_stage(c + 1, (c + 1) & 1); cp_wait<1>(); }
        else            { cp_wait<0>(); }
        __syncthreads();

        const uint32_t sA = sb + (c & 1) * STAGE;
        const uint32_t sB = sA + 2 * ABYTES;

#pragma unroll
        for (int ks = 0; ks < 4; ks++) {
            uint32_t bh[8][2], bl[8][2];
            uint32_t ah[MI][4], al[MI][4];
            const int achunk = ks * 2 + (j >> 1);
            const int bchunk = ks * 2 + (j & 1);
            // ---- all fragment loads first ----
#pragma unroll
            for (int nb = 0; nb < 4; nb++) {
                int r = brow_b + nb * 16;
                uint32_t off = (uint32_t)(r << 7) + (uint32_t)((bchunk ^ (r & 7)) << 4);
                uint32_t t0, t1, t2, t3;
                ldsm4(t0, t1, t2, t3, sB + off);
                bh[2 * nb][0] = t0; bh[2 * nb][1] = t1;
                bh[2 * nb + 1][0] = t2; bh[2 * nb + 1][1] = t3;
                ldsm4(t0, t1, t2, t3, sB + BBYTES + off);
                bl[2 * nb][0] = t0; bl[2 * nb][1] = t1;
                bl[2 * nb + 1][0] = t2; bl[2 * nb + 1][1] = t3;
            }
#pragma unroll
            for (int mi = 0; mi < MI; mi++) {
                int r = arow_b + mi * 16;
                uint32_t off = (uint32_t)(r << 7) + (uint32_t)((achunk ^ (r & 7)) << 4);
                ldsm4(ah[mi][0], ah[mi][1], ah[mi][2], ah[mi][3], sA + off);
                ldsm4(al[mi][0], al[mi][1], al[mi][2], al[mi][3], sA + ABYTES + off);
            }
            // ---- product-major MMA sweeps: each acc revisited after MI*8-1 others ----
#pragma unroll
            for (int mi = 0; mi < MI; mi++)
#pragma unroll
                for (int ni = 0; ni < 8; ni++)
                    mma16816(acc[mi][ni], ah[mi], bh[ni]);
#pragma unroll
            for (int mi = 0; mi < MI; mi++)
#pragma unroll
                for (int ni = 0; ni < 8; ni++)
                    mma16816(acc[mi][ni], ah[mi], bl[ni]);
#pragma unroll
            for (int mi = 0; mi < MI; mi++)
#pragma unroll
                for (int ni = 0; ni < 8; ni++)
                    mma16816(acc[mi][ni], al[mi], bh[ni]);
        }
        __syncthreads();
    }

    // ---- epilogue ----
#pragma unroll
    for (int mi = 0; mi < MI; mi++) {
        int row0 = m0 + wm * (16 * MI) + mi * 16 + g;
        float p0 = 0.f, p1 = 0.f;
#pragma unroll
        for (int ni = 0; ni < 8; ni++) {
            int col = n0 + wn * 64 + ni * 8 + tg * 2;
            float b0 = bias ? bias[col] : 0.f;
            float b1 = bias ? bias[col + 1] : 0.f;
            float v0 = acc[mi][ni][0] + b0;
            float v1 = acc[mi][ni][1] + b1;
            float v2 = acc[mi][ni][2] + b0;
            float v3 = acc[mi][ni][3] + b1;
            if (RELU) {
                v0 = fmaxf(v0, 0.f); v1 = fmaxf(v1, 0.f);
                v2 = fmaxf(v2, 0.f); v3 = fmaxf(v3, 0.f);
            }
            if (SUMSQ) { p0 += v0 * v0 + v1 * v1; p1 += v2 * v2 + v3 * v3; }
            if (WRITEBF) {
                bf16 h0, l0, h1, l1;
                bf162 hp, lp;
                split_bf16(v0, h0, l0); split_bf16(v1, h1, l1);
                hp.x = h0; hp.y = h1; lp.x = l0; lp.y = l1;
                *(bf162*)(Chi + (size_t)row0 * ldc + col) = hp;
                *(bf162*)(Clo + (size_t)row0 * ldc + col) = lp;
                split_bf16(v2, h0, l0); split_bf16(v3, h1, l1);
                hp.x = h0; hp.y = h1; lp.x = l0; lp.y = l1;
                *(bf162*)(Chi + (size_t)(row0 + 8) * ldc + col) = hp;
                *(bf162*)(Clo + (size_t)(row0 + 8) * ldc + col) = lp;
            } else if (!NOC) {
                float2 q0; q0.x = v0; q0.y = v1;
                float2 q1; q1.x = v2; q1.y = v3;
                *(float2*)(C + (size_t)row0 * ldc + col) = q0;
                *(float2*)(C + (size_t)(row0 + 8) * ldc + col) = q1;
            }
        }
        if (SUMSQ) {
            p0 += __shfl_xor_sync(0xffffffffu, p0, 1);
            p0 += __shfl_xor_sync(0xffffffffu, p0, 2);
            p1 += __shfl_xor_sync(0xffffffffu, p1, 1);
            p1 += __shfl_xor_sync(0xffffffffu, p1, 2);
            if (tg == 0) {
                atomicAdd(&g_tension[row0], p0);
                atomicAdd(&g_tension[row0 + 8], p1);
            }
        }
    }
}

// ---------------- prep ----------------
__global__ void k_prep_all(const float* __restrict__ hiddens, const float* __restrict__ W_ih,
                           const float* __restrict__ W_hh,
                           const float* __restrict__ Wa1, const float* __restrict__ Wg1,
                           const float* __restrict__ Wa2, const float* __restrict__ Wg2,
                           const float* __restrict__ ba2, const float* __restrict__ bg2)
{
    long i = (long)blockIdx.x * 256 + threadIdx.x;
    const long N0 = 4194304L;
    const long N1 = N0 + 3145728L;
    const long N2 = N1 + 3145728L;
    const long N3 = N2 + 262144L;
    const long N4 = N3 + 131072L;
    const long N5 = N4 + 1024L;
    bf16 h, l;
    if (i < N0) {
        float v = hiddens[i];
        split_bf16(v, h, l); g_hid_h[i] = h; g_hid_l[i] = l;
    } else if (i < N1) {
        long k = i - N0; int r = (int)(k >> 10), c = (int)(k & 1023);
        float v = W_ih[(size_t)r * GIN + c];
        split_bf16(v, h, l); g_wih_h[k] = h; g_wih_l[k] = l;
    } else if (i < N2) {
        long k = i - N1;
        float v = W_hh[k];
        split_bf16(v, h, l); g_whh_h[k] = h; g_whh_l[k] = l;
    } else if (i < N3) {
        long k = i - N2; int r = (int)(k >> 10), c = (int)(k & 1023);
        float v = (r < 128) ? Wa1[r * 2048 + 1024 + c] : Wg1[(r - 128) * 2048 + 1024 + c];
        split_bf16(v, h, l); g_b1_h[k] = h; g_b1_l[k] = l;
    } else if (i < N4) {
        long k = i - N3; int jr = (int)(k >> 7), m = (int)(k & 127);
        float va = Wa2[k], vg = -Wg2[k];
        split_bf16(va, h, l);
        g_wc2_h[jr * 256 + m] = h;          g_wc2_l[jr * 256 + m] = l;
        g_w2t_h[m * 1024 + jr] = h;         g_w2t_l[m * 1024 + jr] = l;
        split_bf16(vg, h, l);
        g_wc2_h[jr * 256 + 128 + m] = h;    g_wc2_l[jr * 256 + 128 + m] = l;
        g_w2t_h[(128 + m) * 1024 + jr] = h; g_w2t_l[(128 + m) * 1024 + jr] = l;
    } else if (i < N5) {
        long k = i - N4;
        g_bconst[k] = ba2[k] - bg2[k];
    }
}

__global__ void k_zero()
{
    int i = blockIdx.x * 256 + threadIdx.x;
    if (i < NT) g_counts[i] = 0.f;
    if (i < NT * HID) { g_sums[i] = 0.f; g_fsums[i] = 0.f; }
    if (i < 256) g_wa[i] = 0.f;
    if (i < N_CELLS) g_tension[i] = 0.f;
}

__global__ void k_bias1(const float* __restrict__ Wa1, const float* __restrict__ ba1,
                        const float* __restrict__ Wg1, const float* __restrict__ bg1,
                        const float* __restrict__ x)
{
    int b = blockIdx.x * 8 + (threadIdx.x >> 5);
    int lane = threadIdx.x & 31;
    const float* row = (b < 128) ? (Wa1 + (size_t)b * 2048) : (Wg1 + (size_t)(b - 128) * 2048);
    float s = 0.f;
    for (int jj = lane; jj < 1024; jj += 32) s += row[jj] * x[jj];
    s = wred(s);
    if (lane == 0)
        g_bias1[b] = s + ((b < 128) ? ba1[b] : bg1[b - 128]);
}

__global__ void k_vih(const float* __restrict__ W_ih, const float* __restrict__ b_ih)
{
    int k = blockIdx.x * 8 + (threadIdx.x >> 5);
    int lane = threadIdx.x & 31;
    const float* row = W_ih + (size_t)k * GIN;
    float s = 0.f;
    for (int jj = lane; jj < 1024; jj += 32) s += row[jj] * g_bconst[jj];
    s = wred(s);
    if (lane == 0) { g_vih[k] = s + b_ih[k]; g_wt[k] = row[1024]; }
}

__global__ void k_vote(const float* __restrict__ infl, const float* __restrict__ op,
                       const float* __restrict__ noise)
{
    int row = blockIdx.x;
    int tid = threadIdx.x;
    int lane = tid & 31, wid = tid >> 5;
    float acc[NT];
#pragma unroll
    for (int t = 0; t < NT; t++) acc[t] = 0.f;
    const float* ir = infl + (size_t)row * N_CELLS;
    for (int c = tid; c < N_CELLS; c += 256) {
        float w = ir[c];
        if (w != 0.f) {
            const float4* o4 = (const float4*)(op + (size_t)c * NT);
            float4 a = o4[0], b = o4[1];
            acc[0] += w * a.x; acc[1] += w * a.y; acc[2] += w * a.z; acc[3] += w * a.w;
            acc[4] += w * b.x; acc[5] += w * b.y; acc[6] += w * b.z; acc[7] += w * b.w;
        }
    }
    __shared__ float sh[8][NT];
#pragma unroll
    for (int t = 0; t < NT; t++) {
        float v = wred(acc[t]);
        if (lane == 0) sh[wid][t] = v;
    }
    __syncthreads();
    if (tid == 0) {
        float v[NT]; float sum = 0.f;
#pragma unroll
        for (int t = 0; t < NT; t++) {
            float s = 0.f;
#pragma unroll
            for (int w = 0; w < 8; w++) s += sh[w][t];
            float u = 0.7f * op[row * NT + t] + 0.3f * s + 0.01f * noise[row * NT + t];
            u = fmaxf(u, 0.01f);
            v[t] = u; sum += u;
        }
        float inv = 1.f / sum;
        int am = 0; float mx = v[0] * inv;
#pragma unroll
        for (int t = 1; t < NT; t++) {
            float u = v[t] * inv;
            if (u > mx) { mx = u; am = t; }
        }
        g_votes[row] = am;
        g_energy[row] = mx;
        atomicAdd(&g_counts[am], 1.f);
    }
}

__global__ void k_gru(const float* __restrict__ hiddens)
{
    int i = blockIdx.x;
    float scale = 0.9f + 0.2f * g_energy[i];
    float t = g_tension[i] * (1.f / 1024.f);
    const float* gi = g_gi + (size_t)i * G3;
    const float* gh = g_gh + (size_t)i * G3;
    for (int jj = threadIdx.x; jj < HID; jj += 256) {
        float r = 1.f / (1.f + expf(-(gi[jj] + t * g_wt[jj] + gh[jj])));
        float z = 1.f / (1.f + expf(-(gi[jj + 1024] + t * g_wt[jj + 1024] + gh[jj + 1024])));
        float n = tanhf(gi[jj + 2048] + t * g_wt[jj + 2048] + r * gh[jj + 2048]);
        float h = hiddens[(size_t)i * 1024 + jj];
        float nh = (1.f - z) * n + z * h;
        nh = fminf(fmaxf(nh * scale, -10.f), 10.f);
        g_nh[(size_t)i * HID + jj] = nh;
    }
}

__global__ void k_segsum()
{
    int c = blockIdx.x * 256 + threadIdx.x;
    int r0 = blockIdx.y * 128;
    float acc[NT];
#pragma unroll
    for (int q = 0; q < NT; q++) acc[q] = 0.f;
    for (int r = r0; r < r0 + 128; r++) {
        float v = g_nh[(size_t)r * HID + c];
        int t = g_votes[r];
#pragma unroll
        for (int q = 0; q < NT; q++) acc[q] += (t == q) ? v : 0.f;
    }
#pragma unroll
    for (int q = 0; q < NT; q++) atomicAdd(&g_sums[q * HID + c], acc[q]);
}

__global__ void k_blend()
{
    int c = blockIdx.x * 256 + threadIdx.x;
    int r0 = blockIdx.y * 64;
    int f = r0 >> 9;
    float facc = 0.f;
    for (int r = r0; r < r0 + 64; r++) {
        int t = g_votes[r];
        float cnt = g_counts[t];
        float v = g_nh[(size_t)r * HID + c];
        if (cnt >= 2.f)
            v = 0.85f * v + 0.15f * (g_sums[t * HID + c] / fmaxf(cnt, 1.f));
        g_nh[(size_t)r * HID + c] = v;
        facc += v;
    }
    atomicAdd(&g_fsums[f * HID + c], facc);
}

__global__ void k_final(float* __restrict__ out_nh, const int* __restrict__ step)
{
    int i = blockIdx.x;
    int f = i >> 9;
    bool dcz = (*step > 5) && ((i & 511) < 128);
    for (int jj = threadIdx.x; jj < HID; jj += 256) {
        float fm = g_fsums[f * HID + jj] * (1.f / 512.f);
        float v = 0.85f * g_nh[(size_t)i * HID + jj] + 0.15f * fm;
        if (dcz) {
            float gsum = 0.f;
#pragma unroll
            for (int q = 0; q < NF; q++) gsum += g_fsums[q * HID + jj];
            v = 0.85f * v + 0.15f * (gsum * (1.f / 4096.f));
        }
        out_nh[(size_t)i * HID + jj] = v;
    }
}

__global__ void k_softmax(float* __restrict__ out_avg)
{
    __shared__ float sh[1024];
    int tid = threadIdx.x;
    float t4[4];
    float mx = -1e30f, av = 0.f;
#pragma unroll
    for (int q = 0; q < 4; q++) {
        t4[q] = g_tension[tid + q * 1024] * (1.f / 1024.f);
        mx = fmaxf(mx, t4[q]);
        av += t4[q];
    }
    sh[tid] = mx; __syncthreads();
    for (int o = 512; o > 0; o >>= 1) {
        if (tid < o) sh[tid] = fmaxf(sh[tid], sh[tid + o]);
        __syncthreads();
    }
    float M = sh[0]; __syncthreads();
    float sm = 0.f;
#pragma unroll
    for (int q = 0; q < 4; q++) {
        float e = expf(t4[q] - M);
        g_w[tid + q * 1024] = e;
        sm += e;
    }
    sh[tid] = sm; __syncthreads();
    for (int o = 512; o > 0; o >>= 1) {
        if (tid < o) sh[tid] += sh[tid + o];
        __syncthreads();
    }
    float inv = 1.f / sh[0]; __syncthreads();
#pragma unroll
    for (int q = 0; q < 4; q++) g_w[tid + q * 1024] *= inv;
    sh[tid] = av; __syncthreads();
    for (int o = 512; o > 0; o >>= 1) {
        if (tid < o) sh[tid] += sh[tid + o];
        __syncthreads();
    }
    if (tid == 0) out_avg[0] = sh[0] * (1.f / 4096.f);
}

__global__ void k_wA()
{
    int c = threadIdx.x;
    int r0 = blockIdx.x * 128;
    float acc = 0.f;
    for (int r = r0; r < r0 + 128; r++) {
        float w = g_w[r];
        float v = __bfloat162float(g_a1g1_h[(size_t)r * 256 + c])
                + __bfloat162float(g_a1g1_l[(size_t)r * 256 + c]);
        acc += w * v;
    }
    atomicAdd(&g_wa[c], acc);
}

__global__ void k_comb2()
{
    int jr = blockIdx.x * 8 + (threadIdx.x >> 5);
    int lane = threadIdx.x & 31;
    float s = 0.f;
    for (int m = lane; m < 256; m += 32) {
        float wv = __bfloat162float(g_wc2_h[(size_t)jr * 256 + m])
                 + __bfloat162float(g_wc2_l[(size_t)jr * 256 + m]);
        s += g_wa[m] * wv;
    }
    s = wred(s);
    if (lane == 0) g_combined[jr] = s + g_bconst[jr];
}

__global__ void k_pred(const float* __restrict__ Wo, const float* __restrict__ bo,
                       float* __restrict__ out_pred)
{
    int i = blockIdx.x * 8 + (threadIdx.x >> 5);
    int lane = threadIdx.x & 31;
    const float* row = Wo + (size_t)i * 1024;
    float s = 0.f;
    for (int jj = lane; jj < 1024; jj += 32) s += g_combined[jj] * row[jj];
    s = wred(s);
    if (lane == 0) out_pred[i] = s + bo[i];
}

// ---------------- launch ----------------
template <typename T>
static T* symp(const void* s)
{
    void* p = nullptr;
    cudaGetSymbolAddress(&p, s);
    return (T*)p;
}

#define SMEM_MI1 (2 * (2 * 64 * 128 + 2 * 128 * 128))    // 96 KB
#define SMEM_MI4 (2 * (2 * 256 * 128 + 2 * 128 * 128))   // 192 KB

extern "C" void kernel_launch(void* const* d_in, const int* in_sizes, int n_in,
                              void* d_out, int out_size)
{
    const float* x        = (const float*)d_in[0];
    const float* hiddens  = (const float*)d_in[1];
    const float* opinions = (const float*)d_in[2];
    const float* influence= (const float*)d_in[3];
    const float* noise    = (const float*)d_in[4];
    const float* Wa1 = (const float*)d_in[5];
    const float* ba1 = (const float*)d_in[6];
    const float* Wa2 = (const float*)d_in[7];
    const float* ba2 = (const float*)d_in[8];
    const float* Wg1 = (const float*)d_in[9];
    const float* bg1 = (const float*)d_in[10];
    const float* Wg2 = (const float*)d_in[11];
    const float* bg2 = (const float*)d_in[12];
    const float* W_ih = (const float*)d_in[13];
    const float* b_ih = (const float*)d_in[14];
    const float* W_hh = (const float*)d_in[15];
    const float* b_hh = (const float*)d_in[16];
    const float* Wo  = (const float*)d_in[17];
    const float* bo  = (const float*)d_in[18];
    const int*   step = (const int*)d_in[19];

    float* out = (float*)d_out;
    float* out_pred = out;
    float* out_avg  = out + 1024;
    float* out_nh   = out + 1025;

    bf16* pHidH = symp<bf16>(g_hid_h);  bf16* pHidL = symp<bf16>(g_hid_l);
    bf16* pWihH = symp<bf16>(g_wih_h);  bf16* pWihL = symp<bf16>(g_wih_l);
    bf16* pWhhH = symp<bf16>(g_whh_h);  bf16* pWhhL = symp<bf16>(g_whh_l);
    bf16* pB1H  = symp<bf16>(g_b1_h);   bf16* pB1L  = symp<bf16>(g_b1_l);
    bf16* pWc2H = symp<bf16>(g_wc2_h);  bf16* pWc2L = symp<bf16>(g_wc2_l);
    bf16* pW2TH = symp<bf16>(g_w2t_h);  bf16* pW2TL = symp<bf16>(g_w2t_l);
    bf16* pMcH  = symp<bf16>(g_mcat_h); bf16* pMcL  = symp<bf16>(g_mcat_l);
    bf16* pAgH  = symp<bf16>(g_a1g1_h); bf16* pAgL  = symp<bf16>(g_a1g1_l);
    float* pGi  = symp<float>(g_gi);
    float* pGh  = symp<float>(g_gh);
    float* pBias1 = symp<float>(g_bias1);
    float* pVih = symp<float>(g_vih);

    static bool init_done = false;
    static bool use_streams = false;
    static cudaStream_t sM = nullptr, sG = nullptr, sV = nullptr;
    static cudaEvent_t ev0 = nullptr, evPrep = nullptr, evM = nullptr,
                       evG = nullptr, evV = nullptr, evT = nullptr, evP = nullptr;
    if (!init_done) {
        init_done = true;
        cudaFuncSetAttribute(gemm_bf<1, false, true, false, false>,
                             cudaFuncAttributeMaxDynamicSharedMemorySize, SMEM_MI1);
        cudaFuncSetAttribute(gemm_bf<1, true, true, false, false>,
                             cudaFuncAttributeMaxDynamicSharedMemorySize, SMEM_MI1);
        cudaFuncSetAttribute(gemm_bf<4, false, false, false, false>,
                             cudaFuncAttributeMaxDynamicSharedMemorySize, SMEM_MI4);
        cudaFuncSetAttribute(gemm_bf<4, false, false, true, true>,
                             cudaFuncAttributeMaxDynamicSharedMemorySize, SMEM_MI4);
        use_streams =
            (cudaStreamCreateWithFlags(&sM, cudaStreamNonBlocking) == cudaSuccess) &&
            (cudaStreamCreateWithFlags(&sG, cudaStreamNonBlocking) == cudaSuccess) &&
            (cudaStreamCreateWithFlags(&sV, cudaStreamNonBlocking) == cudaSuccess) &&
            (cudaEventCreateWithFlags(&ev0, cudaEventDisableTiming) == cudaSuccess) &&
            (cudaEventCreateWithFlags(&evPrep, cudaEventDisableTiming) == cudaSuccess) &&
            (cudaEventCreateWithFlags(&evM, cudaEventDisableTiming) == cudaSuccess) &&
            (cudaEventCreateWithFlags(&evG, cudaEventDisableTiming) == cudaSuccess) &&
            (cudaEventCreateWithFlags(&evV, cudaEventDisableTiming) == cudaSuccess) &&
            (cudaEventCreateWithFlags(&evT, cudaEventDisableTiming) == cudaSuccess) &&
            (cudaEventCreateWithFlags(&evP, cudaEventDisableTiming) == cudaSuccess);
    }

    cudaStream_t m = use_streams ? sM : (cudaStream_t)0;
    cudaStream_t gg = use_streams ? sG : (cudaStream_t)0;
    cudaStream_t vv = use_streams ? sV : (cudaStream_t)0;

    k_zero<<<32, 256>>>();

    if (use_streams) { cudaEventRecord(ev0, 0); cudaStreamWaitEvent(vv, ev0, 0); }
    k_vote<<<N_CELLS, 256, 0, vv>>>(influence, opinions, noise);
    if (use_streams) cudaEventRecord(evV, vv);

    k_prep_all<<<42501, 256>>>(hiddens, W_ih, W_hh, Wa1, Wg1, Wa2, Wg2, ba2, bg2);
    if (use_streams) {
        cudaEventRecord(evPrep, 0);
        cudaStreamWaitEvent(m, evPrep, 0);
        cudaStreamWaitEvent(gg, evPrep, 0);
    }

    // gh on its own stream (heaviest, independent)
    gemm_bf<4, false, false, false, false><<<dim3(24, 16), 256, SMEM_MI4, gg>>>(
        pHidH, pHidL, 1024, pWhhH, pWhhL, 1024,
        pGh, nullptr, nullptr, G3, 1024, b_hh);
    if (use_streams) cudaEventRecord(evG, gg);

    // Mcat on stream m
    gemm_bf<1, false, true, false, false><<<dim3(2, 48), 256, SMEM_MI1, m>>>(
        pWihH, pWihL, 1024, pW2TH, pW2TL, 1024,
        nullptr, pMcH, pMcL, 256, 1024, nullptr);
    if (use_streams) cudaEventRecord(evM, m);

    // main chain
    k_bias1<<<32, 256>>>(Wa1, ba1, Wg1, bg1, x);
    k_vih<<<G3 / 8, 256>>>(W_ih, b_ih);

    gemm_bf<1, true, true, false, false><<<dim3(2, 64), 256, SMEM_MI1>>>(
        pHidH, pHidL, 1024, pB1H, pB1L, 1024,
        nullptr, pAgH, pAgL, 256, 1024, pBias1);

    // out-GEMM: tension only, no C write
    gemm_bf<4, false, false, true, true><<<dim3(8, 16), 256, SMEM_MI4>>>(
        pAgH, pAgL, 256, pWc2H, pWc2L, 256,
        nullptr, nullptr, nullptr, 1024, 256, symp<float>(g_bconst));
    if (use_streams) { cudaEventRecord(evT, 0); cudaStreamWaitEvent(m, evT, 0); }

    // softmax -> pred chain on stream m (hidden behind gi/gh)
    k_softmax<<<1, 1024, 0, m>>>(out_avg);
    k_wA<<<32, 256, 0, m>>>();
    k_comb2<<<128, 256, 0, m>>>();
    k_pred<<<128, 256, 0, m>>>(Wo, bo, out_pred);
    if (use_streams) cudaEventRecord(evP, m);

    // gi after Mcat
    if (use_streams) cudaStreamWaitEvent(0, evM, 0);
    gemm_bf<4, false, false, false, false><<<dim3(24, 16), 256, SMEM_MI4>>>(
        pAgH, pAgL, 256, pMcH, pMcL, 256,
        pGi, nullptr, nullptr, G3, 256, pVih);

    // join gh + vote, then GRU chain
    if (use_streams) { cudaStreamWaitEvent(0, evG, 0); cudaStreamWaitEvent(0, evV, 0); }
    k_gru<<<N_CELLS, 256>>>(hiddens);
    k_segsum<<<dim3(4, 32), 256>>>();
    k_blend<<<dim3(4, 64), 256>>>();
    k_final<<<N_CELLS, 256>>>(out_nh, step);

    // join pred chain
    if (use_streams) cudaStreamWaitEvent(0, evP, 0);
}

// round 8
// speedup vs baseline: 3.4523x; 1.0195x over previous
#include <cuda_runtime.h>
#include <cuda_bf16.h>
#include <math.h>
#include <stdint.h>

#define N_CELLS 4096
#define IN_DIM 1024
#define HID 1024
#define OUT_DIM 1024
#define NT 8
#define NF 8
#define GIN 1025
#define G3 3072

typedef __nv_bfloat16 bf16;
typedef __nv_bfloat162 bf162;

// ---------------- scratch (device globals) ----------------
__device__ bf16 g_hid_h[N_CELLS * HID],   g_hid_l[N_CELLS * HID];
__device__ bf16 g_wih_h[G3 * 1024],       g_wih_l[G3 * 1024];
__device__ bf16 g_whh_h[G3 * 1024],       g_whh_l[G3 * 1024];
__device__ bf16 g_b1_h[256 * 1024],       g_b1_l[256 * 1024];
__device__ bf16 g_wc2_h[1024 * 256],      g_wc2_l[1024 * 256];
__device__ bf16 g_w2t_h[256 * 1024],      g_w2t_l[256 * 1024];
__device__ bf16 g_mcat_h[G3 * 256],       g_mcat_l[G3 * 256];
__device__ bf16 g_a1g1_h[N_CELLS * 256],  g_a1g1_l[N_CELLS * 256];
__device__ float g_gi[N_CELLS * G3];
__device__ float g_gh[N_CELLS * G3];
__device__ float g_nh[N_CELLS * HID];
__device__ float g_tension[N_CELLS];
__device__ float g_energy[N_CELLS];
__device__ int   g_votes[N_CELLS];
__device__ float g_bias1[256];
__device__ float g_bconst[1024];
__device__ float g_vih[G3];
__device__ float g_wt[G3];
__device__ float g_counts[NT];
__device__ float g_sums[NT * HID];
__device__ float g_fsums[NF * HID];
__device__ float g_w[N_CELLS];
__device__ float g_wa[256];
__device__ float g_combined[OUT_DIM];

// ---------------- asm helpers ----------------
__device__ __forceinline__ uint32_t smem_u32(const void* p) {
    uint32_t a;
    asm("{ .reg .u64 t; cvta.to.shared.u64 t, %1; cvt.u32.u64 %0, t; }" : "=r"(a) : "l"(p));
    return a;
}
__device__ __forceinline__ void cpa16(uint32_t s, const void* g) {
    asm volatile("cp.async.cg.shared.global [%0], [%1], 16;" :: "r"(s), "l"(g));
}
__device__ __forceinline__ void cp_commit() {
    asm volatile("cp.async.commit_group;" ::: "memory");
}
template <int N>
__device__ __forceinline__ void cp_wait() {
    asm volatile("cp.async.wait_group %0;" :: "n"(N) : "memory");
}
__device__ __forceinline__ void ldsm4(uint32_t& r0, uint32_t& r1, uint32_t& r2, uint32_t& r3,
                                      uint32_t a) {
    asm volatile("ldmatrix.sync.aligned.m8n8.x4.shared.b16 {%0,%1,%2,%3}, [%4];"
                 : "=r"(r0), "=r"(r1), "=r"(r2), "=r"(r3) : "r"(a));
}
__device__ __forceinline__ void mma16816(float c[4], const uint32_t a[4], const uint32_t b[2])
{
    asm("mma.sync.aligned.m16n8k16.row.col.f32.bf16.bf16.f32 "
        "{%0,%1,%2,%3}, {%4,%5,%6,%7}, {%8,%9}, {%0,%1,%2,%3};"
        : "+f"(c[0]), "+f"(c[1]), "+f"(c[2]), "+f"(c[3])
        : "r"(a[0]), "r"(a[1]), "r"(a[2]), "r"(a[3]), "r"(b[0]), "r"(b[1]));
}
__device__ __forceinline__ void split_bf16(float x, bf16& hi, bf16& lo)
{
    hi = __float2bfloat16_rn(x);
    lo = __float2bfloat16_rn(x - __bfloat162float(hi));
}
__device__ __forceinline__ float wred(float v)
{
    v += __shfl_xor_sync(0xffffffffu, v, 16);
    v += __shfl_xor_sync(0xffffffffu, v, 8);
    v += __shfl_xor_sync(0xffffffffu, v, 4);
    v += __shfl_xor_sync(0xffffffffu, v, 2);
    v += __shfl_xor_sync(0xffffffffu, v, 1);
    return v;
}

// ---- epilogue modes: 0 = fp32 write, 1 = bf16 split + relu, 2 = sumsq-only, 3 = bf16 split ----
template <int MODE, int MI>
__device__ __forceinline__ void epilogue(
    float (*acc)[8][4], int m0, int nb0,
    bf16* __restrict__ Chi, bf16* __restrict__ Clo, int ldcb,
    float* __restrict__ Cf, int ldcf,
    const float* __restrict__ bias,
    int wm, int wn, int g, int tg)
{
#pragma unroll
    for (int mi = 0; mi < MI; mi++) {
        int row0 = m0 + wm * (16 * MI) + mi * 16 + g;
        float p0 = 0.f, p1 = 0.f;
#pragma unroll
        for (int ni = 0; ni < 8; ni++) {
            int lc = wn * 64 + ni * 8 + tg * 2;
            float b0 = bias ? bias[lc] : 0.f;
            float b1 = bias ? bias[lc + 1] : 0.f;
            float v0 = acc[mi][ni][0] + b0;
            float v1 = acc[mi][ni][1] + b1;
            float v2 = acc[mi][ni][2] + b0;
            float v3 = acc[mi][ni][3] + b1;
            if (MODE == 1) {
                v0 = fmaxf(v0, 0.f); v1 = fmaxf(v1, 0.f);
                v2 = fmaxf(v2, 0.f); v3 = fmaxf(v3, 0.f);
            }
            if (MODE == 2) { p0 += v0 * v0 + v1 * v1; p1 += v2 * v2 + v3 * v3; }
            if (MODE == 1 || MODE == 3) {
                bf16 h0, l0, h1, l1;
                bf162 hp, lp;
                split_bf16(v0, h0, l0); split_bf16(v1, h1, l1);
                hp.x = h0; hp.y = h1; lp.x = l0; lp.y = l1;
                *(bf162*)(Chi + (size_t)row0 * ldcb + nb0 + lc) = hp;
                *(bf162*)(Clo + (size_t)row0 * ldcb + nb0 + lc) = lp;
                split_bf16(v2, h0, l0); split_bf16(v3, h1, l1);
                hp.x = h0; hp.y = h1; lp.x = l0; lp.y = l1;
                *(bf162*)(Chi + (size_t)(row0 + 8) * ldcb + nb0 + lc) = hp;
                *(bf162*)(Clo + (size_t)(row0 + 8) * ldcb + nb0 + lc) = lp;
            }
            if (MODE == 0) {
                float2 q0; q0.x = v0; q0.y = v1;
                float2 q1; q1.x = v2; q1.y = v3;
                *(float2*)(Cf + (size_t)row0 * ldcf + nb0 + lc) = q0;
                *(float2*)(Cf + (size_t)(row0 + 8) * ldcf + nb0 + lc) = q1;
            }
        }
        if (MODE == 2) {
            p0 += __shfl_xor_sync(0xffffffffu, p0, 1);
            p0 += __shfl_xor_sync(0xffffffffu, p0, 2);
            p1 += __shfl_xor_sync(0xffffffffu, p1, 1);
            p1 += __shfl_xor_sync(0xffffffffu, p1, 2);
            if (tg == 0) {
                atomicAdd(&g_tension[row0], p0);
                atomicAdd(&g_tension[row0 + 8], p1);
            }
        }
    }
}

// =============== merged dual-region bf16 split GEMM ===============
// C over N = [region1 | region2] split at NSPLIT; per-region B source, bias, and mode.
// A [M,K] hi/lo bf16; B rows [N,K] hi/lo. 3-product fp32 emulation. 1 sync/chunk,
// deferred next-stage cp.async (issued after first k16 MMA sweep).
template <int MI, int NSPLIT, int MODE1, int MODE2>
__global__ void __launch_bounds__(256) gemm2(
    const bf16* __restrict__ Ahi, const bf16* __restrict__ Alo, int lda,
    const bf16* __restrict__ B1h, const bf16* __restrict__ B1l,
    const bf16* __restrict__ B2h, const bf16* __restrict__ B2l,
    bf16* __restrict__ Chi, bf16* __restrict__ Clo, int ldcb,
    float* __restrict__ C1, int ldc1,
    float* __restrict__ C2, int ldc2,
    int K,
    const float* __restrict__ bias1, const float* __restrict__ bias2)
{
    constexpr int TM = 64 * MI;
    constexpr int ABYTES = TM * 128;
    constexpr int BBYTES = 128 * 128;
    constexpr int STAGE = 2 * ABYTES + 2 * BBYTES;

    extern __shared__ __align__(1024) char smem[];
    const uint32_t sb = smem_u32(smem);
    const int tid = threadIdx.x;
    const int wid = tid >> 5, lane = tid & 31;
    const int wm = wid & 3, wn = wid >> 2;
    const int g = lane >> 2, tg = lane & 3;
    const int m0 = blockIdx.y * TM, n0 = blockIdx.x * 128;
    const int nc = K >> 6;

    const bool r1 = (n0 < NSPLIT);
    const int nb0 = r1 ? n0 : n0 - NSPLIT;
    const bf16* __restrict__ Bh = (r1 ? B1h : B2h) + (size_t)nb0 * K;
    const bf16* __restrict__ Bl = (r1 ? B1l : B2l) + (size_t)nb0 * K;
    const float* bias = r1 ? (bias1 ? bias1 + nb0 : nullptr)
                           : (bias2 ? bias2 + nb0 : nullptr);

    float acc[MI][8][4];
#pragma unroll
    for (int mi = 0; mi < MI; mi++)
#pragma unroll
        for (int ni = 0; ni < 8; ni++)
#pragma unroll
            for (int q = 0; q < 4; q++) acc[mi][ni][q] = 0.f;

    auto load_stage = [&](int c, int b) {
        const uint32_t s0 = sb + b * STAGE;
        const int k0 = c << 6;
#pragma unroll
        for (int it = 0; it < TM * 8 / 256; it++) {
            int idx = tid + it * 256;
            int row = idx >> 3, ch = idx & 7;
            uint32_t so = (uint32_t)(row << 7) + (uint32_t)((ch ^ (row & 7)) << 4);
            size_t go = (size_t)(m0 + row) * lda + k0 + ch * 8;
            cpa16(s0 + so, Ahi + go);
            cpa16(s0 + ABYTES + so, Alo + go);
        }
#pragma unroll
        for (int it = 0; it < 4; it++) {
            int idx = tid + it * 256;
            int row = idx >> 3, ch = idx & 7;
            uint32_t so = (uint32_t)(row << 7) + (uint32_t)((ch ^ (row & 7)) << 4);
            size_t go = (size_t)row * K + k0 + ch * 8;
            cpa16(s0 + 2 * ABYTES + so, Bh + go);
            cpa16(s0 + 2 * ABYTES + BBYTES + so, Bl + go);
        }
        cp_commit();
    };

    const int j = lane >> 3;
    const int arow_b = wm * (16 * MI) + (j & 1) * 8 + (lane & 7);
    const int brow_b = wn * 64 + (j >> 1) * 8 + (lane & 7);

    load_stage(0, 0);

    for (int c = 0; c < nc; c++) {
        cp_wait<0>();
        __syncthreads();

        const uint32_t sA = sb + (c & 1) * STAGE;
        const uint32_t sB = sA + 2 * ABYTES;

#pragma unroll
        for (int ks = 0; ks < 4; ks++) {
            uint32_t bh[8][2], bl[8][2];
            uint32_t ah[MI][4], al[MI][4];
            const int achunk = ks * 2 + (j >> 1);
            const int bchunk = ks * 2 + (j & 1);
#pragma unroll
            for (int nb = 0; nb < 4; nb++) {
                int r = brow_b + nb * 16;
                uint32_t off = (uint32_t)(r << 7) + (uint32_t)((bchunk ^ (r & 7)) << 4);
                uint32_t t0, t1, t2, t3;
                ldsm4(t0, t1, t2, t3, sB + off);
                bh[2 * nb][0] = t0; bh[2 * nb][1] = t1;
                bh[2 * nb + 1][0] = t2; bh[2 * nb + 1][1] = t3;
                ldsm4(t0, t1, t2, t3, sB + BBYTES + off);
                bl[2 * nb][0] = t0; bl[2 * nb][1] = t1;
                bl[2 * nb + 1][0] = t2; bl[2 * nb + 1][1] = t3;
            }
#pragma unroll
            for (int mi = 0; mi < MI; mi++) {
                int r = arow_b + mi * 16;
                uint32_t off = (uint32_t)(r << 7) + (uint32_t)((achunk ^ (r & 7)) << 4);
                ldsm4(ah[mi][0], ah[mi][1], ah[mi][2], ah[mi][3], sA + off);
                ldsm4(al[mi][0], al[mi][1], al[mi][2], al[mi][3], sA + ABYTES + off);
            }
#pragma unroll
            for (int mi = 0; mi < MI; mi++)
#pragma unroll
                for (int ni = 0; ni < 8; ni++)
                    mma16816(acc[mi][ni], ah[mi], bh[ni]);
#pragma unroll
            for (int mi = 0; mi < MI; mi++)
#pragma unroll
                for (int ni = 0; ni < 8; ni++)
                    mma16816(acc[mi][ni], ah[mi], bl[ni]);
#pragma unroll
            for (int mi = 0; mi < MI; mi++)
#pragma unroll
                for (int ni = 0; ni < 8; ni++)
                    mma16816(acc[mi][ni], al[mi], bh[ni]);
            // overlap next-stage global loads with remaining MMA sweeps
            if (ks == 0 && c + 1 < nc) load_stage(c + 1, (c + 1) & 1);
        }
        // single sync per chunk: top-of-next-chunk sync orders buffer reuse
    }

    if (r1) epilogue<MODE1, MI>(acc, m0, nb0, Chi, Clo, ldcb, C1, ldc1, bias, wm, wn, g, tg);
    else    epilogue<MODE2, MI>(acc, m0, nb0, Chi, Clo, ldcb, C2, ldc2, bias, wm, wn, g, tg);
}

// ---------------- prep ----------------
__global__ void k_prep_all(const float* __restrict__ hiddens, const float* __restrict__ W_ih,
                           const float* __restrict__ W_hh,
                           const float* __restrict__ Wa1, const float* __restrict__ Wg1,
                           const float* __restrict__ Wa2, const float* __restrict__ Wg2,
                           const float* __restrict__ ba2, const float* __restrict__ bg2)
{
    long i = (long)blockIdx.x * 256 + threadIdx.x;
    const long N0 = 4194304L;
    const long N1 = N0 + 3145728L;
    const long N2 = N1 + 3145728L;
    const long N3 = N2 + 262144L;
    const long N4 = N3 + 131072L;
    const long N5 = N4 + 1024L;
    bf16 h, l;
    if (i < N0) {
        float v = hiddens[i];
        split_bf16(v, h, l); g_hid_h[i] = h; g_hid_l[i] = l;
    } else if (i < N1) {
        long k = i - N0; int r = (int)(k >> 10), c = (int)(k & 1023);
        float v = W_ih[(size_t)r * GIN + c];
        split_bf16(v, h, l); g_wih_h[k] = h; g_wih_l[k] = l;
    } else if (i < N2) {
        long k = i - N1;
        float v = W_hh[k];
        split_bf16(v, h, l); g_whh_h[k] = h; g_whh_l[k] = l;
    } else if (i < N3) {
        long k = i - N2; int r = (int)(k >> 10), c = (int)(k & 1023);
        float v = (r < 128) ? Wa1[r * 2048 + 1024 + c] : Wg1[(r - 128) * 2048 + 1024 + c];
        split_bf16(v, h, l); g_b1_h[k] = h; g_b1_l[k] = l;
    } else if (i < N4) {
        long k = i - N3; int jr = (int)(k >> 7), m = (int)(k & 127);
        float va = Wa2[k], vg = -Wg2[k];
        split_bf16(va, h, l);
        g_wc2_h[jr * 256 + m] = h;          g_wc2_l[jr * 256 + m] = l;
        g_w2t_h[m * 1024 + jr] = h;         g_w2t_l[m * 1024 + jr] = l;
        split_bf16(vg, h, l);
        g_wc2_h[jr * 256 + 128 + m] = h;    g_wc2_l[jr * 256 + 128 + m] = l;
        g_w2t_h[(128 + m) * 1024 + jr] = h; g_w2t_l[(128 + m) * 1024 + jr] = l;
    } else if (i < N5) {
        long k = i - N4;
        g_bconst[k] = ba2[k] - bg2[k];
    }
}

__global__ void k_zero()
{
    int i = blockIdx.x * 256 + threadIdx.x;
    if (i < NT) g_counts[i] = 0.f;
    if (i < NT * HID) { g_sums[i] = 0.f; g_fsums[i] = 0.f; }
    if (i < 256) g_wa[i] = 0.f;
    if (i < N_CELLS) g_tension[i] = 0.f;
}

__global__ void k_bias1(const float* __restrict__ Wa1, const float* __restrict__ ba1,
                        const float* __restrict__ Wg1, const float* __restrict__ bg1,
                        const float* __restrict__ x)
{
    int b = blockIdx.x * 8 + (threadIdx.x >> 5);
    int lane = threadIdx.x & 31;
    const float* row = (b < 128) ? (Wa1 + (size_t)b * 2048) : (Wg1 + (size_t)(b - 128) * 2048);
    float s = 0.f;
    for (int jj = lane; jj < 1024; jj += 32) s += row[jj] * x[jj];
    s = wred(s);
    if (lane == 0)
        g_bias1[b] = s + ((b < 128) ? ba1[b] : bg1[b - 128]);
}

__global__ void k_vih(const float* __restrict__ W_ih, const float* __restrict__ b_ih)
{
    int k = blockIdx.x * 8 + (threadIdx.x >> 5);
    int lane = threadIdx.x & 31;
    const float* row = W_ih + (size_t)k * GIN;
    float s = 0.f;
    for (int jj = lane; jj < 1024; jj += 32) s += row[jj] * g_bconst[jj];
    s = wred(s);
    if (lane == 0) { g_vih[k] = s + b_ih[k]; g_wt[k] = row[1024]; }
}

__global__ void k_vote(const float* __restrict__ infl, const float* __restrict__ op,
                       const float* __restrict__ noise)
{
    int row = blockIdx.x;
    int tid = threadIdx.x;
    int lane = tid & 31, wid = tid >> 5;
    float acc[NT];
#pragma unroll
    for (int t = 0; t < NT; t++) acc[t] = 0.f;
    const float* ir = infl + (size_t)row * N_CELLS;
    for (int c = tid; c < N_CELLS; c += 256) {
        float w = ir[c];
        if (w != 0.f) {
            const float4* o4 = (const float4*)(op + (size_t)c * NT);
            float4 a = o4[0], b = o4[1];
            acc[0] += w * a.x; acc[1] += w * a.y; acc[2] += w * a.z; acc[3] += w * a.w;
            acc[4] += w * b.x; acc[5] += w * b.y; acc[6] += w * b.z; acc[7] += w * b.w;
        }
    }
    __shared__ float sh[8][NT];
#pragma unroll
    for (int t = 0; t < NT; t++) {
        float v = wred(acc[t]);
        if (lane == 0) sh[wid][t] = v;
    }
    __syncthreads();
    if (tid == 0) {
        float v[NT]; float sum = 0.f;
#pragma unroll
        for (int t = 0; t < NT; t++) {
            float s = 0.f;
#pragma unroll
            for (int w = 0; w < 8; w++) s += sh[w][t];
            float u = 0.7f * op[row * NT + t] + 0.3f * s + 0.01f * noise[row * NT + t];
            u = fmaxf(u, 0.01f);
            v[t] = u; sum += u;
        }
        float inv = 1.f / sum;
        int am = 0; float mx = v[0] * inv;
#pragma unroll
        for (int t = 1; t < NT; t++) {
            float u = v[t] * inv;
            if (u > mx) { mx = u; am = t; }
        }
        g_votes[row] = am;
        g_energy[row] = mx;
        atomicAdd(&g_counts[am], 1.f);
    }
}

__global__ void k_gru(const float* __restrict__ hiddens)
{
    int i = blockIdx.x;
    float scale = 0.9f + 0.2f * g_energy[i];
    float t = g_tension[i] * (1.f / 1024.f);
    const float* gi = g_gi + (size_t)i * G3;
    const float* gh = g_gh + (size_t)i * G3;
    for (int jj = threadIdx.x; jj < HID; jj += 256) {
        float r = 1.f / (1.f + expf(-(gi[jj] + t * g_wt[jj] + gh[jj])));
        float z = 1.f / (1.f + expf(-(gi[jj + 1024] + t * g_wt[jj + 1024] + gh[jj + 1024])));
        float n = tanhf(gi[jj + 2048] + t * g_wt[jj + 2048] + r * gh[jj + 2048]);
        float h = hiddens[(size_t)i * 1024 + jj];
        float nh = (1.f - z) * n + z * h;
        nh = fminf(fmaxf(nh * scale, -10.f), 10.f);
        g_nh[(size_t)i * HID + jj] = nh;
    }
}

__global__ void k_segsum()
{
    int c = blockIdx.x * 256 + threadIdx.x;
    int r0 = blockIdx.y * 128;
    float acc[NT];
#pragma unroll
    for (int q = 0; q < NT; q++) acc[q] = 0.f;
    for (int r = r0; r < r0 + 128; r++) {
        float v = g_nh[(size_t)r * HID + c];
        int t = g_votes[r];
#pragma unroll
        for (int q = 0; q < NT; q++) acc[q] += (t == q) ? v : 0.f;
    }
#pragma unroll
    for (int q = 0; q < NT; q++) atomicAdd(&g_sums[q * HID + c], acc[q]);
}

__global__ void k_blend()
{
    int c = blockIdx.x * 256 + threadIdx.x;
    int r0 = blockIdx.y * 64;
    int f = r0 >> 9;
    float facc = 0.f;
    for (int r = r0; r < r0 + 64; r++) {
        int t = g_votes[r];
        float cnt = g_counts[t];
        float v = g_nh[(size_t)r * HID + c];
        if (cnt >= 2.f)
            v = 0.85f * v + 0.15f * (g_sums[t * HID + c] / fmaxf(cnt, 1.f));
        g_nh[(size_t)r * HID + c] = v;
        facc += v;
    }
    atomicAdd(&g_fsums[f * HID + c], facc);
}

__global__ void k_final(float* __restrict__ out_nh, const int* __restrict__ step)
{
    int i = blockIdx.x;
    int f = i >> 9;
    bool dcz = (*step > 5) && ((i & 511) < 128);
    for (int jj = threadIdx.x; jj < HID; jj += 256) {
        float fm = g_fsums[f * HID + jj] * (1.f / 512.f);
        float v = 0.85f * g_nh[(size_t)i * HID + jj] + 0.15f * fm;
        if (dcz) {
            float gsum = 0.f;
#pragma unroll
            for (int q = 0; q < NF; q++) gsum += g_fsums[q * HID + jj];
            v = 0.85f * v + 0.15f * (gsum * (1.f / 4096.f));
        }
        out_nh[(size_t)i * HID + jj] = v;
    }
}

__global__ void k_softmax(float* __restrict__ out_avg)
{
    __shared__ float sh[1024];
    int tid = threadIdx.x;
    float t4[4];
    float mx = -1e30f, av = 0.f;
#pragma unroll
    for (int q = 0; q < 4; q++) {
        t4[q] = g_tension[tid + q * 1024] * (1.f / 1024.f);
        mx = fmaxf(mx, t4[q]);
        av += t4[q];
    }
    sh[tid] = mx; __syncthreads();
    for (int o = 512; o > 0; o >>= 1) {
        if (tid < o) sh[tid] = fmaxf(sh[tid], sh[tid + o]);
        __syncthreads();
    }
    float M = sh[0]; __syncthreads();
    float sm = 0.f;
#pragma unroll
    for (int q = 0; q < 4; q++) {
        float e = expf(t4[q] - M);
        g_w[tid + q * 1024] = e;
        sm += e;
    }
    sh[tid] = sm; __syncthreads();
    for (int o = 512; o > 0; o >>= 1) {
        if (tid < o) sh[tid] += sh[tid + o];
        __syncthreads();
    }
    float inv = 1.f / sh[0]; __syncthreads();
#pragma unroll
    for (int q = 0; q < 4; q++) g_w[tid + q * 1024] *= inv;
    sh[tid] = av; __syncthreads();
    for (int o = 512; o > 0; o >>= 1) {
        if (tid < o) sh[tid] += sh[tid + o];
        __syncthreads();
    }
    if (tid == 0) out_avg[0] = sh[0] * (1.f / 4096.f);
}

__global__ void k_wA()
{
    int c = threadIdx.x;
    int r0 = blockIdx.x * 128;
    float acc = 0.f;
    for (int r = r0; r < r0 + 128; r++) {
        float w = g_w[r];
        float v = __bfloat162float(g_a1g1_h[(size_t)r * 256 + c])
                + __bfloat162float(g_a1g1_l[(size_t)r * 256 + c]);
        acc += w * v;
    }
    atomicAdd(&g_wa[c], acc);
}

__global__ void k_comb2()
{
    int jr = blockIdx.x * 8 + (threadIdx.x >> 5);
    int lane = threadIdx.x & 31;
    float s = 0.f;
    for (int m = lane; m < 256; m += 32) {
        float wv = __bfloat162float(g_wc2_h[(size_t)jr * 256 + m])
                 + __bfloat162float(g_wc2_l[(size_t)jr * 256 + m]);
        s += g_wa[m] * wv;
    }
    s = wred(s);
    if (lane == 0) g_combined[jr] = s + g_bconst[jr];
}

__global__ void k_pred(const float* __restrict__ Wo, const float* __restrict__ bo,
                       float* __restrict__ out_pred)
{
    int i = blockIdx.x * 8 + (threadIdx.x >> 5);
    int lane = threadIdx.x & 31;
    const float* row = Wo + (size_t)i * 1024;
    float s = 0.f;
    for (int jj = lane; jj < 1024; jj += 32) s += g_combined[jj] * row[jj];
    s = wred(s);
    if (lane == 0) out_pred[i] = s + bo[i];
}

// ---------------- launch ----------------
template <typename T>
static T* symp(const void* s)
{
    void* p = nullptr;
    cudaGetSymbolAddress(&p, s);
    return (T*)p;
}

#define SMEM_MI1 (2 * (2 * 64 * 128 + 2 * 128 * 128))    // 96 KB
#define SMEM_MI4 (2 * (2 * 256 * 128 + 2 * 128 * 128))   // 192 KB

extern "C" void kernel_launch(void* const* d_in, const int* in_sizes, int n_in,
                              void* d_out, int out_size)
{
    const float* x        = (const float*)d_in[0];
    const float* hiddens  = (const float*)d_in[1];
    const float* opinions = (const float*)d_in[2];
    const float* influence= (const float*)d_in[3];
    const float* noise    = (const float*)d_in[4];
    const float* Wa1 = (const float*)d_in[5];
    const float* ba1 = (const float*)d_in[6];
    const float* Wa2 = (const float*)d_in[7];
    const float* ba2 = (const float*)d_in[8];
    const float* Wg1 = (const float*)d_in[9];
    const float* bg1 = (const float*)d_in[10];
    const float* Wg2 = (const float*)d_in[11];
    const float* bg2 = (const float*)d_in[12];
    const float* W_ih = (const float*)d_in[13];
    const float* b_ih = (const float*)d_in[14];
    const float* W_hh = (const float*)d_in[15];
    const float* b_hh = (const float*)d_in[16];
    const float* Wo  = (const float*)d_in[17];
    const float* bo  = (const float*)d_in[18];
    const int*   step = (const int*)d_in[19];

    float* out = (float*)d_out;
    float* out_pred = out;
    float* out_avg  = out + 1024;
    float* out_nh   = out + 1025;

    bf16* pHidH = symp<bf16>(g_hid_h);  bf16* pHidL = symp<bf16>(g_hid_l);
    bf16* pWihH = symp<bf16>(g_wih_h);  bf16* pWihL = symp<bf16>(g_wih_l);
    bf16* pWhhH = symp<bf16>(g_whh_h);  bf16* pWhhL = symp<bf16>(g_whh_l);
    bf16* pB1H  = symp<bf16>(g_b1_h);   bf16* pB1L  = symp<bf16>(g_b1_l);
    bf16* pWc2H = symp<bf16>(g_wc2_h);  bf16* pWc2L = symp<bf16>(g_wc2_l);
    bf16* pW2TH = symp<bf16>(g_w2t_h);  bf16* pW2TL = symp<bf16>(g_w2t_l);
    bf16* pMcH  = symp<bf16>(g_mcat_h); bf16* pMcL  = symp<bf16>(g_mcat_l);
    bf16* pAgH  = symp<bf16>(g_a1g1_h); bf16* pAgL  = symp<bf16>(g_a1g1_l);
    float* pGi  = symp<float>(g_gi);
    float* pGh  = symp<float>(g_gh);
    float* pBias1 = symp<float>(g_bias1);
    float* pBconst= symp<float>(g_bconst);
    float* pVih = symp<float>(g_vih);

    static bool init_done = false;
    static bool use_streams = false;
    static cudaStream_t sM = nullptr, sV = nullptr;
    static cudaEvent_t ev0 = nullptr, evPrep = nullptr, evM = nullptr,
                       evV = nullptr, evT = nullptr, evP = nullptr;
    if (!init_done) {
        init_done = true;
        cudaFuncSetAttribute(gemm2<4, 256, 1, 0>,
                             cudaFuncAttributeMaxDynamicSharedMemorySize, SMEM_MI4);
        cudaFuncSetAttribute(gemm2<4, 3072, 0, 2>,
                             cudaFuncAttributeMaxDynamicSharedMemorySize, SMEM_MI4);
        cudaFuncSetAttribute(gemm2<1, 4096, 3, 0>,
                             cudaFuncAttributeMaxDynamicSharedMemorySize, SMEM_MI1);
        use_streams =
            (cudaStreamCreateWithFlags(&sM, cudaStreamNonBlocking) == cudaSuccess) &&
            (cudaStreamCreateWithFlags(&sV, cudaStreamNonBlocking) == cudaSuccess) &&
            (cudaEventCreateWithFlags(&ev0, cudaEventDisableTiming) == cudaSuccess) &&
            (cudaEventCreateWithFlags(&evPrep, cudaEventDisableTiming) == cudaSuccess) &&
            (cudaEventCreateWithFlags(&evM, cudaEventDisableTiming) == cudaSuccess) &&
            (cudaEventCreateWithFlags(&evV, cudaEventDisableTiming) == cudaSuccess) &&
            (cudaEventCreateWithFlags(&evT, cudaEventDisableTiming) == cudaSuccess) &&
            (cudaEventCreateWithFlags(&evP, cudaEventDisableTiming) == cudaSuccess);
    }

    cudaStream_t m = use_streams ? sM : (cudaStream_t)0;
    cudaStream_t vv = use_streams ? sV : (cudaStream_t)0;

    k_zero<<<32, 256>>>();

    if (use_streams) { cudaEventRecord(ev0, 0); cudaStreamWaitEvent(vv, ev0, 0); }
    k_vote<<<N_CELLS, 256, 0, vv>>>(influence, opinions, noise);
    if (use_streams) cudaEventRecord(evV, vv);

    k_prep_all<<<42501, 256>>>(hiddens, W_ih, W_hh, Wa1, Wg1, Wa2, Wg2, ba2, bg2);
    if (use_streams) {
        cudaEventRecord(evPrep, 0);
        cudaStreamWaitEvent(m, evPrep, 0);
    }
    k_bias1<<<32, 256>>>(Wa1, ba1, Wg1, bg1, x);
    k_vih<<<G3 / 8, 256>>>(W_ih, b_ih);

    // Mcat[3072,256] on side stream (concurrent with hid GEMM)
    gemm2<1, 4096, 3, 0><<<dim3(2, 48), 256, SMEM_MI1, m>>>(
        pWihH, pWihL, 1024,
        pW2TH, pW2TL, nullptr, nullptr,
        pMcH, pMcL, 256,
        nullptr, 0, nullptr, 0,
        1024, nullptr, nullptr);
    if (use_streams) cudaEventRecord(evM, m);

    // merged hid GEMM: N=[A1G1(256) | gh(3072)]  (grid 26 x 16)
    gemm2<4, 256, 1, 0><<<dim3(26, 16), 256, SMEM_MI4>>>(
        pHidH, pHidL, 1024,
        pB1H, pB1L, pWhhH, pWhhL,
        pAgH, pAgL, 256,
        nullptr, 0, pGh, G3,
        1024, pBias1, b_hh);

    // merged A1G1 GEMM: N=[gi(3072) | tension-sumsq(1024)]  (grid 32 x 16)
    if (use_streams) cudaStreamWaitEvent(0, evM, 0);
    gemm2<4, 3072, 0, 2><<<dim3(32, 16), 256, SMEM_MI4>>>(
        pAgH, pAgL, 256,
        pMcH, pMcL, pWc2H, pWc2L,
        nullptr, nullptr, 0,
        pGi, G3, nullptr, 0,
        256, pVih, pBconst);
    if (use_streams) { cudaEventRecord(evT, 0); cudaStreamWaitEvent(m, evT, 0); }

    // softmax -> pred chain on side stream (hidden under gru chain)
    k_softmax<<<1, 1024, 0, m>>>(out_avg);
    k_wA<<<32, 256, 0, m>>>();
    k_comb2<<<128, 256, 0, m>>>();
    k_pred<<<128, 256, 0, m>>>(Wo, bo, out_pred);
    if (use_streams) cudaEventRecord(evP, m);

    // GRU chain
    if (use_streams) cudaStreamWaitEvent(0, evV, 0);
    k_gru<<<N_CELLS, 256>>>(hiddens);
    k_segsum<<<dim3(4, 32), 256>>>();
    k_blend<<<dim3(4, 64), 256>>>();
    k_final<<<N_CELLS, 256>>>(out_nh, step);

    if (use_streams) cudaStreamWaitEvent(0, evP, 0);
}